// round 1
// baseline (speedup 1.0000x reference)
#include <cuda_runtime.h>

#define NROWS  300000
#define HD     128
#define NLANES 25000
#define LNEPS  1e-5f

// Scratch (device globals: no allocation allowed in kernel_launch)
__device__ float g_h[(size_t)NROWS * HD];        // fc1 output, 153.6 MB
__device__ int   g_lanemax[NLANES * HD];         // per-lane max (float bits), 12.8 MB

typedef unsigned long long u64;

static __device__ __forceinline__ u64 pack2(float lo, float hi) {
    u64 r; asm("mov.b64 %0, {%1, %2};" : "=l"(r) : "f"(lo), "f"(hi)); return r;
}
static __device__ __forceinline__ void unpack2(u64 v, float& lo, float& hi) {
    asm("mov.b64 {%0, %1}, %2;" : "=f"(lo), "=f"(hi) : "l"(v));
}
// packed fp32x2 FMA: d = a*b + d   (full-rate fp32 path on sm_10x)
static __device__ __forceinline__ void fma2(u64& d, u64 a, u64 b) {
    asm("fma.rn.f32x2 %0, %1, %2, %0;" : "+l"(d) : "l"(a), "l"(b));
}

static __device__ __forceinline__ void wreduce2(float& s, float& q) {
    #pragma unroll
    for (int off = 16; off; off >>= 1) {
        s += __shfl_xor_sync(0xffffffffu, s, off);
        q += __shfl_xor_sync(0xffffffffu, q, off);
    }
}

// Row LayerNorm over 128 cols spread as 4 cols/thread across one warp.
static __device__ __forceinline__ float4 lnrow(float v0, float v1, float v2, float v3,
                                               float4 gam, float4 bet, bool do_relu) {
    float s = v0 + v1 + v2 + v3;
    float q = v0*v0 + v1*v1 + v2*v2 + v3*v3;
    wreduce2(s, q);
    float m    = s * (1.0f / HD);
    float rstd = rsqrtf(q * (1.0f / HD) - m * m + LNEPS);
    float4 o;
    o.x = (v0 - m) * rstd * gam.x + bet.x;
    o.y = (v1 - m) * rstd * gam.y + bet.y;
    o.z = (v2 - m) * rstd * gam.z + bet.z;
    o.w = (v3 - m) * rstd * gam.w + bet.w;
    if (do_relu) {
        o.x = fmaxf(o.x, 0.0f); o.y = fmaxf(o.y, 0.0f);
        o.z = fmaxf(o.z, 0.0f); o.w = fmaxf(o.w, 0.0f);
    }
    return o;
}

// acc[8 rows][2 col-pairs] += xs[8 rows][0:128] @ w[0:128][4 cols of this lane]
// wv: weights in SMEM as float4 rows of 32 (w[k][j], j = lane*4 + 0..3)
// xs_row0: SMEM base of this warp's 8 rows (row stride HD floats)
static __device__ __forceinline__ void gemm128(const float4* __restrict__ wv,
                                               const float* __restrict__ xs_row0,
                                               int lane, u64 acc[8][2]) {
    #pragma unroll 2
    for (int k4 = 0; k4 < 32; ++k4) {
        float4 w0 = wv[(k4*4 + 0)*32 + lane];
        float4 w1 = wv[(k4*4 + 1)*32 + lane];
        float4 w2 = wv[(k4*4 + 2)*32 + lane];
        float4 w3 = wv[(k4*4 + 3)*32 + lane];
        u64 wp0a = pack2(w0.x, w0.y), wp0b = pack2(w0.z, w0.w);
        u64 wp1a = pack2(w1.x, w1.y), wp1b = pack2(w1.z, w1.w);
        u64 wp2a = pack2(w2.x, w2.y), wp2b = pack2(w2.z, w2.w);
        u64 wp3a = pack2(w3.x, w3.y), wp3b = pack2(w3.z, w3.w);
        #pragma unroll
        for (int r = 0; r < 8; ++r) {
            float4 xq = *(const float4*)(xs_row0 + r*HD + k4*4);  // warp-broadcast LDS.128
            u64 xx;
            xx = pack2(xq.x, xq.x); fma2(acc[r][0], xx, wp0a); fma2(acc[r][1], xx, wp0b);
            xx = pack2(xq.y, xq.y); fma2(acc[r][0], xx, wp1a); fma2(acc[r][1], xx, wp1b);
            xx = pack2(xq.z, xq.z); fma2(acc[r][0], xx, wp2a); fma2(acc[r][1], xx, wp2b);
            xx = pack2(xq.w, xq.w); fma2(acc[r][0], xx, wp3a); fma2(acc[r][1], xx, wp3b);
        }
    }
}

// ---------------- kernel 0: zero lane-max accumulator ----------------
__global__ void k_init_lanemax() {
    int i = blockIdx.x * blockDim.x + threadIdx.x;
    if (i < NLANES * HD) g_lanemax[i] = 0;   // h = relu(..) >= 0, so 0 is a valid identity
}

// ---------------- kernel 1: fc1 (two Linear+LN+ReLU) + scatter-max ----------------
// 512 threads, 16 warps x 8 rows = 128-row tiles. Rows are warp-exclusive -> warp-local sync only.
__global__ void __launch_bounds__(512, 1) k_fc1(
    const float* __restrict__ x, const int* __restrict__ lane_ids,
    const float* __restrict__ w1a, const float* __restrict__ b1a,
    const float* __restrict__ g1a, const float* __restrict__ be1a,
    const float* __restrict__ w1b, const float* __restrict__ b1b,
    const float* __restrict__ g1b, const float* __restrict__ be1b)
{
    extern __shared__ float smem[];
    float* sw1a = smem;           // 16384 floats
    float* sw1b = smem + 16384;   // 16384 floats
    float* xs   = smem + 32768;   // 16384 floats (128 rows x 128)
    int tid = threadIdx.x;
    {
        float4* da = (float4*)sw1a; const float4* sa = (const float4*)w1a;
        float4* db = (float4*)sw1b; const float4* sb = (const float4*)w1b;
        for (int i = tid; i < 4096; i += 512) { da[i] = sa[i]; db[i] = sb[i]; }
    }
    __syncthreads();

    int lane = tid & 31, warp = tid >> 5;
    float4 B1a = ((const float4*)b1a)[lane], G1a = ((const float4*)g1a)[lane], E1a = ((const float4*)be1a)[lane];
    float4 B1b = ((const float4*)b1b)[lane], G1b = ((const float4*)g1b)[lane], E1b = ((const float4*)be1b)[lane];

    float*  xsw  = xs + warp * 8 * HD;
    float4* xsw4 = (float4*)xsw;

    const int ntiles = (NROWS + 127) / 128;
    for (int t = blockIdx.x; t < ntiles; t += gridDim.x) {
        int r0 = t * 128 + warp * 8;
        if (r0 >= NROWS) continue;              // NROWS % 8 == 0: all 8 rows valid when r0 < N

        #pragma unroll
        for (int r = 0; r < 8; ++r)
            xsw4[r*32 + lane] = ((const float4*)x)[(size_t)(r0 + r)*32 + lane];
        __syncwarp();

        u64 acc[8][2];
        #pragma unroll
        for (int r = 0; r < 8; ++r) { acc[r][0] = 0ull; acc[r][1] = 0ull; }
        gemm128((const float4*)sw1a, xsw, lane, acc);
        __syncwarp();
        #pragma unroll
        for (int r = 0; r < 8; ++r) {
            float v0, v1, v2, v3;
            unpack2(acc[r][0], v0, v1); unpack2(acc[r][1], v2, v3);
            float4 y = lnrow(v0 + B1a.x, v1 + B1a.y, v2 + B1a.z, v3 + B1a.w, G1a, E1a, true);
            xsw4[r*32 + lane] = y;
        }
        __syncwarp();

        #pragma unroll
        for (int r = 0; r < 8; ++r) { acc[r][0] = 0ull; acc[r][1] = 0ull; }
        gemm128((const float4*)sw1b, xsw, lane, acc);
        __syncwarp();
        #pragma unroll
        for (int r = 0; r < 8; ++r) {
            float v0, v1, v2, v3;
            unpack2(acc[r][0], v0, v1); unpack2(acc[r][1], v2, v3);
            float4 y = lnrow(v0 + B1b.x, v1 + B1b.y, v2 + B1b.z, v3 + B1b.w, G1b, E1b, true);
            ((float4*)g_h)[(size_t)(r0 + r)*32 + lane] = y;
            int ln   = lane_ids[r0 + r];
            int base = ln * HD + lane * 4;
            // y >= 0 -> float bits monotone as int -> int atomicMax == float max
            atomicMax(&g_lanemax[base + 0], __float_as_int(y.x));
            atomicMax(&g_lanemax[base + 1], __float_as_int(y.y));
            atomicMax(&g_lanemax[base + 2], __float_as_int(y.z));
            atomicMax(&g_lanemax[base + 3], __float_as_int(y.w));
        }
        __syncwarp();
    }
}

// ---------------- kernel 2: fc2 (concat-GEMM as two K=128 chunks) + residual LN ----------------
// 256 threads, 8 warps x 8 rows = 64-row tiles. smem: w2a(128K) + w2b(64K) + tile(32K) = 224 KB.
__global__ void __launch_bounds__(256, 1) k_fc2(
    const float* __restrict__ x, const int* __restrict__ lane_ids,
    const float* __restrict__ w2a, const float* __restrict__ b2a,
    const float* __restrict__ g2a, const float* __restrict__ be2a,
    const float* __restrict__ w2b, const float* __restrict__ b2b,
    const float* __restrict__ g2b, const float* __restrict__ be2b,
    const float* __restrict__ gn, const float* __restrict__ bn,
    float* __restrict__ out)
{
    extern __shared__ float smem[];
    float* sw2a = smem;           // 32768 floats ([256][128])
    float* sw2b = smem + 32768;   // 16384 floats
    float* xs   = smem + 49152;   // 8192 floats (64 rows x 128)
    int tid = threadIdx.x;
    {
        float4* da = (float4*)sw2a; const float4* sa = (const float4*)w2a;
        for (int i = tid; i < 8192; i += 256) da[i] = sa[i];
        float4* db = (float4*)sw2b; const float4* sb = (const float4*)w2b;
        for (int i = tid; i < 4096; i += 256) db[i] = sb[i];
    }
    __syncthreads();

    int lane = tid & 31, warp = tid >> 5;
    float4 B2a = ((const float4*)b2a)[lane], G2a = ((const float4*)g2a)[lane], E2a = ((const float4*)be2a)[lane];
    float4 B2b = ((const float4*)b2b)[lane], G2b = ((const float4*)g2b)[lane], E2b = ((const float4*)be2b)[lane];
    float4 GN  = ((const float4*)gn)[lane],  BN  = ((const float4*)bn)[lane];

    float*  xsw  = xs + warp * 8 * HD;
    float4* xsw4 = (float4*)xsw;

    const int ntiles = (NROWS + 63) / 64;
    for (int t = blockIdx.x; t < ntiles; t += gridDim.x) {
        int r0 = t * 64 + warp * 8;
        if (r0 >= NROWS) continue;

        // chunk 1: h rows
        #pragma unroll
        for (int r = 0; r < 8; ++r)
            xsw4[r*32 + lane] = ((const float4*)g_h)[(size_t)(r0 + r)*32 + lane];
        __syncwarp();

        u64 acc[8][2];
        #pragma unroll
        for (int r = 0; r < 8; ++r) { acc[r][0] = 0ull; acc[r][1] = 0ull; }
        gemm128((const float4*)sw2a, xsw, lane, acc);
        __syncwarp();

        // chunk 2: gathered per-lane max (12.8 MB table -> L2 resident)
        #pragma unroll
        for (int r = 0; r < 8; ++r) {
            int ln = lane_ids[r0 + r];
            xsw4[r*32 + lane] = ((const float4*)g_lanemax)[(size_t)ln*32 + lane];
        }
        __syncwarp();
        gemm128((const float4*)(sw2a + 16384), xsw, lane, acc);
        __syncwarp();

        #pragma unroll
        for (int r = 0; r < 8; ++r) {
            float v0, v1, v2, v3;
            unpack2(acc[r][0], v0, v1); unpack2(acc[r][1], v2, v3);
            float4 y = lnrow(v0 + B2a.x, v1 + B2a.y, v2 + B2a.z, v3 + B2a.w, G2a, E2a, true);
            xsw4[r*32 + lane] = y;
        }
        __syncwarp();

        #pragma unroll
        for (int r = 0; r < 8; ++r) { acc[r][0] = 0ull; acc[r][1] = 0ull; }
        gemm128((const float4*)sw2b, xsw, lane, acc);
        __syncwarp();

        #pragma unroll
        for (int r = 0; r < 8; ++r) {
            float v0, v1, v2, v3;
            unpack2(acc[r][0], v0, v1); unpack2(acc[r][1], v2, v3);
            float4 f  = lnrow(v0 + B2b.x, v1 + B2b.y, v2 + B2b.z, v3 + B2b.w, G2b, E2b, true);
            float4 xv = ((const float4*)x)[(size_t)(r0 + r)*32 + lane];
            float4 o  = lnrow(xv.x + f.x, xv.y + f.y, xv.z + f.z, xv.w + f.w, GN, BN, false);
            ((float4*)out)[(size_t)(r0 + r)*32 + lane] = o;
        }
        __syncwarp();
    }
}

extern "C" void kernel_launch(void* const* d_in, const int* in_sizes, int n_in,
                              void* d_out, int out_size) {
    (void)in_sizes; (void)n_in; (void)out_size;
    const float* x        = (const float*)d_in[0];
    const int*   lane_ids = (const int*)  d_in[1];
    const float* w1a  = (const float*)d_in[2];
    const float* b1a  = (const float*)d_in[3];
    const float* g1a  = (const float*)d_in[4];
    const float* be1a = (const float*)d_in[5];
    const float* w1b  = (const float*)d_in[6];
    const float* b1b  = (const float*)d_in[7];
    const float* g1b  = (const float*)d_in[8];
    const float* be1b = (const float*)d_in[9];
    const float* w2a  = (const float*)d_in[10];
    const float* b2a  = (const float*)d_in[11];
    const float* g2a  = (const float*)d_in[12];
    const float* be2a = (const float*)d_in[13];
    const float* w2b  = (const float*)d_in[14];
    const float* b2b  = (const float*)d_in[15];
    const float* g2b  = (const float*)d_in[16];
    const float* be2b = (const float*)d_in[17];
    const float* gn   = (const float*)d_in[18];
    const float* bn   = (const float*)d_in[19];
    float* out = (float*)d_out;

    const int smem1 = 49152 * 4;   // 192 KB
    const int smem2 = 57344 * 4;   // 224 KB
    cudaFuncSetAttribute(k_fc1, cudaFuncAttributeMaxDynamicSharedMemorySize, smem1);
    cudaFuncSetAttribute(k_fc2, cudaFuncAttributeMaxDynamicSharedMemorySize, smem2);

    k_init_lanemax<<<(NLANES * HD + 511) / 512, 512>>>();
    k_fc1<<<148, 512, smem1>>>(x, lane_ids, w1a, b1a, g1a, be1a, w1b, b1b, g1b, be1b);
    k_fc2<<<148, 256, smem2>>>(x, lane_ids, w2a, b2a, g2a, be2a, w2b, b2b, g2b, be2b, gn, bn, out);
}

// round 3
// speedup vs baseline: 1.0609x; 1.0609x over previous
#include <cuda_runtime.h>
#include <cuda_bf16.h>
#include <cstdint>

#define NROWS  300000
#define HD     128
#define NLANES 25000
#define LNEPS  1e-5f
#define TM     128
#define NT     ((NROWS + TM - 1) / TM)   // 2344 tiles
#define PADU   68                         // u32 per 128-bf16 row (padded, conflict-free)
#define TILEU4 4352                       // uint4 per split tile image (hi+lo)

typedef unsigned int       u32;
typedef unsigned short     u16;
typedef unsigned long long u64;

// ---------------- device scratch ----------------
// Split (hi/lo bf16) padded tile images: per tile 2 * 128 * 68 u32 = 69632 B.
__device__ uint4 g_h[(size_t)NT * TILEU4];   // fc1 output image, 163 MB
__device__ uint4 g_f[(size_t)NT * TILEU4];   // fc2a output image, 163 MB
__device__ int   g_lanemax[NLANES * HD];     // per-lane max (float bits, relu>=0)

// ---------------- bf16 split helpers ----------------
static __device__ __forceinline__ u16 f2bf(float f) {
    return __bfloat16_as_ushort(__float2bfloat16(f));
}
static __device__ __forceinline__ float bf2f(u16 u) {
    return __uint_as_float(((u32)u) << 16);
}
static __device__ __forceinline__ u32 packsplit_hi(float v0, float v1) {
    return (u32)f2bf(v0) | ((u32)f2bf(v1) << 16);
}
static __device__ __forceinline__ u32 packsplit_lo(float v0, float v1) {
    u16 h0 = f2bf(v0), h1 = f2bf(v1);
    return (u32)f2bf(v0 - bf2f(h0)) | ((u32)f2bf(v1 - bf2f(h1)) << 16);
}

// ---------------- warp-level MMA ----------------
static __device__ __forceinline__ void mma16816(float (&d)[4], const u32 (&a)[4], u32 b0, u32 b1) {
    asm volatile("mma.sync.aligned.m16n8k16.row.col.f32.bf16.bf16.f32 "
        "{%0,%1,%2,%3}, {%4,%5,%6,%7}, {%8,%9}, {%0,%1,%2,%3};"
        : "+f"(d[0]), "+f"(d[1]), "+f"(d[2]), "+f"(d[3])
        : "r"(a[0]), "r"(a[1]), "r"(a[2]), "r"(a[3]), "r"(b0), "r"(b1));
}

// One bf16 pass: acc[2 row-tiles][4 n-tiles] += A[wrow+32][128] * B[wcol+32][128]^T
static __device__ __forceinline__ void mma_pass(
    const u32* __restrict__ Asm, const u32* __restrict__ Bsm,
    int wrow, int wcol, int lr, int lc, float (&acc)[8][4])
{
    #pragma unroll
    for (int kc = 0; kc < 8; ++kc) {
        u32 a[2][4];
        #pragma unroll
        for (int rt = 0; rt < 2; ++rt) {
            int r = wrow + rt * 16 + lr;
            const u32* ap0 = Asm + r * PADU + kc * 8 + lc;
            const u32* ap1 = Asm + (r + 8) * PADU + kc * 8 + lc;
            a[rt][0] = ap0[0]; a[rt][1] = ap1[0]; a[rt][2] = ap0[4]; a[rt][3] = ap1[4];
        }
        #pragma unroll
        for (int nt = 0; nt < 4; ++nt) {
            const u32* bp = Bsm + (wcol + nt * 8 + lr) * PADU + kc * 8 + lc;
            u32 b0 = bp[0], b1 = bp[4];
            mma16816(acc[nt],     a[0], b0, b1);
            mma16816(acc[4 + nt], a[1], b0, b1);
        }
    }
}

// Full split GEMM: 3 passes (hi*hi + lo*hi + hi*lo)
static __device__ __forceinline__ void gemm_split(
    const u32* Ah, const u32* Al, const u32* Bh, const u32* Bl,
    int wrow, int wcol, int lr, int lc, float (&acc)[8][4])
{
    mma_pass(Ah, Bh, wrow, wcol, lr, lc, acc);
    mma_pass(Al, Bh, wrow, wcol, lr, lc, acc);
    mma_pass(Ah, Bl, wrow, wcol, lr, lc, acc);
}

// ---------------- LN epilogue on register fragments ----------------
// acc index: [rt*4+nt? no: [nt] rt0, [4+nt] rt1]; within: {r,c0},{r,c1},{r+8,c0},{r+8,c1}
template<bool HASB, bool RELU>
static __device__ __forceinline__ void ln_tile(
    float (&acc)[8][4], int wrow, int wcol, int lr, int lc, int cw,
    const float* __restrict__ bias, const float* __restrict__ gam,
    const float* __restrict__ bet, float* RS, float* RQ)
{
    float s[4] = {0.f,0.f,0.f,0.f}, q[4] = {0.f,0.f,0.f,0.f};
    #pragma unroll
    for (int rt = 0; rt < 2; ++rt)
    #pragma unroll
    for (int nt = 0; nt < 4; ++nt) {
        float* a = acc[rt * 4 + nt];
        if (HASB) {
            int c = wcol + nt * 8 + lc * 2;
            float bx = bias[c], by = bias[c + 1];
            a[0] += bx; a[1] += by; a[2] += bx; a[3] += by;
        }
        s[rt*2+0] += a[0] + a[1]; q[rt*2+0] += a[0]*a[0] + a[1]*a[1];
        s[rt*2+1] += a[2] + a[3]; q[rt*2+1] += a[2]*a[2] + a[3]*a[3];
    }
    #pragma unroll
    for (int off = 1; off <= 2; off <<= 1)
        #pragma unroll
        for (int i = 0; i < 4; ++i) {
            s[i] += __shfl_xor_sync(0xffffffffu, s[i], off);
            q[i] += __shfl_xor_sync(0xffffffffu, q[i], off);
        }
    if (lc == 0) {
        #pragma unroll
        for (int i = 0; i < 4; ++i) {
            int row = wrow + (i >> 1) * 16 + (i & 1) * 8 + lr;
            RS[cw * 128 + row] = s[i];
            RQ[cw * 128 + row] = q[i];
        }
    }
    __syncthreads();
    float mm[4], rsd[4];
    #pragma unroll
    for (int i = 0; i < 4; ++i) {
        int row = wrow + (i >> 1) * 16 + (i & 1) * 8 + lr;
        float S = RS[row] + RS[128 + row] + RS[256 + row] + RS[384 + row];
        float Q = RQ[row] + RQ[128 + row] + RQ[256 + row] + RQ[384 + row];
        float m = S * (1.f / 128.f);
        mm[i] = m;
        rsd[i] = rsqrtf(Q * (1.f / 128.f) - m * m + LNEPS);
    }
    __syncthreads();
    #pragma unroll
    for (int rt = 0; rt < 2; ++rt)
    #pragma unroll
    for (int nt = 0; nt < 4; ++nt) {
        int c = wcol + nt * 8 + lc * 2;
        float gx = gam[c], gy = gam[c + 1], ex = bet[c], ey = bet[c + 1];
        float* a = acc[rt * 4 + nt];
        int s0 = rt * 2, s1 = rt * 2 + 1;
        a[0] = (a[0] - mm[s0]) * rsd[s0] * gx + ex;
        a[1] = (a[1] - mm[s0]) * rsd[s0] * gy + ey;
        a[2] = (a[2] - mm[s1]) * rsd[s1] * gx + ex;
        a[3] = (a[3] - mm[s1]) * rsd[s1] * gy + ey;
        if (RELU) {
            a[0] = fmaxf(a[0], 0.f); a[1] = fmaxf(a[1], 0.f);
            a[2] = fmaxf(a[2], 0.f); a[3] = fmaxf(a[3], 0.f);
        }
    }
}

// store normalized fragments back to split A (padded layout)
static __device__ __forceinline__ void store_acc_split(
    const float (&acc)[8][4], u32* hi, u32* lo, int wrow, int wcol, int lr, int lc)
{
    #pragma unroll
    for (int rt = 0; rt < 2; ++rt)
    #pragma unroll
    for (int hh = 0; hh < 2; ++hh) {
        int row = wrow + rt * 16 + hh * 8 + lr;
        u32 base = row * PADU + (wcol >> 1) + lc;
        #pragma unroll
        for (int nt = 0; nt < 4; ++nt) {
            float v0 = acc[rt*4+nt][hh*2+0], v1 = acc[rt*4+nt][hh*2+1];
            hi[base + nt*4] = packsplit_hi(v0, v1);
            lo[base + nt*4] = packsplit_lo(v0, v1);
        }
    }
}

// split a float4 (cols col..col+3) into hi/lo at (row, col) of padded layout
static __device__ __forceinline__ void store_split4(u32* hi, u32* lo, int row, int col, float4 xv) {
    u32 idx = row * PADU + (col >> 1);
    hi[idx]   = packsplit_hi(xv.x, xv.y);
    hi[idx+1] = packsplit_hi(xv.z, xv.w);
    lo[idx]   = packsplit_lo(xv.x, xv.y);
    lo[idx+1] = packsplit_lo(xv.z, xv.w);
}

// weights: gmem w[k][o] -> B[n=o][k] hi/lo padded
static __device__ __forceinline__ void load_wsplit(u32* hi, u32* lo, const float* __restrict__ w,
                                                   int tid, int nth) {
    for (int idx = tid; idx < HD * HD / 2; idx += nth) {
        int o = idx & 127, k2 = idx >> 7;              // k pair index
        float v0 = w[(2*k2)   * HD + o];
        float v1 = w[(2*k2+1) * HD + o];
        u32 off = o * PADU + k2;
        hi[off] = packsplit_hi(v0, v1);
        lo[off] = packsplit_lo(v0, v1);
    }
}

// ---------------- kernel 0: zero lane-max ----------------
__global__ void k_init_lanemax() {
    int i = blockIdx.x * blockDim.x + threadIdx.x;
    if (i < NLANES * HD) g_lanemax[i] = 0;
}

// SMEM offsets (bytes)
#define WSZ 34816      // one 128x68-u32 array

// ======================== fc1 ========================
__global__ void __launch_bounds__(512, 1) k_fc1(
    const float* __restrict__ x, const int* __restrict__ lane_ids,
    const float* __restrict__ w1a, const float* __restrict__ b1a,
    const float* __restrict__ g1a, const float* __restrict__ be1a,
    const float* __restrict__ w1b, const float* __restrict__ b1b,
    const float* __restrict__ g1b, const float* __restrict__ be1b)
{
    extern __shared__ char sm[];
    u32* WA_HI = (u32*)(sm);            u32* WA_LO = (u32*)(sm + WSZ);
    u32* WB_HI = (u32*)(sm + 2*WSZ);    u32* WB_LO = (u32*)(sm + 3*WSZ);
    u32* A_HI  = (u32*)(sm + 4*WSZ);    u32* A_LO  = (u32*)(sm + 5*WSZ);
    float* P  = (float*)(sm + 6*WSZ);                 // 6*128 floats
    float* RS = (float*)(sm + 6*WSZ + 3072);          // 4*128
    float* RQ = (float*)(sm + 6*WSZ + 5120);          // 4*128

    const int tid = threadIdx.x, w = tid >> 5, lane = tid & 31;
    const int lr = lane >> 2, lc = lane & 3;
    const int wrow = (w & 3) * 32, wcol = (w >> 2) * 32, cw = w >> 2;

    load_wsplit(WA_HI, WA_LO, w1a, tid, 512);
    load_wsplit(WB_HI, WB_LO, w1b, tid, 512);
    for (int i = tid; i < HD; i += 512) {
        P[i] = b1a[i]; P[128+i] = g1a[i]; P[256+i] = be1a[i];
        P[384+i] = b1b[i]; P[512+i] = g1b[i]; P[640+i] = be1b[i];
    }
    __syncthreads();

    for (int t = blockIdx.x; t < NT; t += gridDim.x) {
        int r0 = t * TM;
        #pragma unroll
        for (int j = 0; j < 8; ++j) {
            int idx = tid + j * 512; int xr = idx >> 5; int cg = idx & 31;
            int grow = r0 + xr; if (grow >= NROWS) grow = NROWS - 1;
            float4 xv = __ldg(((const float4*)x) + ((size_t)grow * 32 + cg));
            store_split4(A_HI, A_LO, xr, cg * 4, xv);
        }
        __syncthreads();

        float acc[8][4];
        #pragma unroll
        for (int i = 0; i < 8; ++i) { acc[i][0]=acc[i][1]=acc[i][2]=acc[i][3]=0.f; }
        gemm_split(A_HI, A_LO, WA_HI, WA_LO, wrow, wcol, lr, lc, acc);
        ln_tile<true, true>(acc, wrow, wcol, lr, lc, cw, P, P+128, P+256, RS, RQ);
        store_acc_split(acc, A_HI, A_LO, wrow, wcol, lr, lc);
        __syncthreads();

        #pragma unroll
        for (int i = 0; i < 8; ++i) { acc[i][0]=acc[i][1]=acc[i][2]=acc[i][3]=0.f; }
        gemm_split(A_HI, A_LO, WB_HI, WB_LO, wrow, wcol, lr, lc, acc);
        ln_tile<true, true>(acc, wrow, wcol, lr, lc, cw, P+384, P+512, P+640, RS, RQ);

        // scatter-max (relu output >= 0 -> int-bits max == float max)
        #pragma unroll
        for (int rt = 0; rt < 2; ++rt)
        #pragma unroll
        for (int hh = 0; hh < 2; ++hh) {
            int row = wrow + rt*16 + hh*8 + lr;
            int grow = r0 + row; if (grow >= NROWS) grow = NROWS - 1;
            int ln = __ldg(lane_ids + grow);
            int* bp = g_lanemax + ln * HD;
            #pragma unroll
            for (int nt = 0; nt < 4; ++nt) {
                int c = wcol + nt*8 + lc*2;
                atomicMax(bp + c,     __float_as_int(acc[rt*4+nt][hh*2+0]));
                atomicMax(bp + c + 1, __float_as_int(acc[rt*4+nt][hh*2+1]));
            }
        }
        store_acc_split(acc, A_HI, A_LO, wrow, wcol, lr, lc);
        __syncthreads();

        const uint4* s4 = (const uint4*)A_HI;     // A_HI ++ A_LO contiguous
        uint4* d4 = g_h + (size_t)t * TILEU4;
        for (int i = tid; i < TILEU4; i += 512) d4[i] = s4[i];
        __syncthreads();
    }
}

// ======================== fc2a ========================
__global__ void __launch_bounds__(512, 1) k_fc2a(
    const int* __restrict__ lane_ids,
    const float* __restrict__ w2a, const float* __restrict__ b2a,
    const float* __restrict__ g2a, const float* __restrict__ be2a)
{
    extern __shared__ char sm[];
    u32* W1_HI = (u32*)(sm);            u32* W1_LO = (u32*)(sm + WSZ);
    u32* W2_HI = (u32*)(sm + 2*WSZ);    u32* W2_LO = (u32*)(sm + 3*WSZ);
    u32* A_HI  = (u32*)(sm + 4*WSZ);    u32* A_LO  = (u32*)(sm + 5*WSZ);
    float* P  = (float*)(sm + 6*WSZ);                 // 3*128
    float* RS = (float*)(sm + 6*WSZ + 1536);
    float* RQ = (float*)(sm + 6*WSZ + 3584);

    const int tid = threadIdx.x, w = tid >> 5, lane = tid & 31;
    const int lr = lane >> 2, lc = lane & 3;
    const int wrow = (w & 3) * 32, wcol = (w >> 2) * 32, cw = w >> 2;

    load_wsplit(W1_HI, W1_LO, w2a,            tid, 512);   // concat rows 0..127 (h)
    load_wsplit(W2_HI, W2_LO, w2a + 128 * HD, tid, 512);   // concat rows 128..255 (max)
    for (int i = tid; i < HD; i += 512) { P[i] = b2a[i]; P[128+i] = g2a[i]; P[256+i] = be2a[i]; }
    __syncthreads();

    const int grow_t = tid & 127;      // gather mapping: thread -> (row, 32-col group)
    const int gc0 = (tid >> 7) * 32;

    for (int t = blockIdx.x; t < NT; t += gridDim.x) {
        int r0 = t * TM;
        {
            const uint4* s4 = g_h + (size_t)t * TILEU4;
            uint4* d4 = (uint4*)A_HI;
            for (int i = tid; i < TILEU4; i += 512) d4[i] = s4[i];
        }
        __syncthreads();

        float acc[8][4];
        #pragma unroll
        for (int i = 0; i < 8; ++i) { acc[i][0]=acc[i][1]=acc[i][2]=acc[i][3]=0.f; }
        gemm_split(A_HI, A_LO, W1_HI, W1_LO, wrow, wcol, lr, lc, acc);
        __syncthreads();

        // overwrite A with gathered lane-max (L2-resident table)
        {
            int grow = r0 + grow_t; if (grow >= NROWS) grow = NROWS - 1;
            int ln = __ldg(lane_ids + grow);
            const int4* gp = (const int4*)(g_lanemax + ln * HD + gc0);
            #pragma unroll
            for (int j = 0; j < 8; ++j) {
                int4 gv = __ldg(gp + j);
                store_split4(A_HI, A_LO, grow_t, gc0 + j * 4,
                    make_float4(__int_as_float(gv.x), __int_as_float(gv.y),
                                __int_as_float(gv.z), __int_as_float(gv.w)));
            }
        }
        __syncthreads();
        gemm_split(A_HI, A_LO, W2_HI, W2_LO, wrow, wcol, lr, lc, acc);
        ln_tile<true, true>(acc, wrow, wcol, lr, lc, cw, P, P+128, P+256, RS, RQ);
        store_acc_split(acc, A_HI, A_LO, wrow, wcol, lr, lc);
        __syncthreads();

        const uint4* s4 = (const uint4*)A_HI;
        uint4* d4 = g_f + (size_t)t * TILEU4;
        for (int i = tid; i < TILEU4; i += 512) d4[i] = s4[i];
        __syncthreads();
    }
}

// ======================== fc2b ========================
#define XSTR 132
__global__ void __launch_bounds__(512, 1) k_fc2b(
    const float* __restrict__ x,
    const float* __restrict__ w2b, const float* __restrict__ b2b,
    const float* __restrict__ g2b, const float* __restrict__ be2b,
    const float* __restrict__ gn, const float* __restrict__ bn,
    float* __restrict__ out)
{
    extern __shared__ char sm[];
    u32* W_HI = (u32*)(sm);            u32* W_LO = (u32*)(sm + WSZ);
    u32* A_HI = (u32*)(sm + 2*WSZ);    u32* A_LO = (u32*)(sm + 3*WSZ);
    float* XS = (float*)(sm + 4*WSZ);                  // [128][132] f32 = 67584 B
    float* P  = (float*)(sm + 4*WSZ + 67584);          // 5*128
    float* RS = (float*)(sm + 4*WSZ + 67584 + 2560);
    float* RQ = (float*)(sm + 4*WSZ + 67584 + 4608);

    const int tid = threadIdx.x, w = tid >> 5, lane = tid & 31;
    const int lr = lane >> 2, lc = lane & 3;
    const int wrow = (w & 3) * 32, wcol = (w >> 2) * 32, cw = w >> 2;

    load_wsplit(W_HI, W_LO, w2b, tid, 512);
    for (int i = tid; i < HD; i += 512) {
        P[i] = b2b[i]; P[128+i] = g2b[i]; P[256+i] = be2b[i]; P[384+i] = gn[i]; P[512+i] = bn[i];
    }
    __syncthreads();

    for (int t = blockIdx.x; t < NT; t += gridDim.x) {
        int r0 = t * TM;
        {
            const uint4* s4 = g_f + (size_t)t * TILEU4;
            uint4* d4 = (uint4*)A_HI;
            for (int i = tid; i < TILEU4; i += 512) d4[i] = s4[i];
        }
        #pragma unroll
        for (int j = 0; j < 32; ++j) {
            int idx = tid + j * 512; int xr = idx >> 7; int c = idx & 127;
            int grow = r0 + xr; if (grow >= NROWS) grow = NROWS - 1;
            XS[xr * XSTR + c] = __ldg(x + (size_t)grow * HD + c);
        }
        __syncthreads();

        float acc[8][4];
        #pragma unroll
        for (int i = 0; i < 8; ++i) { acc[i][0]=acc[i][1]=acc[i][2]=acc[i][3]=0.f; }
        gemm_split(A_HI, A_LO, W_HI, W_LO, wrow, wcol, lr, lc, acc);
        ln_tile<true, true>(acc, wrow, wcol, lr, lc, cw, P, P+128, P+256, RS, RQ);

        // residual add
        #pragma unroll
        for (int rt = 0; rt < 2; ++rt)
        #pragma unroll
        for (int hh = 0; hh < 2; ++hh) {
            int row = wrow + rt*16 + hh*8 + lr;
            #pragma unroll
            for (int nt = 0; nt < 4; ++nt) {
                int c = wcol + nt*8 + lc*2;
                float2 xv = *(const float2*)&XS[row * XSTR + c];
                acc[rt*4+nt][hh*2+0] += xv.x;
                acc[rt*4+nt][hh*2+1] += xv.y;
            }
        }
        ln_tile<false, false>(acc, wrow, wcol, lr, lc, cw, P, P+384, P+512, RS, RQ);

        // stage to XS (sync inside ln_tile guarantees residual reads are done)
        #pragma unroll
        for (int rt = 0; rt < 2; ++rt)
        #pragma unroll
        for (int hh = 0; hh < 2; ++hh) {
            int row = wrow + rt*16 + hh*8 + lr;
            #pragma unroll
            for (int nt = 0; nt < 4; ++nt) {
                int c = wcol + nt*8 + lc*2;
                *(float2*)&XS[row * XSTR + c] =
                    make_float2(acc[rt*4+nt][hh*2+0], acc[rt*4+nt][hh*2+1]);
            }
        }
        __syncthreads();
        #pragma unroll
        for (int j = 0; j < 32; ++j) {
            int idx = tid + j * 512; int xr = idx >> 7; int c = idx & 127;
            int grow = r0 + xr;
            if (grow < NROWS) out[(size_t)grow * HD + c] = XS[xr * XSTR + c];
        }
        __syncthreads();
    }
}

// ---------------- launcher ----------------
extern "C" void kernel_launch(void* const* d_in, const int* in_sizes, int n_in,
                              void* d_out, int out_size) {
    (void)in_sizes; (void)n_in; (void)out_size;
    const float* x        = (const float*)d_in[0];
    const int*   lane_ids = (const int*)  d_in[1];
    const float* w1a  = (const float*)d_in[2];
    const float* b1a  = (const float*)d_in[3];
    const float* g1a  = (const float*)d_in[4];
    const float* be1a = (const float*)d_in[5];
    const float* w1b  = (const float*)d_in[6];
    const float* b1b  = (const float*)d_in[7];
    const float* g1b  = (const float*)d_in[8];
    const float* be1b = (const float*)d_in[9];
    const float* w2a  = (const float*)d_in[10];
    const float* b2a  = (const float*)d_in[11];
    const float* g2a  = (const float*)d_in[12];
    const float* be2a = (const float*)d_in[13];
    const float* w2b  = (const float*)d_in[14];
    const float* b2b  = (const float*)d_in[15];
    const float* g2b  = (const float*)d_in[16];
    const float* be2b = (const float*)d_in[17];
    const float* gn   = (const float*)d_in[18];
    const float* bn   = (const float*)d_in[19];
    float* out = (float*)d_out;

    const int SM1  = 6*WSZ + 3072 + 4096;            // 216064
    const int SM2A = 6*WSZ + 1536 + 4096;            // 214528
    const int SM2B = 4*WSZ + 67584 + 2560 + 4096;    // 213408 (rounded up below)
    cudaFuncSetAttribute(k_fc1,  cudaFuncAttributeMaxDynamicSharedMemorySize, SM1);
    cudaFuncSetAttribute(k_fc2a, cudaFuncAttributeMaxDynamicSharedMemorySize, SM2A);
    cudaFuncSetAttribute(k_fc2b, cudaFuncAttributeMaxDynamicSharedMemorySize, SM2B + 128);

    k_init_lanemax<<<(NLANES * HD + 511) / 512, 512>>>();
    k_fc1 <<<148, 512, SM1>>> (x, lane_ids, w1a, b1a, g1a, be1a, w1b, b1b, g1b, be1b);
    k_fc2a<<<148, 512, SM2A>>>(lane_ids, w2a, b2a, g2a, be2a);
    k_fc2b<<<148, 512, SM2B + 128>>>(x, w2b, b2b, g2b, be2b, gn, bn, out);
}

// round 4
// speedup vs baseline: 1.5147x; 1.4277x over previous
#include <cuda_runtime.h>
#include <cuda_bf16.h>
#include <cstdint>

#define NROWS  300000
#define HD     128
#define NLANES 25000
#define LNEPS  1e-5f
#define TM     128
#define NT     ((NROWS + TM - 1) / TM)   // 2344 tiles
#define PADU   68                         // u32 per 128-bf16 row (272B, 16B-aligned, conflict-free)
#define ROWB   272                        // row stride bytes
#define TILEU4 4352                       // uint4 per split tile image (hi+lo)

typedef unsigned int       u32;
typedef unsigned short     u16;
typedef unsigned long long u64;

// ---------------- device scratch ----------------
__device__ uint4 g_h[(size_t)NT * TILEU4];   // fc1 output image (split, padded)
__device__ uint4 g_f[(size_t)NT * TILEU4];   // fc2a output image
__device__ int   g_lanemax[NLANES * HD];     // per-lane max (float bits, relu>=0)

// ---------------- helpers ----------------
static __device__ __forceinline__ u32 smem_u32(const void* p) {
    u32 a;
    asm("{ .reg .u64 t; cvta.to.shared.u64 t, %1; cvt.u32.u64 %0, t; }" : "=r"(a) : "l"(p));
    return a;
}
static __device__ __forceinline__ u16 f2bf(float f) {
    return __bfloat16_as_ushort(__float2bfloat16(f));
}
static __device__ __forceinline__ float bf2f(u16 u) {
    return __uint_as_float(((u32)u) << 16);
}
static __device__ __forceinline__ u32 packsplit_hi(float v0, float v1) {
    return (u32)f2bf(v0) | ((u32)f2bf(v1) << 16);
}
static __device__ __forceinline__ u32 packsplit_lo(float v0, float v1) {
    u16 h0 = f2bf(v0), h1 = f2bf(v1);
    return (u32)f2bf(v0 - bf2f(h0)) | ((u32)f2bf(v1 - bf2f(h1)) << 16);
}

#define CP16(sm_addr, gptr) \
    asm volatile("cp.async.cg.shared.global [%0], [%1], 16;" :: "r"(sm_addr), "l"(gptr))
#define CP_WAIT() \
    asm volatile("cp.async.commit_group;\n\tcp.async.wait_group 0;" ::: "memory")
#define PREF_L2(p) asm volatile("prefetch.global.L2 [%0];" :: "l"(p))

static __device__ __forceinline__ void ldsm4(u32& r0, u32& r1, u32& r2, u32& r3, u32 addr) {
    asm volatile("ldmatrix.sync.aligned.m8n8.x4.shared.b16 {%0,%1,%2,%3}, [%4];"
        : "=r"(r0), "=r"(r1), "=r"(r2), "=r"(r3) : "r"(addr));
}
static __device__ __forceinline__ void mma16816(float (&d)[4], const u32 (&a)[4], u32 b0, u32 b1) {
    asm volatile("mma.sync.aligned.m16n8k16.row.col.f32.bf16.bf16.f32 "
        "{%0,%1,%2,%3}, {%4,%5,%6,%7}, {%8,%9}, {%0,%1,%2,%3};"
        : "+f"(d[0]), "+f"(d[1]), "+f"(d[2]), "+f"(d[3])
        : "r"(a[0]), "r"(a[1]), "r"(a[2]), "r"(a[3]), "r"(b0), "r"(b1));
}

// Merged split GEMM: acc += (Ah+Al)*(Bh)^T + Ah*(Bl)^T over K=128.
// Fragments loaded ONCE per k-chunk via ldmatrix.x4; 24 MMAs per kc.
static __device__ __forceinline__ void gemm_merged(
    u32 Ah, u32 Al, u32 Bh, u32 Bl, u32 aoff, u32 boff, float (&acc)[8][4])
{
    #pragma unroll
    for (int kc = 0; kc < 8; ++kc) {
        const u32 ka = kc * 32;
        u32 ah0[4], ah1[4], al0[4], al1[4], bh[8], bl[8];
        ldsm4(ah0[0], ah0[1], ah0[2], ah0[3], Ah + aoff + ka);
        ldsm4(ah1[0], ah1[1], ah1[2], ah1[3], Ah + aoff + 16 * ROWB + ka);
        ldsm4(al0[0], al0[1], al0[2], al0[3], Al + aoff + ka);
        ldsm4(al1[0], al1[1], al1[2], al1[3], Al + aoff + 16 * ROWB + ka);
        ldsm4(bh[0], bh[1], bh[2], bh[3], Bh + boff + ka);
        ldsm4(bh[4], bh[5], bh[6], bh[7], Bh + boff + 16 * ROWB + ka);
        ldsm4(bl[0], bl[1], bl[2], bl[3], Bl + boff + ka);
        ldsm4(bl[4], bl[5], bl[6], bl[7], Bl + boff + 16 * ROWB + ka);
        #pragma unroll
        for (int p = 0; p < 2; ++p)
        #pragma unroll
        for (int j = 0; j < 2; ++j) {
            const int nt = p * 2 + j;
            const u32 b0h = bh[p*4 + j*2], b1h = bh[p*4 + j*2 + 1];
            const u32 b0l = bl[p*4 + j*2], b1l = bl[p*4 + j*2 + 1];
            mma16816(acc[nt],     ah0, b0h, b1h);
            mma16816(acc[4 + nt], ah1, b0h, b1h);
            mma16816(acc[nt],     al0, b0h, b1h);
            mma16816(acc[4 + nt], al1, b0h, b1h);
            mma16816(acc[nt],     ah0, b0l, b1l);
            mma16816(acc[4 + nt], ah1, b0l, b1l);
        }
    }
}

// ---------------- LN epilogue on register fragments ----------------
template<bool HASB, bool RELU>
static __device__ __forceinline__ void ln_tile(
    float (&acc)[8][4], int wrow, int wcol, int lr, int lc, int cw,
    const float* __restrict__ bias, const float* __restrict__ gam,
    const float* __restrict__ bet, float* RS, float* RQ)
{
    float s[4] = {0.f,0.f,0.f,0.f}, q[4] = {0.f,0.f,0.f,0.f};
    #pragma unroll
    for (int rt = 0; rt < 2; ++rt)
    #pragma unroll
    for (int nt = 0; nt < 4; ++nt) {
        float* a = acc[rt * 4 + nt];
        if (HASB) {
            int c = wcol + nt * 8 + lc * 2;
            float bx = bias[c], by = bias[c + 1];
            a[0] += bx; a[1] += by; a[2] += bx; a[3] += by;
        }
        s[rt*2+0] += a[0] + a[1]; q[rt*2+0] += a[0]*a[0] + a[1]*a[1];
        s[rt*2+1] += a[2] + a[3]; q[rt*2+1] += a[2]*a[2] + a[3]*a[3];
    }
    #pragma unroll
    for (int off = 1; off <= 2; off <<= 1)
        #pragma unroll
        for (int i = 0; i < 4; ++i) {
            s[i] += __shfl_xor_sync(0xffffffffu, s[i], off);
            q[i] += __shfl_xor_sync(0xffffffffu, q[i], off);
        }
    if (lc == 0) {
        #pragma unroll
        for (int i = 0; i < 4; ++i) {
            int row = wrow + (i >> 1) * 16 + (i & 1) * 8 + lr;
            RS[cw * 128 + row] = s[i];
            RQ[cw * 128 + row] = q[i];
        }
    }
    __syncthreads();
    float mm[4], rsd[4];
    #pragma unroll
    for (int i = 0; i < 4; ++i) {
        int row = wrow + (i >> 1) * 16 + (i & 1) * 8 + lr;
        float S = RS[row] + RS[128 + row] + RS[256 + row] + RS[384 + row];
        float Q = RQ[row] + RQ[128 + row] + RQ[256 + row] + RQ[384 + row];
        float m = S * (1.f / 128.f);
        mm[i] = m;
        rsd[i] = rsqrtf(Q * (1.f / 128.f) - m * m + LNEPS);
    }
    __syncthreads();
    #pragma unroll
    for (int rt = 0; rt < 2; ++rt)
    #pragma unroll
    for (int nt = 0; nt < 4; ++nt) {
        int c = wcol + nt * 8 + lc * 2;
        float gx = gam[c], gy = gam[c + 1], ex = bet[c], ey = bet[c + 1];
        float* a = acc[rt * 4 + nt];
        int s0 = rt * 2, s1 = rt * 2 + 1;
        a[0] = (a[0] - mm[s0]) * rsd[s0] * gx + ex;
        a[1] = (a[1] - mm[s0]) * rsd[s0] * gy + ey;
        a[2] = (a[2] - mm[s1]) * rsd[s1] * gx + ex;
        a[3] = (a[3] - mm[s1]) * rsd[s1] * gy + ey;
        if (RELU) {
            a[0] = fmaxf(a[0], 0.f); a[1] = fmaxf(a[1], 0.f);
            a[2] = fmaxf(a[2], 0.f); a[3] = fmaxf(a[3], 0.f);
        }
    }
}

static __device__ __forceinline__ void store_acc_split(
    const float (&acc)[8][4], u32* hi, u32* lo, int wrow, int wcol, int lr, int lc)
{
    #pragma unroll
    for (int rt = 0; rt < 2; ++rt)
    #pragma unroll
    for (int hh = 0; hh < 2; ++hh) {
        int row = wrow + rt * 16 + hh * 8 + lr;
        u32 base = row * PADU + (wcol >> 1) + lc;
        #pragma unroll
        for (int nt = 0; nt < 4; ++nt) {
            float v0 = acc[rt*4+nt][hh*2+0], v1 = acc[rt*4+nt][hh*2+1];
            hi[base + nt*4] = packsplit_hi(v0, v1);
            lo[base + nt*4] = packsplit_lo(v0, v1);
        }
    }
}

static __device__ __forceinline__ void store_split4(u32* hi, u32* lo, int row, int col, float4 xv) {
    u32 idx = row * PADU + (col >> 1);
    hi[idx]   = packsplit_hi(xv.x, xv.y);
    hi[idx+1] = packsplit_hi(xv.z, xv.w);
    lo[idx]   = packsplit_lo(xv.x, xv.y);
    lo[idx+1] = packsplit_lo(xv.z, xv.w);
}

static __device__ __forceinline__ void load_wsplit(u32* hi, u32* lo, const float* __restrict__ w,
                                                   int tid, int nth) {
    for (int idx = tid; idx < HD * HD / 2; idx += nth) {
        int o = idx & 127, k2 = idx >> 7;
        float v0 = w[(2*k2)   * HD + o];
        float v1 = w[(2*k2+1) * HD + o];
        u32 off = o * PADU + k2;
        hi[off] = packsplit_hi(v0, v1);
        lo[off] = packsplit_lo(v0, v1);
    }
}

__global__ void k_init_lanemax() {
    int i = blockIdx.x * blockDim.x + threadIdx.x;
    if (i < NLANES * HD) g_lanemax[i] = 0;
}

#define WSZ 34816

// per-warp fragment offsets
static __device__ __forceinline__ u32 mk_aoff(int wrow, int lane) {
    return (u32)((wrow + (lane & 15)) * ROWB + ((lane >> 4) & 1) * 16);
}
static __device__ __forceinline__ u32 mk_boff(int wcol, int lane) {
    return (u32)((wcol + ((lane >> 4) & 1) * 8 + (lane & 7)) * ROWB + ((lane >> 3) & 1) * 16);
}

// ======================== fc1 ========================
__global__ void __launch_bounds__(512, 1) k_fc1(
    const float* __restrict__ x, const int* __restrict__ lane_ids,
    const float* __restrict__ w1a, const float* __restrict__ b1a,
    const float* __restrict__ g1a, const float* __restrict__ be1a,
    const float* __restrict__ w1b, const float* __restrict__ b1b,
    const float* __restrict__ g1b, const float* __restrict__ be1b)
{
    extern __shared__ char sm[];
    u32* WA_HI = (u32*)(sm);            u32* WA_LO = (u32*)(sm + WSZ);
    u32* WB_HI = (u32*)(sm + 2*WSZ);    u32* WB_LO = (u32*)(sm + 3*WSZ);
    u32* A_HI  = (u32*)(sm + 4*WSZ);    u32* A_LO  = (u32*)(sm + 5*WSZ);
    float* P  = (float*)(sm + 6*WSZ);
    float* RS = (float*)(sm + 6*WSZ + 3072);
    float* RQ = (float*)(sm + 6*WSZ + 5120);

    const int tid = threadIdx.x, w = tid >> 5, lane = tid & 31;
    const int lr = lane >> 2, lc = lane & 3;
    const int wrow = (w & 3) * 32, wcol = (w >> 2) * 32, cw = w >> 2;
    const u32 aoff = mk_aoff(wrow, lane), boff = mk_boff(wcol, lane);
    const u32 sAH = smem_u32(A_HI), sAL = smem_u32(A_LO);
    const u32 sWAH = smem_u32(WA_HI), sWAL = smem_u32(WA_LO);
    const u32 sWBH = smem_u32(WB_HI), sWBL = smem_u32(WB_LO);

    load_wsplit(WA_HI, WA_LO, w1a, tid, 512);
    load_wsplit(WB_HI, WB_LO, w1b, tid, 512);
    for (int i = tid; i < HD; i += 512) {
        P[i] = b1a[i]; P[128+i] = g1a[i]; P[256+i] = be1a[i];
        P[384+i] = b1b[i]; P[512+i] = g1b[i]; P[640+i] = be1b[i];
    }
    __syncthreads();

    for (int t = blockIdx.x; t < NT; t += gridDim.x) {
        int r0 = t * TM;
        #pragma unroll
        for (int j = 0; j < 8; ++j) {
            int idx = tid + j * 512; int xr = idx >> 5; int cg = idx & 31;
            int grow = r0 + xr; if (grow >= NROWS) grow = NROWS - 1;
            float4 xv = __ldg(((const float4*)x) + ((size_t)grow * 32 + cg));
            store_split4(A_HI, A_LO, xr, cg * 4, xv);
        }
        __syncthreads();

        float acc[8][4];
        #pragma unroll
        for (int i = 0; i < 8; ++i) { acc[i][0]=acc[i][1]=acc[i][2]=acc[i][3]=0.f; }
        gemm_merged(sAH, sAL, sWAH, sWAL, aoff, boff, acc);
        ln_tile<true, true>(acc, wrow, wcol, lr, lc, cw, P, P+128, P+256, RS, RQ);
        store_acc_split(acc, A_HI, A_LO, wrow, wcol, lr, lc);
        __syncthreads();

        #pragma unroll
        for (int i = 0; i < 8; ++i) { acc[i][0]=acc[i][1]=acc[i][2]=acc[i][3]=0.f; }
        gemm_merged(sAH, sAL, sWBH, sWBL, aoff, boff, acc);
        ln_tile<true, true>(acc, wrow, wcol, lr, lc, cw, P+384, P+512, P+640, RS, RQ);

        #pragma unroll
        for (int rt = 0; rt < 2; ++rt)
        #pragma unroll
        for (int hh = 0; hh < 2; ++hh) {
            int row = wrow + rt*16 + hh*8 + lr;
            int grow = r0 + row; if (grow >= NROWS) grow = NROWS - 1;
            int ln = __ldg(lane_ids + grow);
            int* bp = g_lanemax + ln * HD;
            #pragma unroll
            for (int nt = 0; nt < 4; ++nt) {
                int c = wcol + nt*8 + lc*2;
                atomicMax(bp + c,     __float_as_int(acc[rt*4+nt][hh*2+0]));
                atomicMax(bp + c + 1, __float_as_int(acc[rt*4+nt][hh*2+1]));
            }
        }
        store_acc_split(acc, A_HI, A_LO, wrow, wcol, lr, lc);
        __syncthreads();

        const uint4* s4 = (const uint4*)A_HI;
        uint4* d4 = g_h + (size_t)t * TILEU4;
        for (int i = tid; i < TILEU4; i += 512) d4[i] = s4[i];
        __syncthreads();
    }
}

// ======================== fc2a ========================
__global__ void __launch_bounds__(512, 1) k_fc2a(
    const int* __restrict__ lane_ids,
    const float* __restrict__ w2a, const float* __restrict__ b2a,
    const float* __restrict__ g2a, const float* __restrict__ be2a)
{
    extern __shared__ char sm[];
    u32* W1_HI = (u32*)(sm);            u32* W1_LO = (u32*)(sm + WSZ);
    u32* W2_HI = (u32*)(sm + 2*WSZ);    u32* W2_LO = (u32*)(sm + 3*WSZ);
    u32* A_HI  = (u32*)(sm + 4*WSZ);    u32* A_LO  = (u32*)(sm + 5*WSZ);
    float* P  = (float*)(sm + 6*WSZ);
    float* RS = (float*)(sm + 6*WSZ + 1536);
    float* RQ = (float*)(sm + 6*WSZ + 3584);

    const int tid = threadIdx.x, w = tid >> 5, lane = tid & 31;
    const int lr = lane >> 2, lc = lane & 3;
    const int wrow = (w & 3) * 32, wcol = (w >> 2) * 32, cw = w >> 2;
    const u32 aoff = mk_aoff(wrow, lane), boff = mk_boff(wcol, lane);
    const u32 sAH = smem_u32(A_HI), sAL = smem_u32(A_LO);
    const u32 sW1H = smem_u32(W1_HI), sW1L = smem_u32(W1_LO);
    const u32 sW2H = smem_u32(W2_HI), sW2L = smem_u32(W2_LO);

    load_wsplit(W1_HI, W1_LO, w2a,            tid, 512);
    load_wsplit(W2_HI, W2_LO, w2a + 128 * HD, tid, 512);
    for (int i = tid; i < HD; i += 512) { P[i] = b2a[i]; P[128+i] = g2a[i]; P[256+i] = be2a[i]; }
    __syncthreads();

    const int grow_t = tid & 127;
    const int gc0 = (tid >> 7) * 32;

    for (int t = blockIdx.x; t < NT; t += gridDim.x) {
        int r0 = t * TM;
        {   // cp.async bulk copy of split h tile
            const uint4* s4 = g_h + (size_t)t * TILEU4;
            #pragma unroll
            for (int j = 0; j < 8; ++j) {
                int i = tid + j * 512;
                if (i < TILEU4) CP16(sAH + (u32)i * 16, s4 + i);
            }
            CP_WAIT();
        }
        // prefetch lane-max gather target into L2 (consumed after GEMM1)
        int grow = r0 + grow_t; if (grow >= NROWS) grow = NROWS - 1;
        int lnid = __ldg(lane_ids + grow);
        const int4* gp = (const int4*)(g_lanemax + lnid * HD + gc0);
        PREF_L2(gp);
        __syncthreads();

        float acc[8][4];
        #pragma unroll
        for (int i = 0; i < 8; ++i) { acc[i][0]=acc[i][1]=acc[i][2]=acc[i][3]=0.f; }
        gemm_merged(sAH, sAL, sW1H, sW1L, aoff, boff, acc);
        __syncthreads();

        // overwrite A with gathered lane-max
        #pragma unroll
        for (int j = 0; j < 8; ++j) {
            int4 gv = __ldg(gp + j);
            store_split4(A_HI, A_LO, grow_t, gc0 + j * 4,
                make_float4(__int_as_float(gv.x), __int_as_float(gv.y),
                            __int_as_float(gv.z), __int_as_float(gv.w)));
        }
        __syncthreads();
        gemm_merged(sAH, sAL, sW2H, sW2L, aoff, boff, acc);
        ln_tile<true, true>(acc, wrow, wcol, lr, lc, cw, P, P+128, P+256, RS, RQ);
        store_acc_split(acc, A_HI, A_LO, wrow, wcol, lr, lc);
        __syncthreads();

        const uint4* s4 = (const uint4*)A_HI;
        uint4* d4 = g_f + (size_t)t * TILEU4;
        for (int i = tid; i < TILEU4; i += 512) d4[i] = s4[i];
        __syncthreads();
    }
}

// ======================== fc2b ========================
__global__ void __launch_bounds__(512, 1) k_fc2b(
    const float* __restrict__ x,
    const float* __restrict__ w2b, const float* __restrict__ b2b,
    const float* __restrict__ g2b, const float* __restrict__ be2b,
    const float* __restrict__ gn, const float* __restrict__ bn,
    float* __restrict__ out)
{
    extern __shared__ char sm[];
    u32* W_HI = (u32*)(sm);            u32* W_LO = (u32*)(sm + WSZ);
    u32* A_HI = (u32*)(sm + 2*WSZ);    u32* A_LO = (u32*)(sm + 3*WSZ);
    float* P  = (float*)(sm + 4*WSZ);
    float* RS = (float*)(sm + 4*WSZ + 2560);
    float* RQ = (float*)(sm + 4*WSZ + 4608);

    const int tid = threadIdx.x, w = tid >> 5, lane = tid & 31;
    const int lr = lane >> 2, lc = lane & 3;
    const int wrow = (w & 3) * 32, wcol = (w >> 2) * 32, cw = w >> 2;
    const u32 aoff = mk_aoff(wrow, lane), boff = mk_boff(wcol, lane);
    const u32 sAH = smem_u32(A_HI), sAL = smem_u32(A_LO);
    const u32 sWH = smem_u32(W_HI), sWL = smem_u32(W_LO);

    load_wsplit(W_HI, W_LO, w2b, tid, 512);
    for (int i = tid; i < HD; i += 512) {
        P[i] = b2b[i]; P[128+i] = g2b[i]; P[256+i] = be2b[i]; P[384+i] = gn[i]; P[512+i] = bn[i];
    }
    __syncthreads();

    for (int t = blockIdx.x; t < NT; t += gridDim.x) {
        int r0 = t * TM;
        {   // cp.async bulk copy of split f tile
            const uint4* s4 = g_f + (size_t)t * TILEU4;
            #pragma unroll
            for (int j = 0; j < 8; ++j) {
                int i = tid + j * 512;
                if (i < TILEU4) CP16(sAH + (u32)i * 16, s4 + i);
            }
            CP_WAIT();
        }
        // prefetch x residual rows into L2
        {
            int xr = tid >> 2; int seg = (tid & 3) * 32;
            int grow = r0 + xr; if (grow >= NROWS) grow = NROWS - 1;
            PREF_L2(x + (size_t)grow * HD + seg);
        }
        __syncthreads();

        float acc[8][4];
        #pragma unroll
        for (int i = 0; i < 8; ++i) { acc[i][0]=acc[i][1]=acc[i][2]=acc[i][3]=0.f; }
        gemm_merged(sAH, sAL, sWH, sWL, aoff, boff, acc);
        ln_tile<true, true>(acc, wrow, wcol, lr, lc, cw, P, P+128, P+256, RS, RQ);

        // residual add straight from gmem (sector-aligned float2 per fragment)
        #pragma unroll
        for (int rt = 0; rt < 2; ++rt)
        #pragma unroll
        for (int hh = 0; hh < 2; ++hh) {
            int row = wrow + rt*16 + hh*8 + lr;
            int grow = r0 + row; if (grow >= NROWS) grow = NROWS - 1;
            #pragma unroll
            for (int nt = 0; nt < 4; ++nt) {
                int c = wcol + nt*8 + lc*2;
                float2 xv = __ldg((const float2*)(x + (size_t)grow * HD + c));
                acc[rt*4+nt][hh*2+0] += xv.x;
                acc[rt*4+nt][hh*2+1] += xv.y;
            }
        }
        ln_tile<false, false>(acc, wrow, wcol, lr, lc, cw, P, P+384, P+512, RS, RQ);

        // write out straight from registers (32B-sector aligned float2 stores)
        #pragma unroll
        for (int rt = 0; rt < 2; ++rt)
        #pragma unroll
        for (int hh = 0; hh < 2; ++hh) {
            int row = wrow + rt*16 + hh*8 + lr;
            int grow = r0 + row;
            if (grow < NROWS) {
                #pragma unroll
                for (int nt = 0; nt < 4; ++nt) {
                    int c = wcol + nt*8 + lc*2;
                    *(float2*)(out + (size_t)grow * HD + c) =
                        make_float2(acc[rt*4+nt][hh*2+0], acc[rt*4+nt][hh*2+1]);
                }
            }
        }
        __syncthreads();
    }
}

// ---------------- launcher ----------------
extern "C" void kernel_launch(void* const* d_in, const int* in_sizes, int n_in,
                              void* d_out, int out_size) {
    (void)in_sizes; (void)n_in; (void)out_size;
    const float* x        = (const float*)d_in[0];
    const int*   lane_ids = (const int*)  d_in[1];
    const float* w1a  = (const float*)d_in[2];
    const float* b1a  = (const float*)d_in[3];
    const float* g1a  = (const float*)d_in[4];
    const float* be1a = (const float*)d_in[5];
    const float* w1b  = (const float*)d_in[6];
    const float* b1b  = (const float*)d_in[7];
    const float* g1b  = (const float*)d_in[8];
    const float* be1b = (const float*)d_in[9];
    const float* w2a  = (const float*)d_in[10];
    const float* b2a  = (const float*)d_in[11];
    const float* g2a  = (const float*)d_in[12];
    const float* be2a = (const float*)d_in[13];
    const float* w2b  = (const float*)d_in[14];
    const float* b2b  = (const float*)d_in[15];
    const float* g2b  = (const float*)d_in[16];
    const float* be2b = (const float*)d_in[17];
    const float* gn   = (const float*)d_in[18];
    const float* bn   = (const float*)d_in[19];
    float* out = (float*)d_out;

    const int SM1  = 6*WSZ + 3072 + 4096;   // 216064
    const int SM2A = 6*WSZ + 1536 + 4096;   // 214528
    const int SM2B = 4*WSZ + 2560 + 4096;   // 145920
    cudaFuncSetAttribute(k_fc1,  cudaFuncAttributeMaxDynamicSharedMemorySize, SM1);
    cudaFuncSetAttribute(k_fc2a, cudaFuncAttributeMaxDynamicSharedMemorySize, SM2A);
    cudaFuncSetAttribute(k_fc2b, cudaFuncAttributeMaxDynamicSharedMemorySize, SM2B);

    k_init_lanemax<<<(NLANES * HD + 511) / 512, 512>>>();
    k_fc1 <<<148, 512, SM1>>> (x, lane_ids, w1a, b1a, g1a, be1a, w1b, b1b, g1b, be1b);
    k_fc2a<<<148, 512, SM2A>>>(lane_ids, w2a, b2a, g2a, be2a);
    k_fc2b<<<148, 512, SM2B>>>(x, w2b, b2b, g2b, be2b, gn, bn, out);
}

// round 5
// speedup vs baseline: 1.5324x; 1.0117x over previous
#include <cuda_runtime.h>
#include <cuda_bf16.h>
#include <cstdint>

#define NROWS  300000
#define HD     128
#define NLANES 25000
#define LNEPS  1e-5f
#define TM     128
#define NT     ((NROWS + TM - 1) / TM)   // 2344 tiles
#define PADU   68                         // u32 per 128-bf16 row (272B, 16B-aligned, conflict-free)
#define ROWB   272                        // row stride bytes
#define TILEU4 4352                       // uint4 per split tile image (hi+lo)

typedef unsigned int       u32;
typedef unsigned short     u16;
typedef unsigned long long u64;

// ---------------- device scratch ----------------
__device__ uint4 g_h[(size_t)NT * TILEU4];   // fc1 output image (split, padded)
__device__ uint4 g_f[(size_t)NT * TILEU4];   // fc2a output image
__device__ int   g_lanemax[NLANES * HD];     // per-lane max (float bits, relu>=0)

// ---------------- helpers ----------------
static __device__ __forceinline__ u32 smem_u32(const void* p) {
    u32 a;
    asm("{ .reg .u64 t; cvta.to.shared.u64 t, %1; cvt.u32.u64 %0, t; }" : "=r"(a) : "l"(p));
    return a;
}
static __device__ __forceinline__ u16 f2bf(float f) {
    return __bfloat16_as_ushort(__float2bfloat16(f));
}
static __device__ __forceinline__ float bf2f(u16 u) {
    return __uint_as_float(((u32)u) << 16);
}
static __device__ __forceinline__ u32 packsplit_hi(float v0, float v1) {
    return (u32)f2bf(v0) | ((u32)f2bf(v1) << 16);
}
static __device__ __forceinline__ u32 packsplit_lo(float v0, float v1) {
    u16 h0 = f2bf(v0), h1 = f2bf(v1);
    return (u32)f2bf(v0 - bf2f(h0)) | ((u32)f2bf(v1 - bf2f(h1)) << 16);
}

#define CP16(sm_addr, gptr) \
    asm volatile("cp.async.cg.shared.global [%0], [%1], 16;" :: "r"(sm_addr), "l"(gptr))
#define CP_COMMIT() asm volatile("cp.async.commit_group;" ::: "memory")
#define CP_WAIT0()  asm volatile("cp.async.wait_group 0;" ::: "memory")
#define PREF_L2(p)  asm volatile("prefetch.global.L2 [%0];" :: "l"(p))

static __device__ __forceinline__ void ldsm4(u32& r0, u32& r1, u32& r2, u32& r3, u32 addr) {
    asm volatile("ldmatrix.sync.aligned.m8n8.x4.shared.b16 {%0,%1,%2,%3}, [%4];"
        : "=r"(r0), "=r"(r1), "=r"(r2), "=r"(r3) : "r"(addr));
}
static __device__ __forceinline__ void mma16816(float (&d)[4], const u32 (&a)[4], u32 b0, u32 b1) {
    asm volatile("mma.sync.aligned.m16n8k16.row.col.f32.bf16.bf16.f32 "
        "{%0,%1,%2,%3}, {%4,%5,%6,%7}, {%8,%9}, {%0,%1,%2,%3};"
        : "+f"(d[0]), "+f"(d[1]), "+f"(d[2]), "+f"(d[3])
        : "r"(a[0]), "r"(a[1]), "r"(a[2]), "r"(a[3]), "r"(b0), "r"(b1));
}

// Merged split GEMM: acc += Ah*Bh^T + Al*Bh^T + Ah*Bl^T over K=128.
static __device__ __forceinline__ void gemm_merged(
    u32 Ah, u32 Al, u32 Bh, u32 Bl, u32 aoff, u32 boff, float (&acc)[8][4])
{
    #pragma unroll
    for (int kc = 0; kc < 8; ++kc) {
        const u32 ka = kc * 32;
        u32 ah0[4], ah1[4], al0[4], al1[4], bh[8], bl[8];
        ldsm4(ah0[0], ah0[1], ah0[2], ah0[3], Ah + aoff + ka);
        ldsm4(ah1[0], ah1[1], ah1[2], ah1[3], Ah + aoff + 16 * ROWB + ka);
        ldsm4(al0[0], al0[1], al0[2], al0[3], Al + aoff + ka);
        ldsm4(al1[0], al1[1], al1[2], al1[3], Al + aoff + 16 * ROWB + ka);
        ldsm4(bh[0], bh[1], bh[2], bh[3], Bh + boff + ka);
        ldsm4(bh[4], bh[5], bh[6], bh[7], Bh + boff + 16 * ROWB + ka);
        ldsm4(bl[0], bl[1], bl[2], bl[3], Bl + boff + ka);
        ldsm4(bl[4], bl[5], bl[6], bl[7], Bl + boff + 16 * ROWB + ka);
        #pragma unroll
        for (int p = 0; p < 2; ++p)
        #pragma unroll
        for (int j = 0; j < 2; ++j) {
            const int nt = p * 2 + j;
            const u32 b0h = bh[p*4 + j*2], b1h = bh[p*4 + j*2 + 1];
            const u32 b0l = bl[p*4 + j*2], b1l = bl[p*4 + j*2 + 1];
            mma16816(acc[nt],     ah0, b0h, b1h);
            mma16816(acc[4 + nt], ah1, b0h, b1h);
            mma16816(acc[nt],     al0, b0h, b1h);
            mma16816(acc[4 + nt], al1, b0h, b1h);
            mma16816(acc[nt],     ah0, b0l, b1l);
            mma16816(acc[4 + nt], ah1, b0l, b1l);
        }
    }
}

// ---------------- LN epilogue on register fragments ----------------
template<bool HASB, bool RELU>
static __device__ __forceinline__ void ln_tile(
    float (&acc)[8][4], int wrow, int wcol, int lr, int lc, int cw,
    const float* __restrict__ bias, const float* __restrict__ gam,
    const float* __restrict__ bet, float* RS, float* RQ)
{
    float s[4] = {0.f,0.f,0.f,0.f}, q[4] = {0.f,0.f,0.f,0.f};
    #pragma unroll
    for (int rt = 0; rt < 2; ++rt)
    #pragma unroll
    for (int nt = 0; nt < 4; ++nt) {
        float* a = acc[rt * 4 + nt];
        if (HASB) {
            int c = wcol + nt * 8 + lc * 2;
            float bx = bias[c], by = bias[c + 1];
            a[0] += bx; a[1] += by; a[2] += bx; a[3] += by;
        }
        s[rt*2+0] += a[0] + a[1]; q[rt*2+0] += a[0]*a[0] + a[1]*a[1];
        s[rt*2+1] += a[2] + a[3]; q[rt*2+1] += a[2]*a[2] + a[3]*a[3];
    }
    #pragma unroll
    for (int off = 1; off <= 2; off <<= 1)
        #pragma unroll
        for (int i = 0; i < 4; ++i) {
            s[i] += __shfl_xor_sync(0xffffffffu, s[i], off);
            q[i] += __shfl_xor_sync(0xffffffffu, q[i], off);
        }
    if (lc == 0) {
        #pragma unroll
        for (int i = 0; i < 4; ++i) {
            int row = wrow + (i >> 1) * 16 + (i & 1) * 8 + lr;
            RS[cw * 128 + row] = s[i];
            RQ[cw * 128 + row] = q[i];
        }
    }
    __syncthreads();
    float mm[4], rsd[4];
    #pragma unroll
    for (int i = 0; i < 4; ++i) {
        int row = wrow + (i >> 1) * 16 + (i & 1) * 8 + lr;
        float S = RS[row] + RS[128 + row] + RS[256 + row] + RS[384 + row];
        float Q = RQ[row] + RQ[128 + row] + RQ[256 + row] + RQ[384 + row];
        float m = S * (1.f / 128.f);
        mm[i] = m;
        rsd[i] = rsqrtf(Q * (1.f / 128.f) - m * m + LNEPS);
    }
    __syncthreads();
    #pragma unroll
    for (int rt = 0; rt < 2; ++rt)
    #pragma unroll
    for (int nt = 0; nt < 4; ++nt) {
        int c = wcol + nt * 8 + lc * 2;
        float gx = gam[c], gy = gam[c + 1], ex = bet[c], ey = bet[c + 1];
        float* a = acc[rt * 4 + nt];
        int s0 = rt * 2, s1 = rt * 2 + 1;
        a[0] = (a[0] - mm[s0]) * rsd[s0] * gx + ex;
        a[1] = (a[1] - mm[s0]) * rsd[s0] * gy + ey;
        a[2] = (a[2] - mm[s1]) * rsd[s1] * gx + ex;
        a[3] = (a[3] - mm[s1]) * rsd[s1] * gy + ey;
        if (RELU) {
            a[0] = fmaxf(a[0], 0.f); a[1] = fmaxf(a[1], 0.f);
            a[2] = fmaxf(a[2], 0.f); a[3] = fmaxf(a[3], 0.f);
        }
    }
}

static __device__ __forceinline__ void store_acc_split(
    const float (&acc)[8][4], u32* hi, u32* lo, int wrow, int wcol, int lr, int lc)
{
    #pragma unroll
    for (int rt = 0; rt < 2; ++rt)
    #pragma unroll
    for (int hh = 0; hh < 2; ++hh) {
        int row = wrow + rt * 16 + hh * 8 + lr;
        u32 base = row * PADU + (wcol >> 1) + lc;
        #pragma unroll
        for (int nt = 0; nt < 4; ++nt) {
            float v0 = acc[rt*4+nt][hh*2+0], v1 = acc[rt*4+nt][hh*2+1];
            hi[base + nt*4] = packsplit_hi(v0, v1);
            lo[base + nt*4] = packsplit_lo(v0, v1);
        }
    }
}

static __device__ __forceinline__ void store_split4(u32* hi, u32* lo, int row, int col, float4 xv) {
    u32 idx = row * PADU + (col >> 1);
    hi[idx]   = packsplit_hi(xv.x, xv.y);
    hi[idx+1] = packsplit_hi(xv.z, xv.w);
    lo[idx]   = packsplit_lo(xv.x, xv.y);
    lo[idx+1] = packsplit_lo(xv.z, xv.w);
}

static __device__ __forceinline__ void load_wsplit(u32* hi, u32* lo, const float* __restrict__ w,
                                                   int tid, int nth) {
    for (int idx = tid; idx < HD * HD / 2; idx += nth) {
        int o = idx & 127, k2 = idx >> 7;
        float v0 = w[(2*k2)   * HD + o];
        float v1 = w[(2*k2+1) * HD + o];
        u32 off = o * PADU + k2;
        hi[off] = packsplit_hi(v0, v1);
        lo[off] = packsplit_lo(v0, v1);
    }
}

__global__ void k_init_lanemax() {
    int i = blockIdx.x * blockDim.x + threadIdx.x;
    if (i < NLANES * HD) g_lanemax[i] = 0;
}

#define WSZ 34816

static __device__ __forceinline__ u32 mk_aoff(int wrow, int lane) {
    return (u32)((wrow + (lane & 15)) * ROWB + ((lane >> 4) & 1) * 16);
}
static __device__ __forceinline__ u32 mk_boff(int wcol, int lane) {
    return (u32)((wcol + ((lane >> 4) & 1) * 8 + (lane & 7)) * ROWB + ((lane >> 3) & 1) * 16);
}

// ======================== fc1 ========================
__global__ void __launch_bounds__(512, 1) k_fc1(
    const float* __restrict__ x, const int* __restrict__ lane_ids,
    const float* __restrict__ w1a, const float* __restrict__ b1a,
    const float* __restrict__ g1a, const float* __restrict__ be1a,
    const float* __restrict__ w1b, const float* __restrict__ b1b,
    const float* __restrict__ g1b, const float* __restrict__ be1b)
{
    extern __shared__ char sm[];
    u32* WA_HI = (u32*)(sm);            u32* WA_LO = (u32*)(sm + WSZ);
    u32* WB_HI = (u32*)(sm + 2*WSZ);    u32* WB_LO = (u32*)(sm + 3*WSZ);
    u32* A_HI  = (u32*)(sm + 4*WSZ);    u32* A_LO  = (u32*)(sm + 5*WSZ);
    float* P  = (float*)(sm + 6*WSZ);
    float* RS = (float*)(sm + 6*WSZ + 3072);
    float* RQ = (float*)(sm + 6*WSZ + 5120);

    const int tid = threadIdx.x, w = tid >> 5, lane = tid & 31;
    const int lr = lane >> 2, lc = lane & 3;
    const int wrow = (w & 3) * 32, wcol = (w >> 2) * 32, cw = w >> 2;
    const u32 aoff = mk_aoff(wrow, lane), boff = mk_boff(wcol, lane);
    const u32 sAH = smem_u32(A_HI), sAL = smem_u32(A_LO);
    const u32 sWAH = smem_u32(WA_HI), sWAL = smem_u32(WA_LO);
    const u32 sWBH = smem_u32(WB_HI), sWBL = smem_u32(WB_LO);

    load_wsplit(WA_HI, WA_LO, w1a, tid, 512);
    load_wsplit(WB_HI, WB_LO, w1b, tid, 512);
    for (int i = tid; i < HD; i += 512) {
        P[i] = b1a[i]; P[128+i] = g1a[i]; P[256+i] = be1a[i];
        P[384+i] = b1b[i]; P[512+i] = g1b[i]; P[640+i] = be1b[i];
    }
    // prefetch first x tile into L2
    {
        int grow = blockIdx.x * TM + (tid >> 2);
        if (grow < NROWS) PREF_L2((const char*)x + (size_t)blockIdx.x * TM * HD * 4 + tid * 128);
    }
    __syncthreads();

    for (int t = blockIdx.x; t < NT; t += gridDim.x) {
        int r0 = t * TM;
        #pragma unroll
        for (int j = 0; j < 8; ++j) {
            int idx = tid + j * 512; int xr = idx >> 5; int cg = idx & 31;
            int grow = r0 + xr; if (grow >= NROWS) grow = NROWS - 1;
            float4 xv = __ldg(((const float4*)x) + ((size_t)grow * 32 + cg));
            store_split4(A_HI, A_LO, xr, cg * 4, xv);
        }
        // prefetch NEXT tile's x into L2 (overlaps with GEMMs below)
        {
            int tn = t + gridDim.x; if (tn >= NT) tn = t;
            int grow = tn * TM + (tid >> 2);
            if (grow < NROWS) PREF_L2((const char*)x + (size_t)tn * TM * HD * 4 + tid * 128);
        }
        __syncthreads();

        float acc[8][4];
        #pragma unroll
        for (int i = 0; i < 8; ++i) { acc[i][0]=acc[i][1]=acc[i][2]=acc[i][3]=0.f; }
        gemm_merged(sAH, sAL, sWAH, sWAL, aoff, boff, acc);
        ln_tile<true, true>(acc, wrow, wcol, lr, lc, cw, P, P+128, P+256, RS, RQ);
        store_acc_split(acc, A_HI, A_LO, wrow, wcol, lr, lc);
        __syncthreads();

        #pragma unroll
        for (int i = 0; i < 8; ++i) { acc[i][0]=acc[i][1]=acc[i][2]=acc[i][3]=0.f; }
        gemm_merged(sAH, sAL, sWBH, sWBL, aoff, boff, acc);
        ln_tile<true, true>(acc, wrow, wcol, lr, lc, cw, P+384, P+512, P+640, RS, RQ);

        // scatter-max: predicated on v>0 (relu zeros are no-ops vs init 0)
        #pragma unroll
        for (int rt = 0; rt < 2; ++rt)
        #pragma unroll
        for (int hh = 0; hh < 2; ++hh) {
            int row = wrow + rt*16 + hh*8 + lr;
            int grow = r0 + row; if (grow >= NROWS) grow = NROWS - 1;
            int ln = __ldg(lane_ids + grow);
            int* bp = g_lanemax + ln * HD;
            #pragma unroll
            for (int nt = 0; nt < 4; ++nt) {
                int c = wcol + nt*8 + lc*2;
                float v0 = acc[rt*4+nt][hh*2+0], v1 = acc[rt*4+nt][hh*2+1];
                if (v0 > 0.f) atomicMax(bp + c,     __float_as_int(v0));
                if (v1 > 0.f) atomicMax(bp + c + 1, __float_as_int(v1));
            }
        }
        store_acc_split(acc, A_HI, A_LO, wrow, wcol, lr, lc);
        __syncthreads();

        const uint4* s4 = (const uint4*)A_HI;
        uint4* d4 = g_h + (size_t)t * TILEU4;
        for (int i = tid; i < TILEU4; i += 512) d4[i] = s4[i];
        __syncthreads();
    }
}

// ======================== fc2a ========================
__global__ void __launch_bounds__(512, 1) k_fc2a(
    const int* __restrict__ lane_ids,
    const float* __restrict__ w2a, const float* __restrict__ b2a,
    const float* __restrict__ g2a, const float* __restrict__ be2a)
{
    extern __shared__ char sm[];
    u32* W1_HI = (u32*)(sm);            u32* W1_LO = (u32*)(sm + WSZ);
    u32* W2_HI = (u32*)(sm + 2*WSZ);    u32* W2_LO = (u32*)(sm + 3*WSZ);
    u32* A_HI  = (u32*)(sm + 4*WSZ);    u32* A_LO  = (u32*)(sm + 5*WSZ);
    float* P  = (float*)(sm + 6*WSZ);
    float* RS = (float*)(sm + 6*WSZ + 1536);
    float* RQ = (float*)(sm + 6*WSZ + 3584);

    const int tid = threadIdx.x, w = tid >> 5, lane = tid & 31;
    const int lr = lane >> 2, lc = lane & 3;
    const int wrow = (w & 3) * 32, wcol = (w >> 2) * 32, cw = w >> 2;
    const u32 aoff = mk_aoff(wrow, lane), boff = mk_boff(wcol, lane);
    const u32 sAH = smem_u32(A_HI), sAL = smem_u32(A_LO);
    const u32 sW1H = smem_u32(W1_HI), sW1L = smem_u32(W1_LO);
    const u32 sW2H = smem_u32(W2_HI), sW2L = smem_u32(W2_LO);

    load_wsplit(W1_HI, W1_LO, w2a,            tid, 512);
    load_wsplit(W2_HI, W2_LO, w2a + 128 * HD, tid, 512);
    for (int i = tid; i < HD; i += 512) { P[i] = b2a[i]; P[128+i] = g2a[i]; P[256+i] = be2a[i]; }
    __syncthreads();

    const int grow_t = tid & 127;
    const int gc0 = (tid >> 7) * 32;

    for (int t = blockIdx.x; t < NT; t += gridDim.x) {
        int r0 = t * TM;
        {   // cp.async copy of current split h tile (FULL image: 9 chunks)
            const uint4* s4 = g_h + (size_t)t * TILEU4;
            #pragma unroll
            for (int j = 0; j < 9; ++j) {
                int i = tid + j * 512;
                if (i < TILEU4) CP16(sAH + (u32)i * 16, s4 + i);
            }
            CP_COMMIT();
        }
        // prefetch NEXT tile's h image into L2 (overlaps the copy + GEMMs)
        {
            int tn = t + gridDim.x; if (tn >= NT) tn = t;
            const char* nh = (const char*)(g_h + (size_t)tn * TILEU4);
            for (int l = tid; l < 544; l += 512) PREF_L2(nh + (size_t)l * 128);
        }
        // prefetch lane-max gather target into L2 (consumed after GEMM1)
        int grow = r0 + grow_t; if (grow >= NROWS) grow = NROWS - 1;
        int lnid = __ldg(lane_ids + grow);
        const int4* gp = (const int4*)(g_lanemax + lnid * HD + gc0);
        PREF_L2(gp);
        CP_WAIT0();
        __syncthreads();

        float acc[8][4];
        #pragma unroll
        for (int i = 0; i < 8; ++i) { acc[i][0]=acc[i][1]=acc[i][2]=acc[i][3]=0.f; }
        gemm_merged(sAH, sAL, sW1H, sW1L, aoff, boff, acc);
        __syncthreads();

        // overwrite A with gathered lane-max
        #pragma unroll
        for (int j = 0; j < 8; ++j) {
            int4 gv = __ldg(gp + j);
            store_split4(A_HI, A_LO, grow_t, gc0 + j * 4,
                make_float4(__int_as_float(gv.x), __int_as_float(gv.y),
                            __int_as_float(gv.z), __int_as_float(gv.w)));
        }
        __syncthreads();
        gemm_merged(sAH, sAL, sW2H, sW2L, aoff, boff, acc);
        ln_tile<true, true>(acc, wrow, wcol, lr, lc, cw, P, P+128, P+256, RS, RQ);
        store_acc_split(acc, A_HI, A_LO, wrow, wcol, lr, lc);
        __syncthreads();

        const uint4* s4 = (const uint4*)A_HI;
        uint4* d4 = g_f + (size_t)t * TILEU4;
        for (int i = tid; i < TILEU4; i += 512) d4[i] = s4[i];
        __syncthreads();
    }
}

// ======================== fc2b (double-buffered pipeline) ========================
__global__ void __launch_bounds__(512, 1) k_fc2b(
    const float* __restrict__ x,
    const float* __restrict__ w2b, const float* __restrict__ b2b,
    const float* __restrict__ g2b, const float* __restrict__ be2b,
    const float* __restrict__ gn, const float* __restrict__ bn,
    float* __restrict__ out)
{
    extern __shared__ char sm[];
    u32* W_HI = (u32*)(sm);            u32* W_LO = (u32*)(sm + WSZ);
    // A buffers: buf0 = [2*WSZ (hi) | 3*WSZ (lo)], buf1 = [4*WSZ | 5*WSZ]
    float* P  = (float*)(sm + 6*WSZ);
    float* RS = (float*)(sm + 6*WSZ + 2560);
    float* RQ = (float*)(sm + 6*WSZ + 2560 + 2048);

    const int tid = threadIdx.x, w = tid >> 5, lane = tid & 31;
    const int lr = lane >> 2, lc = lane & 3;
    const int wrow = (w & 3) * 32, wcol = (w >> 2) * 32, cw = w >> 2;
    const u32 aoff = mk_aoff(wrow, lane), boff = mk_boff(wcol, lane);
    const u32 sWH = smem_u32(W_HI), sWL = smem_u32(W_LO);
    const u32 sA0 = smem_u32(sm + 2*WSZ), sA1 = smem_u32(sm + 4*WSZ);

    load_wsplit(W_HI, W_LO, w2b, tid, 512);
    for (int i = tid; i < HD; i += 512) {
        P[i] = b2b[i]; P[128+i] = g2b[i]; P[256+i] = be2b[i]; P[384+i] = gn[i]; P[512+i] = bn[i];
    }

    // prologue: issue tile(blockIdx.x) image into buf0; prefetch its x rows
    {
        const uint4* s4 = g_f + (size_t)blockIdx.x * TILEU4;
        #pragma unroll
        for (int j = 0; j < 9; ++j) {
            int i = tid + j * 512;
            if (i < TILEU4) CP16(sA0 + (u32)i * 16, s4 + i);
        }
        CP_COMMIT();
        int grow = blockIdx.x * TM + (tid >> 2);
        if (grow < NROWS) PREF_L2((const char*)x + (size_t)blockIdx.x * TM * HD * 4 + tid * 128);
    }
    __syncthreads();

    int buf = 0;
    for (int t = blockIdx.x; t < NT; t += gridDim.x, buf ^= 1) {
        int r0 = t * TM;
        const u32 sA  = buf ? sA1 : sA0;
        const u32 sAn = buf ? sA0 : sA1;

        CP_WAIT0();            // current tile image resident
        __syncthreads();

        // issue NEXT tile image into the other buffer (overlaps GEMM below)
        int tn = t + gridDim.x; if (tn >= NT) tn = t;
        {
            const uint4* s4 = g_f + (size_t)tn * TILEU4;
            #pragma unroll
            for (int j = 0; j < 9; ++j) {
                int i = tid + j * 512;
                if (i < TILEU4) CP16(sAn + (u32)i * 16, s4 + i);
            }
            CP_COMMIT();
            // prefetch next tile's x rows into L2
            int grow = tn * TM + (tid >> 2);
            if (grow < NROWS) PREF_L2((const char*)x + (size_t)tn * TM * HD * 4 + tid * 128);
        }

        float acc[8][4];
        #pragma unroll
        for (int i = 0; i < 8; ++i) { acc[i][0]=acc[i][1]=acc[i][2]=acc[i][3]=0.f; }
        gemm_merged(sA, sA + WSZ, sWH, sWL, aoff, boff, acc);
        ln_tile<true, true>(acc, wrow, wcol, lr, lc, cw, P, P+128, P+256, RS, RQ);

        // residual add straight from gmem (L2-hot via prefetch)
        #pragma unroll
        for (int rt = 0; rt < 2; ++rt)
        #pragma unroll
        for (int hh = 0; hh < 2; ++hh) {
            int row = wrow + rt*16 + hh*8 + lr;
            int grow = r0 + row; if (grow >= NROWS) grow = NROWS - 1;
            #pragma unroll
            for (int nt = 0; nt < 4; ++nt) {
                int c = wcol + nt*8 + lc*2;
                float2 xv = __ldg((const float2*)(x + (size_t)grow * HD + c));
                acc[rt*4+nt][hh*2+0] += xv.x;
                acc[rt*4+nt][hh*2+1] += xv.y;
            }
        }
        ln_tile<false, false>(acc, wrow, wcol, lr, lc, cw, P, P+384, P+512, RS, RQ);

        // write out straight from registers
        #pragma unroll
        for (int rt = 0; rt < 2; ++rt)
        #pragma unroll
        for (int hh = 0; hh < 2; ++hh) {
            int row = wrow + rt*16 + hh*8 + lr;
            int grow = r0 + row;
            if (grow < NROWS) {
                #pragma unroll
                for (int nt = 0; nt < 4; ++nt) {
                    int c = wcol + nt*8 + lc*2;
                    *(float2*)(out + (size_t)grow * HD + c) =
                        make_float2(acc[rt*4+nt][hh*2+0], acc[rt*4+nt][hh*2+1]);
                }
            }
        }
        __syncthreads();   // all reads of sA done before next iter's issue targets it
    }
}

// ---------------- launcher ----------------
extern "C" void kernel_launch(void* const* d_in, const int* in_sizes, int n_in,
                              void* d_out, int out_size) {
    (void)in_sizes; (void)n_in; (void)out_size;
    const float* x        = (const float*)d_in[0];
    const int*   lane_ids = (const int*)  d_in[1];
    const float* w1a  = (const float*)d_in[2];
    const float* b1a  = (const float*)d_in[3];
    const float* g1a  = (const float*)d_in[4];
    const float* be1a = (const float*)d_in[5];
    const float* w1b  = (const float*)d_in[6];
    const float* b1b  = (const float*)d_in[7];
    const float* g1b  = (const float*)d_in[8];
    const float* be1b = (const float*)d_in[9];
    const float* w2a  = (const float*)d_in[10];
    const float* b2a  = (const float*)d_in[11];
    const float* g2a  = (const float*)d_in[12];
    const float* be2a = (const float*)d_in[13];
    const float* w2b  = (const float*)d_in[14];
    const float* b2b  = (const float*)d_in[15];
    const float* g2b  = (const float*)d_in[16];
    const float* be2b = (const float*)d_in[17];
    const float* gn   = (const float*)d_in[18];
    const float* bn   = (const float*)d_in[19];
    float* out = (float*)d_out;

    const int SM1  = 6*WSZ + 3072 + 4096;          // 216064
    const int SM2A = 6*WSZ + 1536 + 4096;          // 214528
    const int SM2B = 6*WSZ + 2560 + 4096;          // 215552
    cudaFuncSetAttribute(k_fc1,  cudaFuncAttributeMaxDynamicSharedMemorySize, SM1);
    cudaFuncSetAttribute(k_fc2a, cudaFuncAttributeMaxDynamicSharedMemorySize, SM2A);
    cudaFuncSetAttribute(k_fc2b, cudaFuncAttributeMaxDynamicSharedMemorySize, SM2B);

    k_init_lanemax<<<(NLANES * HD + 511) / 512, 512>>>();
    k_fc1 <<<148, 512, SM1>>> (x, lane_ids, w1a, b1a, g1a, be1a, w1b, b1b, g1b, be1b);
    k_fc2a<<<148, 512, SM2A>>>(lane_ids, w2a, b2a, g2a, be2a);
    k_fc2b<<<148, 512, SM2B>>>(x, w2b, b2b, g2b, be2b, gn, bn, out);
}

// round 7
// speedup vs baseline: 1.8037x; 1.1770x over previous
#include <cuda_runtime.h>
#include <cuda_bf16.h>
#include <cstdint>

#define NROWS  300000
#define HD     128
#define NLANES 25000
#define LNEPS  1e-5f
#define TM     128
#define NT     ((NROWS + TM - 1) / TM)     // 2344 tiles
#define NLT    ((NLANES + 127) / 128)      // 196 lane tiles
#define PADU   68                           // u32 per 128-bf16 row (272B, conflict-free)
#define ROWB   272
#define TILEU4 4352                         // uint4 per split tile image (hi+lo)

typedef unsigned int       u32;
typedef unsigned short     u16;
typedef unsigned long long u64;

// ---------------- device scratch ----------------
__device__ uint4 g_h[(size_t)NT * TILEU4];   // fc1 output image (split, padded)
__device__ uint4 g_f[(size_t)NT * TILEU4];   // fc2a output image
__device__ int   g_lanemax[NLANES * HD];     // per-lane max (float bits, relu>=0)
__device__ float g_z[(size_t)NLANES * HD];   // per-lane Z = max @ w2a_bot + b2a

// ---------------- helpers ----------------
static __device__ __forceinline__ u32 smem_u32(const void* p) {
    u32 a;
    asm("{ .reg .u64 t; cvta.to.shared.u64 t, %1; cvt.u32.u64 %0, t; }" : "=r"(a) : "l"(p));
    return a;
}
static __device__ __forceinline__ u16 f2bf(float f) {
    return __bfloat16_as_ushort(__float2bfloat16(f));
}
static __device__ __forceinline__ float bf2f(u16 u) {
    return __uint_as_float(((u32)u) << 16);
}
static __device__ __forceinline__ u32 packsplit_hi(float v0, float v1) {
    return (u32)f2bf(v0) | ((u32)f2bf(v1) << 16);
}
static __device__ __forceinline__ u32 packsplit_lo(float v0, float v1) {
    u16 h0 = f2bf(v0), h1 = f2bf(v1);
    return (u32)f2bf(v0 - bf2f(h0)) | ((u32)f2bf(v1 - bf2f(h1)) << 16);
}

#define CP16(sm_addr, gptr) \
    asm volatile("cp.async.cg.shared.global [%0], [%1], 16;" :: "r"(sm_addr), "l"(gptr))
#define CP_COMMIT() asm volatile("cp.async.commit_group;" ::: "memory")
#define CP_WAIT0()  asm volatile("cp.async.wait_group 0;" ::: "memory")
#define PREF_L2(p)  asm volatile("prefetch.global.L2 [%0];" :: "l"(p))

static __device__ __forceinline__ void ldsm4(u32& r0, u32& r1, u32& r2, u32& r3, u32 addr) {
    asm volatile("ldmatrix.sync.aligned.m8n8.x4.shared.b16 {%0,%1,%2,%3}, [%4];"
        : "=r"(r0), "=r"(r1), "=r"(r2), "=r"(r3) : "r"(addr));
}
static __device__ __forceinline__ void mma16816(float (&d)[4], const u32 (&a)[4], u32 b0, u32 b1) {
    asm volatile("mma.sync.aligned.m16n8k16.row.col.f32.bf16.bf16.f32 "
        "{%0,%1,%2,%3}, {%4,%5,%6,%7}, {%8,%9}, {%0,%1,%2,%3};"
        : "+f"(d[0]), "+f"(d[1]), "+f"(d[2]), "+f"(d[3])
        : "r"(a[0]), "r"(a[1]), "r"(a[2]), "r"(a[3]), "r"(b0), "r"(b1));
}

// Merged split GEMM: acc += Ah*Bh^T + Al*Bh^T + Ah*Bl^T over K=128.
static __device__ __forceinline__ void gemm_merged(
    u32 Ah, u32 Al, u32 Bh, u32 Bl, u32 aoff, u32 boff, float (&acc)[8][4])
{
    #pragma unroll
    for (int kc = 0; kc < 8; ++kc) {
        const u32 ka = kc * 32;
        u32 ah0[4], ah1[4], al0[4], al1[4], bh[8], bl[8];
        ldsm4(ah0[0], ah0[1], ah0[2], ah0[3], Ah + aoff + ka);
        ldsm4(ah1[0], ah1[1], ah1[2], ah1[3], Ah + aoff + 16 * ROWB + ka);
        ldsm4(al0[0], al0[1], al0[2], al0[3], Al + aoff + ka);
        ldsm4(al1[0], al1[1], al1[2], al1[3], Al + aoff + 16 * ROWB + ka);
        ldsm4(bh[0], bh[1], bh[2], bh[3], Bh + boff + ka);
        ldsm4(bh[4], bh[5], bh[6], bh[7], Bh + boff + 16 * ROWB + ka);
        ldsm4(bl[0], bl[1], bl[2], bl[3], Bl + boff + ka);
        ldsm4(bl[4], bl[5], bl[6], bl[7], Bl + boff + 16 * ROWB + ka);
        #pragma unroll
        for (int p = 0; p < 2; ++p)
        #pragma unroll
        for (int j = 0; j < 2; ++j) {
            const int nt = p * 2 + j;
            const u32 b0h = bh[p*4 + j*2], b1h = bh[p*4 + j*2 + 1];
            const u32 b0l = bl[p*4 + j*2], b1l = bl[p*4 + j*2 + 1];
            mma16816(acc[nt],     ah0, b0h, b1h);
            mma16816(acc[4 + nt], ah1, b0h, b1h);
            mma16816(acc[nt],     al0, b0h, b1h);
            mma16816(acc[4 + nt], al1, b0h, b1h);
            mma16816(acc[nt],     ah0, b0l, b1l);
            mma16816(acc[4 + nt], ah1, b0l, b1l);
        }
    }
}

// ---------------- LN epilogue on register fragments ----------------
template<bool HASB, bool RELU>
static __device__ __forceinline__ void ln_tile(
    float (&acc)[8][4], int wrow, int wcol, int lr, int lc, int cw,
    const float* __restrict__ bias, const float* __restrict__ gam,
    const float* __restrict__ bet, float* RS, float* RQ)
{
    float s[4] = {0.f,0.f,0.f,0.f}, q[4] = {0.f,0.f,0.f,0.f};
    #pragma unroll
    for (int rt = 0; rt < 2; ++rt)
    #pragma unroll
    for (int nt = 0; nt < 4; ++nt) {
        float* a = acc[rt * 4 + nt];
        if (HASB) {
            int c = wcol + nt * 8 + lc * 2;
            float bx = bias[c], by = bias[c + 1];
            a[0] += bx; a[1] += by; a[2] += bx; a[3] += by;
        }
        s[rt*2+0] += a[0] + a[1]; q[rt*2+0] += a[0]*a[0] + a[1]*a[1];
        s[rt*2+1] += a[2] + a[3]; q[rt*2+1] += a[2]*a[2] + a[3]*a[3];
    }
    #pragma unroll
    for (int off = 1; off <= 2; off <<= 1)
        #pragma unroll
        for (int i = 0; i < 4; ++i) {
            s[i] += __shfl_xor_sync(0xffffffffu, s[i], off);
            q[i] += __shfl_xor_sync(0xffffffffu, q[i], off);
        }
    if (lc == 0) {
        #pragma unroll
        for (int i = 0; i < 4; ++i) {
            int row = wrow + (i >> 1) * 16 + (i & 1) * 8 + lr;
            RS[cw * 128 + row] = s[i];
            RQ[cw * 128 + row] = q[i];
        }
    }
    __syncthreads();
    float mm[4], rsd[4];
    #pragma unroll
    for (int i = 0; i < 4; ++i) {
        int row = wrow + (i >> 1) * 16 + (i & 1) * 8 + lr;
        float S = RS[row] + RS[128 + row] + RS[256 + row] + RS[384 + row];
        float Q = RQ[row] + RQ[128 + row] + RQ[256 + row] + RQ[384 + row];
        float m = S * (1.f / 128.f);
        mm[i] = m;
        rsd[i] = rsqrtf(Q * (1.f / 128.f) - m * m + LNEPS);
    }
    __syncthreads();
    #pragma unroll
    for (int rt = 0; rt < 2; ++rt)
    #pragma unroll
    for (int nt = 0; nt < 4; ++nt) {
        int c = wcol + nt * 8 + lc * 2;
        float gx = gam[c], gy = gam[c + 1], ex = bet[c], ey = bet[c + 1];
        float* a = acc[rt * 4 + nt];
        int s0 = rt * 2, s1 = rt * 2 + 1;
        a[0] = (a[0] - mm[s0]) * rsd[s0] * gx + ex;
        a[1] = (a[1] - mm[s0]) * rsd[s0] * gy + ey;
        a[2] = (a[2] - mm[s1]) * rsd[s1] * gx + ex;
        a[3] = (a[3] - mm[s1]) * rsd[s1] * gy + ey;
        if (RELU) {
            a[0] = fmaxf(a[0], 0.f); a[1] = fmaxf(a[1], 0.f);
            a[2] = fmaxf(a[2], 0.f); a[3] = fmaxf(a[3], 0.f);
        }
    }
}

static __device__ __forceinline__ void store_acc_split(
    const float (&acc)[8][4], u32* hi, u32* lo, int wrow, int wcol, int lr, int lc)
{
    #pragma unroll
    for (int rt = 0; rt < 2; ++rt)
    #pragma unroll
    for (int hh = 0; hh < 2; ++hh) {
        int row = wrow + rt * 16 + hh * 8 + lr;
        u32 base = row * PADU + (wcol >> 1) + lc;
        #pragma unroll
        for (int nt = 0; nt < 4; ++nt) {
            float v0 = acc[rt*4+nt][hh*2+0], v1 = acc[rt*4+nt][hh*2+1];
            hi[base + nt*4] = packsplit_hi(v0, v1);
            lo[base + nt*4] = packsplit_lo(v0, v1);
        }
    }
}

static __device__ __forceinline__ void store_split4(u32* hi, u32* lo, int row, int col, float4 xv) {
    u32 idx = row * PADU + (col >> 1);
    hi[idx]   = packsplit_hi(xv.x, xv.y);
    hi[idx+1] = packsplit_hi(xv.z, xv.w);
    lo[idx]   = packsplit_lo(xv.x, xv.y);
    lo[idx+1] = packsplit_lo(xv.z, xv.w);
}

static __device__ __forceinline__ void load_wsplit(u32* hi, u32* lo, const float* __restrict__ w,
                                                   int tid, int nth) {
    for (int idx = tid; idx < HD * HD / 2; idx += nth) {
        int o = idx & 127, k2 = idx >> 7;
        float v0 = w[(2*k2)   * HD + o];
        float v1 = w[(2*k2+1) * HD + o];
        u32 off = o * PADU + k2;
        hi[off] = packsplit_hi(v0, v1);
        lo[off] = packsplit_lo(v0, v1);
    }
}

__global__ void k_init_lanemax() {
    int i = blockIdx.x * blockDim.x + threadIdx.x;
    if (i < NLANES * HD) g_lanemax[i] = 0;
}

#define WSZ 34816

static __device__ __forceinline__ u32 mk_aoff(int wrow, int lane) {
    return (u32)((wrow + (lane & 15)) * ROWB + ((lane >> 4) & 1) * 16);
}
static __device__ __forceinline__ u32 mk_boff(int wcol, int lane) {
    return (u32)((wcol + ((lane >> 4) & 1) * 8 + (lane & 7)) * ROWB + ((lane >> 3) & 1) * 16);
}

// ======================== fc1 ========================
__global__ void __launch_bounds__(512, 1) k_fc1(
    const float* __restrict__ x, const int* __restrict__ lane_ids,
    const float* __restrict__ w1a, const float* __restrict__ b1a,
    const float* __restrict__ g1a, const float* __restrict__ be1a,
    const float* __restrict__ w1b, const float* __restrict__ b1b,
    const float* __restrict__ g1b, const float* __restrict__ be1b)
{
    extern __shared__ char sm[];
    u32* WA_HI = (u32*)(sm);            u32* WA_LO = (u32*)(sm + WSZ);
    u32* WB_HI = (u32*)(sm + 2*WSZ);    u32* WB_LO = (u32*)(sm + 3*WSZ);
    u32* A_HI  = (u32*)(sm + 4*WSZ);    u32* A_LO  = (u32*)(sm + 5*WSZ);
    float* P  = (float*)(sm + 6*WSZ);
    float* RS = (float*)(sm + 6*WSZ + 3072);
    float* RQ = (float*)(sm + 6*WSZ + 5120);

    const int tid = threadIdx.x, w = tid >> 5, lane = tid & 31;
    const int lr = lane >> 2, lc = lane & 3;
    const int wrow = (w & 3) * 32, wcol = (w >> 2) * 32, cw = w >> 2;
    const u32 aoff = mk_aoff(wrow, lane), boff = mk_boff(wcol, lane);
    const u32 sAH = smem_u32(A_HI), sAL = smem_u32(A_LO);
    const u32 sWAH = smem_u32(WA_HI), sWAL = smem_u32(WA_LO);
    const u32 sWBH = smem_u32(WB_HI), sWBL = smem_u32(WB_LO);

    load_wsplit(WA_HI, WA_LO, w1a, tid, 512);
    load_wsplit(WB_HI, WB_LO, w1b, tid, 512);
    for (int i = tid; i < HD; i += 512) {
        P[i] = b1a[i]; P[128+i] = g1a[i]; P[256+i] = be1a[i];
        P[384+i] = b1b[i]; P[512+i] = g1b[i]; P[640+i] = be1b[i];
    }
    {
        int grow = blockIdx.x * TM + (tid >> 2);
        if (grow < NROWS) PREF_L2((const char*)x + (size_t)blockIdx.x * TM * HD * 4 + tid * 128);
    }
    __syncthreads();

    for (int t = blockIdx.x; t < NT; t += gridDim.x) {
        int r0 = t * TM;
        #pragma unroll
        for (int j = 0; j < 8; ++j) {
            int idx = tid + j * 512; int xr = idx >> 5; int cg = idx & 31;
            int grow = r0 + xr; if (grow >= NROWS) grow = NROWS - 1;
            float4 xv = __ldg(((const float4*)x) + ((size_t)grow * 32 + cg));
            store_split4(A_HI, A_LO, xr, cg * 4, xv);
        }
        {
            int tn = t + gridDim.x; if (tn >= NT) tn = t;
            int grow = tn * TM + (tid >> 2);
            if (grow < NROWS) PREF_L2((const char*)x + (size_t)tn * TM * HD * 4 + tid * 128);
        }
        __syncthreads();

        float acc[8][4];
        #pragma unroll
        for (int i = 0; i < 8; ++i) { acc[i][0]=acc[i][1]=acc[i][2]=acc[i][3]=0.f; }
        gemm_merged(sAH, sAL, sWAH, sWAL, aoff, boff, acc);
        ln_tile<true, true>(acc, wrow, wcol, lr, lc, cw, P, P+128, P+256, RS, RQ);
        store_acc_split(acc, A_HI, A_LO, wrow, wcol, lr, lc);
        __syncthreads();

        #pragma unroll
        for (int i = 0; i < 8; ++i) { acc[i][0]=acc[i][1]=acc[i][2]=acc[i][3]=0.f; }
        gemm_merged(sAH, sAL, sWBH, sWBL, aoff, boff, acc);
        ln_tile<true, true>(acc, wrow, wcol, lr, lc, cw, P+384, P+512, P+640, RS, RQ);

        // scatter-max (predicated: relu zeros are no-ops vs init 0)
        #pragma unroll
        for (int rt = 0; rt < 2; ++rt)
        #pragma unroll
        for (int hh = 0; hh < 2; ++hh) {
            int row = wrow + rt*16 + hh*8 + lr;
            int grow = r0 + row; if (grow >= NROWS) grow = NROWS - 1;
            int ln = __ldg(lane_ids + grow);
            int* bp = g_lanemax + ln * HD;
            #pragma unroll
            for (int nt = 0; nt < 4; ++nt) {
                int c = wcol + nt*8 + lc*2;
                float v0 = acc[rt*4+nt][hh*2+0], v1 = acc[rt*4+nt][hh*2+1];
                if (v0 > 0.f) atomicMax(bp + c,     __float_as_int(v0));
                if (v1 > 0.f) atomicMax(bp + c + 1, __float_as_int(v1));
            }
        }
        store_acc_split(acc, A_HI, A_LO, wrow, wcol, lr, lc);
        __syncthreads();

        const uint4* s4 = (const uint4*)A_HI;
        uint4* d4 = g_h + (size_t)t * TILEU4;
        for (int i = tid; i < TILEU4; i += 512) d4[i] = s4[i];
        __syncthreads();
    }
}

// ======================== k_lanegemm: Z = lane_max @ w2a_bot + b2a ========================
__global__ void __launch_bounds__(512, 1) k_lanegemm(
    const float* __restrict__ w2a_bot, const float* __restrict__ b2a)
{
    extern __shared__ char sm[];
    u32* W_HI = (u32*)(sm);            u32* W_LO = (u32*)(sm + WSZ);
    u32* A_HI = (u32*)(sm + 2*WSZ);    u32* A_LO = (u32*)(sm + 3*WSZ);
    float* P  = (float*)(sm + 4*WSZ);   // b2a

    const int tid = threadIdx.x, w = tid >> 5, lane = tid & 31;
    const int lr = lane >> 2, lc = lane & 3;
    const int wrow = (w & 3) * 32, wcol = (w >> 2) * 32;
    const u32 aoff = mk_aoff(wrow, lane), boff = mk_boff(wcol, lane);
    const u32 sAH = smem_u32(A_HI), sAL = smem_u32(A_LO);
    const u32 sWH = smem_u32(W_HI), sWL = smem_u32(W_LO);

    load_wsplit(W_HI, W_LO, w2a_bot, tid, 512);
    for (int i = tid; i < HD; i += 512) P[i] = b2a[i];
    __syncthreads();

    for (int t = blockIdx.x; t < NLT; t += gridDim.x) {
        int l0 = t * 128;
        #pragma unroll
        for (int j = 0; j < 8; ++j) {
            int idx = tid + j * 512; int xr = idx >> 5; int cg = idx & 31;
            int l = l0 + xr; if (l >= NLANES) l = NLANES - 1;
            int4 gv = __ldg(((const int4*)(g_lanemax)) + ((size_t)l * 32 + cg));
            store_split4(A_HI, A_LO, xr, cg * 4,
                make_float4(__int_as_float(gv.x), __int_as_float(gv.y),
                            __int_as_float(gv.z), __int_as_float(gv.w)));
        }
        __syncthreads();

        float acc[8][4];
        #pragma unroll
        for (int i = 0; i < 8; ++i) { acc[i][0]=acc[i][1]=acc[i][2]=acc[i][3]=0.f; }
        gemm_merged(sAH, sAL, sWH, sWL, aoff, boff, acc);

        #pragma unroll
        for (int rt = 0; rt < 2; ++rt)
        #pragma unroll
        for (int hh = 0; hh < 2; ++hh) {
            int row = wrow + rt*16 + hh*8 + lr;
            int l = l0 + row;
            if (l < NLANES) {
                #pragma unroll
                for (int nt = 0; nt < 4; ++nt) {
                    int c = wcol + nt*8 + lc*2;
                    *(float2*)(g_z + (size_t)l * HD + c) =
                        make_float2(acc[rt*4+nt][hh*2+0] + P[c],
                                    acc[rt*4+nt][hh*2+1] + P[c+1]);
                }
            }
        }
        __syncthreads();
    }
}

// ======================== fc2a: h @ w2a_top + Z[lane] -> LN -> ReLU -> g_f ========================
__global__ void __launch_bounds__(512, 1) k_fc2a(
    const int* __restrict__ lane_ids,
    const float* __restrict__ w2a_top,
    const float* __restrict__ g2a, const float* __restrict__ be2a)
{
    extern __shared__ char sm[];
    u32* W_HI = (u32*)(sm);            u32* W_LO = (u32*)(sm + WSZ);
    // A buffers: buf0 = sm+2WSZ (hi) / sm+3WSZ (lo), buf1 = sm+4WSZ / sm+5WSZ
    float* P  = (float*)(sm + 6*WSZ);                   // gam, bet
    float* RS = (float*)(sm + 6*WSZ + 1024);
    float* RQ = (float*)(sm + 6*WSZ + 1024 + 2048);

    const int tid = threadIdx.x, w = tid >> 5, lane = tid & 31;
    const int lr = lane >> 2, lc = lane & 3;
    const int wrow = (w & 3) * 32, wcol = (w >> 2) * 32, cw = w >> 2;
    const u32 aoff = mk_aoff(wrow, lane), boff = mk_boff(wcol, lane);
    const u32 sWH = smem_u32(W_HI), sWL = smem_u32(W_LO);
    const u32 sA0 = smem_u32(sm + 2*WSZ), sA1 = smem_u32(sm + 4*WSZ);

    load_wsplit(W_HI, W_LO, w2a_top, tid, 512);
    for (int i = tid; i < HD; i += 512) { P[i] = g2a[i]; P[128+i] = be2a[i]; }

    // prologue: issue first tile image
    {
        const uint4* s4 = g_h + (size_t)blockIdx.x * TILEU4;
        #pragma unroll
        for (int j = 0; j < 9; ++j) {
            int i = tid + j * 512;
            if (i < TILEU4) CP16(sA0 + (u32)i * 16, s4 + i);
        }
        CP_COMMIT();
    }
    __syncthreads();

    int buf = 0;
    for (int t = blockIdx.x; t < NT; t += gridDim.x, buf ^= 1) {
        int r0 = t * TM;
        const u32 sA  = buf ? sA1 : sA0;
        const u32 sAn = buf ? sA0 : sA1;

        CP_WAIT0();
        __syncthreads();

        // issue next tile image (overlaps GEMM)
        int tn = t + gridDim.x; if (tn >= NT) tn = t;
        {
            const uint4* s4 = g_h + (size_t)tn * TILEU4;
            #pragma unroll
            for (int j = 0; j < 9; ++j) {
                int i = tid + j * 512;
                if (i < TILEU4) CP16(sAn + (u32)i * 16, s4 + i);
            }
            CP_COMMIT();
        }
        // prefetch this tile's Z rows into L2
        {
            int grow = r0 + (tid >> 2); if (grow >= NROWS) grow = NROWS - 1;
            int lnid = __ldg(lane_ids + grow);
            PREF_L2(g_z + (size_t)lnid * HD + (tid & 3) * 32);
        }

        float acc[8][4];
        #pragma unroll
        for (int i = 0; i < 8; ++i) { acc[i][0]=acc[i][1]=acc[i][2]=acc[i][3]=0.f; }
        gemm_merged(sA, sA + WSZ, sWH, sWL, aoff, boff, acc);

        // add Z[lane] (fp32, bias folded in)
        #pragma unroll
        for (int rt = 0; rt < 2; ++rt)
        #pragma unroll
        for (int hh = 0; hh < 2; ++hh) {
            int row = wrow + rt*16 + hh*8 + lr;
            int grow = r0 + row; if (grow >= NROWS) grow = NROWS - 1;
            int lnid = __ldg(lane_ids + grow);
            const float* zr = g_z + (size_t)lnid * HD;
            #pragma unroll
            for (int nt = 0; nt < 4; ++nt) {
                int c = wcol + nt*8 + lc*2;
                float2 zv = __ldg((const float2*)(zr + c));
                acc[rt*4+nt][hh*2+0] += zv.x;
                acc[rt*4+nt][hh*2+1] += zv.y;
            }
        }
        ln_tile<false, true>(acc, wrow, wcol, lr, lc, cw, P, P, P+128, RS, RQ);

        // store normalized result into the CURRENT buffer (just consumed)
        {
            u32* hi = (u32*)(sm + (buf ? 4*WSZ : 2*WSZ));
            u32* lo = (u32*)(sm + (buf ? 5*WSZ : 3*WSZ));
            store_acc_split(acc, hi, lo, wrow, wcol, lr, lc);
        }
        __syncthreads();

        // write f image out
        const uint4* s4o = (const uint4*)(sm + (buf ? 4*WSZ : 2*WSZ));
        uint4* d4 = g_f + (size_t)t * TILEU4;
        for (int i = tid; i < TILEU4; i += 512) d4[i] = s4o[i];
        __syncthreads();
    }
}

// ======================== fc2b (double-buffered pipeline) ========================
__global__ void __launch_bounds__(512, 1) k_fc2b(
    const float* __restrict__ x,
    const float* __restrict__ w2b, const float* __restrict__ b2b,
    const float* __restrict__ g2b, const float* __restrict__ be2b,
    const float* __restrict__ gn, const float* __restrict__ bn,
    float* __restrict__ out)
{
    extern __shared__ char sm[];
    u32* W_HI = (u32*)(sm);            u32* W_LO = (u32*)(sm + WSZ);
    float* P  = (float*)(sm + 6*WSZ);
    float* RS = (float*)(sm + 6*WSZ + 2560);
    float* RQ = (float*)(sm + 6*WSZ + 2560 + 2048);

    const int tid = threadIdx.x, w = tid >> 5, lane = tid & 31;
    const int lr = lane >> 2, lc = lane & 3;
    const int wrow = (w & 3) * 32, wcol = (w >> 2) * 32, cw = w >> 2;
    const u32 aoff = mk_aoff(wrow, lane), boff = mk_boff(wcol, lane);
    const u32 sWH = smem_u32(W_HI), sWL = smem_u32(W_LO);
    const u32 sA0 = smem_u32(sm + 2*WSZ), sA1 = smem_u32(sm + 4*WSZ);

    load_wsplit(W_HI, W_LO, w2b, tid, 512);
    for (int i = tid; i < HD; i += 512) {
        P[i] = b2b[i]; P[128+i] = g2b[i]; P[256+i] = be2b[i]; P[384+i] = gn[i]; P[512+i] = bn[i];
    }
    {
        const uint4* s4 = g_f + (size_t)blockIdx.x * TILEU4;
        #pragma unroll
        for (int j = 0; j < 9; ++j) {
            int i = tid + j * 512;
            if (i < TILEU4) CP16(sA0 + (u32)i * 16, s4 + i);
        }
        CP_COMMIT();
        int grow = blockIdx.x * TM + (tid >> 2);
        if (grow < NROWS) PREF_L2((const char*)x + (size_t)blockIdx.x * TM * HD * 4 + tid * 128);
    }
    __syncthreads();

    int buf = 0;
    for (int t = blockIdx.x; t < NT; t += gridDim.x, buf ^= 1) {
        int r0 = t * TM;
        const u32 sA  = buf ? sA1 : sA0;
        const u32 sAn = buf ? sA0 : sA1;

        CP_WAIT0();
        __syncthreads();

        int tn = t + gridDim.x; if (tn >= NT) tn = t;
        {
            const uint4* s4 = g_f + (size_t)tn * TILEU4;
            #pragma unroll
            for (int j = 0; j < 9; ++j) {
                int i = tid + j * 512;
                if (i < TILEU4) CP16(sAn + (u32)i * 16, s4 + i);
            }
            CP_COMMIT();
            int grow = tn * TM + (tid >> 2);
            if (grow < NROWS) PREF_L2((const char*)x + (size_t)tn * TM * HD * 4 + tid * 128);
        }

        float acc[8][4];
        #pragma unroll
        for (int i = 0; i < 8; ++i) { acc[i][0]=acc[i][1]=acc[i][2]=acc[i][3]=0.f; }
        gemm_merged(sA, sA + WSZ, sWH, sWL, aoff, boff, acc);
        ln_tile<true, true>(acc, wrow, wcol, lr, lc, cw, P, P+128, P+256, RS, RQ);

        #pragma unroll
        for (int rt = 0; rt < 2; ++rt)
        #pragma unroll
        for (int hh = 0; hh < 2; ++hh) {
            int row = wrow + rt*16 + hh*8 + lr;
            int grow = r0 + row; if (grow >= NROWS) grow = NROWS - 1;
            #pragma unroll
            for (int nt = 0; nt < 4; ++nt) {
                int c = wcol + nt*8 + lc*2;
                float2 xv = __ldg((const float2*)(x + (size_t)grow * HD + c));
                acc[rt*4+nt][hh*2+0] += xv.x;
                acc[rt*4+nt][hh*2+1] += xv.y;
            }
        }
        ln_tile<false, false>(acc, wrow, wcol, lr, lc, cw, P, P+384, P+512, RS, RQ);

        #pragma unroll
        for (int rt = 0; rt < 2; ++rt)
        #pragma unroll
        for (int hh = 0; hh < 2; ++hh) {
            int row = wrow + rt*16 + hh*8 + lr;
            int grow = r0 + row;
            if (grow < NROWS) {
                #pragma unroll
                for (int nt = 0; nt < 4; ++nt) {
                    int c = wcol + nt*8 + lc*2;
                    *(float2*)(out + (size_t)grow * HD + c) =
                        make_float2(acc[rt*4+nt][hh*2+0], acc[rt*4+nt][hh*2+1]);
                }
            }
        }
        __syncthreads();
    }
}

// ---------------- launcher ----------------
extern "C" void kernel_launch(void* const* d_in, const int* in_sizes, int n_in,
                              void* d_out, int out_size) {
    (void)in_sizes; (void)n_in; (void)out_size;
    const float* x        = (const float*)d_in[0];
    const int*   lane_ids = (const int*)  d_in[1];
    const float* w1a  = (const float*)d_in[2];
    const float* b1a  = (const float*)d_in[3];
    const float* g1a  = (const float*)d_in[4];
    const float* be1a = (const float*)d_in[5];
    const float* w1b  = (const float*)d_in[6];
    const float* b1b  = (const float*)d_in[7];
    const float* g1b  = (const float*)d_in[8];
    const float* be1b = (const float*)d_in[9];
    const float* w2a  = (const float*)d_in[10];
    const float* b2a  = (const float*)d_in[11];
    const float* g2a  = (const float*)d_in[12];
    const float* be2a = (const float*)d_in[13];
    const float* w2b  = (const float*)d_in[14];
    const float* b2b  = (const float*)d_in[15];
    const float* g2b  = (const float*)d_in[16];
    const float* be2b = (const float*)d_in[17];
    const float* gn   = (const float*)d_in[18];
    const float* bn   = (const float*)d_in[19];
    float* out = (float*)d_out;

    const int SM1  = 6*WSZ + 3072 + 4096;          // fc1
    const int SMLG = 4*WSZ + 1024;                 // lanegemm
    const int SM2A = 6*WSZ + 1024 + 4096;          // fc2a
    const int SM2B = 6*WSZ + 2560 + 4096;          // fc2b
    cudaFuncSetAttribute(k_fc1,      cudaFuncAttributeMaxDynamicSharedMemorySize, SM1);
    cudaFuncSetAttribute(k_lanegemm, cudaFuncAttributeMaxDynamicSharedMemorySize, SMLG);
    cudaFuncSetAttribute(k_fc2a,     cudaFuncAttributeMaxDynamicSharedMemorySize, SM2A);
    cudaFuncSetAttribute(k_fc2b,     cudaFuncAttributeMaxDynamicSharedMemorySize, SM2B);

    k_init_lanemax<<<(NLANES * HD + 511) / 512, 512>>>();
    k_fc1     <<<148, 512, SM1>>> (x, lane_ids, w1a, b1a, g1a, be1a, w1b, b1b, g1b, be1b);
    k_lanegemm<<<148, 512, SMLG>>>(w2a + 128 * HD, b2a);
    k_fc2a    <<<148, 512, SM2A>>>(lane_ids, w2a, g2a, be2a);
    k_fc2b    <<<148, 512, SM2B>>>(x, w2b, b2b, g2b, be2b, gn, bn, out);
}

// round 8
// speedup vs baseline: 1.8432x; 1.0219x over previous
#include <cuda_runtime.h>
#include <cuda_bf16.h>
#include <cstdint>

#define NROWS  300000
#define HD     128
#define NLANES 25000
#define LNEPS  1e-5f
#define TM     128
#define NT     ((NROWS + TM - 1) / TM)     // 2344 tiles
#define NLT    ((NLANES + 127) / 128)      // 196 lane tiles
#define PADU   68                           // u32 per 128-bf16 row (272B, conflict-free)
#define ROWB   272
#define TILEU4 4352                         // uint4 per split tile image (hi+lo)

typedef unsigned int       u32;
typedef unsigned short     u16;
typedef unsigned long long u64;

// ---------------- device scratch ----------------
__device__ uint4 g_h[(size_t)NT * TILEU4];   // fc1 output image (split, padded)
__device__ int   g_lanemax[NLANES * HD];     // per-lane max (float bits, relu>=0)
__device__ float g_z[(size_t)NLANES * HD];   // per-lane Z = max @ w2a_bot + b2a

// ---------------- helpers ----------------
static __device__ __forceinline__ u32 smem_u32(const void* p) {
    u32 a;
    asm("{ .reg .u64 t; cvta.to.shared.u64 t, %1; cvt.u32.u64 %0, t; }" : "=r"(a) : "l"(p));
    return a;
}
static __device__ __forceinline__ u16 f2bf(float f) {
    return __bfloat16_as_ushort(__float2bfloat16(f));
}
static __device__ __forceinline__ float bf2f(u16 u) {
    return __uint_as_float(((u32)u) << 16);
}
static __device__ __forceinline__ u32 packsplit_hi(float v0, float v1) {
    return (u32)f2bf(v0) | ((u32)f2bf(v1) << 16);
}
static __device__ __forceinline__ u32 packsplit_lo(float v0, float v1) {
    u16 h0 = f2bf(v0), h1 = f2bf(v1);
    return (u32)f2bf(v0 - bf2f(h0)) | ((u32)f2bf(v1 - bf2f(h1)) << 16);
}

#define CP16(sm_addr, gptr) \
    asm volatile("cp.async.cg.shared.global [%0], [%1], 16;" :: "r"(sm_addr), "l"(gptr))
#define CP_COMMIT() asm volatile("cp.async.commit_group;" ::: "memory")
#define CP_WAIT0()  asm volatile("cp.async.wait_group 0;" ::: "memory")
#define PREF_L2(p)  asm volatile("prefetch.global.L2 [%0];" :: "l"(p))

static __device__ __forceinline__ void ldsm4(u32& r0, u32& r1, u32& r2, u32& r3, u32 addr) {
    asm volatile("ldmatrix.sync.aligned.m8n8.x4.shared.b16 {%0,%1,%2,%3}, [%4];"
        : "=r"(r0), "=r"(r1), "=r"(r2), "=r"(r3) : "r"(addr));
}
static __device__ __forceinline__ void mma16816(float (&d)[4], const u32 (&a)[4], u32 b0, u32 b1) {
    asm volatile("mma.sync.aligned.m16n8k16.row.col.f32.bf16.bf16.f32 "
        "{%0,%1,%2,%3}, {%4,%5,%6,%7}, {%8,%9}, {%0,%1,%2,%3};"
        : "+f"(d[0]), "+f"(d[1]), "+f"(d[2]), "+f"(d[3])
        : "r"(a[0]), "r"(a[1]), "r"(a[2]), "r"(a[3]), "r"(b0), "r"(b1));
}

// Merged split GEMM: acc += Ah*Bh^T + Al*Bh^T + Ah*Bl^T over K=128.
static __device__ __forceinline__ void gemm_merged(
    u32 Ah, u32 Al, u32 Bh, u32 Bl, u32 aoff, u32 boff, float (&acc)[8][4])
{
    #pragma unroll
    for (int kc = 0; kc < 8; ++kc) {
        const u32 ka = kc * 32;
        u32 ah0[4], ah1[4], al0[4], al1[4], bh[8], bl[8];
        ldsm4(ah0[0], ah0[1], ah0[2], ah0[3], Ah + aoff + ka);
        ldsm4(ah1[0], ah1[1], ah1[2], ah1[3], Ah + aoff + 16 * ROWB + ka);
        ldsm4(al0[0], al0[1], al0[2], al0[3], Al + aoff + ka);
        ldsm4(al1[0], al1[1], al1[2], al1[3], Al + aoff + 16 * ROWB + ka);
        ldsm4(bh[0], bh[1], bh[2], bh[3], Bh + boff + ka);
        ldsm4(bh[4], bh[5], bh[6], bh[7], Bh + boff + 16 * ROWB + ka);
        ldsm4(bl[0], bl[1], bl[2], bl[3], Bl + boff + ka);
        ldsm4(bl[4], bl[5], bl[6], bl[7], Bl + boff + 16 * ROWB + ka);
        #pragma unroll
        for (int p = 0; p < 2; ++p)
        #pragma unroll
        for (int j = 0; j < 2; ++j) {
            const int nt = p * 2 + j;
            const u32 b0h = bh[p*4 + j*2], b1h = bh[p*4 + j*2 + 1];
            const u32 b0l = bl[p*4 + j*2], b1l = bl[p*4 + j*2 + 1];
            mma16816(acc[nt],     ah0, b0h, b1h);
            mma16816(acc[4 + nt], ah1, b0h, b1h);
            mma16816(acc[nt],     al0, b0h, b1h);
            mma16816(acc[4 + nt], al1, b0h, b1h);
            mma16816(acc[nt],     ah0, b0l, b1l);
            mma16816(acc[4 + nt], ah1, b0l, b1l);
        }
    }
}

// ---------------- LN epilogue on register fragments ----------------
template<bool HASB, bool RELU>
static __device__ __forceinline__ void ln_tile(
    float (&acc)[8][4], int wrow, int wcol, int lr, int lc, int cw,
    const float* __restrict__ bias, const float* __restrict__ gam,
    const float* __restrict__ bet, float* RS, float* RQ)
{
    float s[4] = {0.f,0.f,0.f,0.f}, q[4] = {0.f,0.f,0.f,0.f};
    #pragma unroll
    for (int rt = 0; rt < 2; ++rt)
    #pragma unroll
    for (int nt = 0; nt < 4; ++nt) {
        float* a = acc[rt * 4 + nt];
        if (HASB) {
            int c = wcol + nt * 8 + lc * 2;
            float bx = bias[c], by = bias[c + 1];
            a[0] += bx; a[1] += by; a[2] += bx; a[3] += by;
        }
        s[rt*2+0] += a[0] + a[1]; q[rt*2+0] += a[0]*a[0] + a[1]*a[1];
        s[rt*2+1] += a[2] + a[3]; q[rt*2+1] += a[2]*a[2] + a[3]*a[3];
    }
    #pragma unroll
    for (int off = 1; off <= 2; off <<= 1)
        #pragma unroll
        for (int i = 0; i < 4; ++i) {
            s[i] += __shfl_xor_sync(0xffffffffu, s[i], off);
            q[i] += __shfl_xor_sync(0xffffffffu, q[i], off);
        }
    if (lc == 0) {
        #pragma unroll
        for (int i = 0; i < 4; ++i) {
            int row = wrow + (i >> 1) * 16 + (i & 1) * 8 + lr;
            RS[cw * 128 + row] = s[i];
            RQ[cw * 128 + row] = q[i];
        }
    }
    __syncthreads();
    float mm[4], rsd[4];
    #pragma unroll
    for (int i = 0; i < 4; ++i) {
        int row = wrow + (i >> 1) * 16 + (i & 1) * 8 + lr;
        float S = RS[row] + RS[128 + row] + RS[256 + row] + RS[384 + row];
        float Q = RQ[row] + RQ[128 + row] + RQ[256 + row] + RQ[384 + row];
        float m = S * (1.f / 128.f);
        mm[i] = m;
        rsd[i] = rsqrtf(Q * (1.f / 128.f) - m * m + LNEPS);
    }
    __syncthreads();
    #pragma unroll
    for (int rt = 0; rt < 2; ++rt)
    #pragma unroll
    for (int nt = 0; nt < 4; ++nt) {
        int c = wcol + nt * 8 + lc * 2;
        float gx = gam[c], gy = gam[c + 1], ex = bet[c], ey = bet[c + 1];
        float* a = acc[rt * 4 + nt];
        int s0 = rt * 2, s1 = rt * 2 + 1;
        a[0] = (a[0] - mm[s0]) * rsd[s0] * gx + ex;
        a[1] = (a[1] - mm[s0]) * rsd[s0] * gy + ey;
        a[2] = (a[2] - mm[s1]) * rsd[s1] * gx + ex;
        a[3] = (a[3] - mm[s1]) * rsd[s1] * gy + ey;
        if (RELU) {
            a[0] = fmaxf(a[0], 0.f); a[1] = fmaxf(a[1], 0.f);
            a[2] = fmaxf(a[2], 0.f); a[3] = fmaxf(a[3], 0.f);
        }
    }
}

static __device__ __forceinline__ void store_acc_split(
    const float (&acc)[8][4], u32* hi, u32* lo, int wrow, int wcol, int lr, int lc)
{
    #pragma unroll
    for (int rt = 0; rt < 2; ++rt)
    #pragma unroll
    for (int hh = 0; hh < 2; ++hh) {
        int row = wrow + rt * 16 + hh * 8 + lr;
        u32 base = row * PADU + (wcol >> 1) + lc;
        #pragma unroll
        for (int nt = 0; nt < 4; ++nt) {
            float v0 = acc[rt*4+nt][hh*2+0], v1 = acc[rt*4+nt][hh*2+1];
            hi[base + nt*4] = packsplit_hi(v0, v1);
            lo[base + nt*4] = packsplit_lo(v0, v1);
        }
    }
}

static __device__ __forceinline__ void store_split4(u32* hi, u32* lo, int row, int col, float4 xv) {
    u32 idx = row * PADU + (col >> 1);
    hi[idx]   = packsplit_hi(xv.x, xv.y);
    hi[idx+1] = packsplit_hi(xv.z, xv.w);
    lo[idx]   = packsplit_lo(xv.x, xv.y);
    lo[idx+1] = packsplit_lo(xv.z, xv.w);
}

static __device__ __forceinline__ void load_wsplit(u32* hi, u32* lo, const float* __restrict__ w,
                                                   int tid, int nth) {
    for (int idx = tid; idx < HD * HD / 2; idx += nth) {
        int o = idx & 127, k2 = idx >> 7;
        float v0 = w[(2*k2)   * HD + o];
        float v1 = w[(2*k2+1) * HD + o];
        u32 off = o * PADU + k2;
        hi[off] = packsplit_hi(v0, v1);
        lo[off] = packsplit_lo(v0, v1);
    }
}

__global__ void k_init_lanemax() {
    int i = blockIdx.x * blockDim.x + threadIdx.x;
    if (i < NLANES * HD) g_lanemax[i] = 0;
}

#define WSZ 34816

static __device__ __forceinline__ u32 mk_aoff(int wrow, int lane) {
    return (u32)((wrow + (lane & 15)) * ROWB + ((lane >> 4) & 1) * 16);
}
static __device__ __forceinline__ u32 mk_boff(int wcol, int lane) {
    return (u32)((wcol + ((lane >> 4) & 1) * 8 + (lane & 7)) * ROWB + ((lane >> 3) & 1) * 16);
}

// ======================== fc1 ========================
__global__ void __launch_bounds__(512, 1) k_fc1(
    const float* __restrict__ x, const int* __restrict__ lane_ids,
    const float* __restrict__ w1a, const float* __restrict__ b1a,
    const float* __restrict__ g1a, const float* __restrict__ be1a,
    const float* __restrict__ w1b, const float* __restrict__ b1b,
    const float* __restrict__ g1b, const float* __restrict__ be1b)
{
    extern __shared__ char sm[];
    u32* WA_HI = (u32*)(sm);            u32* WA_LO = (u32*)(sm + WSZ);
    u32* WB_HI = (u32*)(sm + 2*WSZ);    u32* WB_LO = (u32*)(sm + 3*WSZ);
    u32* A_HI  = (u32*)(sm + 4*WSZ);    u32* A_LO  = (u32*)(sm + 5*WSZ);
    float* P  = (float*)(sm + 6*WSZ);
    float* RS = (float*)(sm + 6*WSZ + 3072);
    float* RQ = (float*)(sm + 6*WSZ + 5120);

    const int tid = threadIdx.x, w = tid >> 5, lane = tid & 31;
    const int lr = lane >> 2, lc = lane & 3;
    const int wrow = (w & 3) * 32, wcol = (w >> 2) * 32, cw = w >> 2;
    const u32 aoff = mk_aoff(wrow, lane), boff = mk_boff(wcol, lane);
    const u32 sAH = smem_u32(A_HI), sAL = smem_u32(A_LO);
    const u32 sWAH = smem_u32(WA_HI), sWAL = smem_u32(WA_LO);
    const u32 sWBH = smem_u32(WB_HI), sWBL = smem_u32(WB_LO);

    load_wsplit(WA_HI, WA_LO, w1a, tid, 512);
    load_wsplit(WB_HI, WB_LO, w1b, tid, 512);
    for (int i = tid; i < HD; i += 512) {
        P[i] = b1a[i]; P[128+i] = g1a[i]; P[256+i] = be1a[i];
        P[384+i] = b1b[i]; P[512+i] = g1b[i]; P[640+i] = be1b[i];
    }
    {
        int grow = blockIdx.x * TM + (tid >> 2);
        if (grow < NROWS) PREF_L2((const char*)x + (size_t)blockIdx.x * TM * HD * 4 + tid * 128);
    }
    __syncthreads();

    for (int t = blockIdx.x; t < NT; t += gridDim.x) {
        int r0 = t * TM;
        #pragma unroll
        for (int j = 0; j < 8; ++j) {
            int idx = tid + j * 512; int xr = idx >> 5; int cg = idx & 31;
            int grow = r0 + xr; if (grow >= NROWS) grow = NROWS - 1;
            float4 xv = __ldg(((const float4*)x) + ((size_t)grow * 32 + cg));
            store_split4(A_HI, A_LO, xr, cg * 4, xv);
        }
        {
            int tn = t + gridDim.x; if (tn >= NT) tn = t;
            int grow = tn * TM + (tid >> 2);
            if (grow < NROWS) PREF_L2((const char*)x + (size_t)tn * TM * HD * 4 + tid * 128);
        }
        __syncthreads();

        float acc[8][4];
        #pragma unroll
        for (int i = 0; i < 8; ++i) { acc[i][0]=acc[i][1]=acc[i][2]=acc[i][3]=0.f; }
        gemm_merged(sAH, sAL, sWAH, sWAL, aoff, boff, acc);
        ln_tile<true, true>(acc, wrow, wcol, lr, lc, cw, P, P+128, P+256, RS, RQ);
        store_acc_split(acc, A_HI, A_LO, wrow, wcol, lr, lc);
        __syncthreads();

        #pragma unroll
        for (int i = 0; i < 8; ++i) { acc[i][0]=acc[i][1]=acc[i][2]=acc[i][3]=0.f; }
        gemm_merged(sAH, sAL, sWBH, sWBL, aoff, boff, acc);
        ln_tile<true, true>(acc, wrow, wcol, lr, lc, cw, P+384, P+512, P+640, RS, RQ);

        // scatter-max (predicated: relu zeros are no-ops vs init 0)
        #pragma unroll
        for (int rt = 0; rt < 2; ++rt)
        #pragma unroll
        for (int hh = 0; hh < 2; ++hh) {
            int row = wrow + rt*16 + hh*8 + lr;
            int grow = r0 + row; if (grow >= NROWS) grow = NROWS - 1;
            int ln = __ldg(lane_ids + grow);
            int* bp = g_lanemax + ln * HD;
            #pragma unroll
            for (int nt = 0; nt < 4; ++nt) {
                int c = wcol + nt*8 + lc*2;
                float v0 = acc[rt*4+nt][hh*2+0], v1 = acc[rt*4+nt][hh*2+1];
                if (v0 > 0.f) atomicMax(bp + c,     __float_as_int(v0));
                if (v1 > 0.f) atomicMax(bp + c + 1, __float_as_int(v1));
            }
        }
        store_acc_split(acc, A_HI, A_LO, wrow, wcol, lr, lc);
        __syncthreads();

        const uint4* s4 = (const uint4*)A_HI;
        uint4* d4 = g_h + (size_t)t * TILEU4;
        for (int i = tid; i < TILEU4; i += 512) d4[i] = s4[i];
        __syncthreads();
    }
}

// ======================== k_lanegemm: Z = lane_max @ w2a_bot + b2a ========================
__global__ void __launch_bounds__(512, 1) k_lanegemm(
    const float* __restrict__ w2a_bot, const float* __restrict__ b2a)
{
    extern __shared__ char sm[];
    u32* W_HI = (u32*)(sm);            u32* W_LO = (u32*)(sm + WSZ);
    u32* A_HI = (u32*)(sm + 2*WSZ);    u32* A_LO = (u32*)(sm + 3*WSZ);
    float* P  = (float*)(sm + 4*WSZ);   // b2a

    const int tid = threadIdx.x, w = tid >> 5, lane = tid & 31;
    const int lr = lane >> 2, lc = lane & 3;
    const int wrow = (w & 3) * 32, wcol = (w >> 2) * 32;
    const u32 aoff = mk_aoff(wrow, lane), boff = mk_boff(wcol, lane);
    const u32 sAH = smem_u32(A_HI), sAL = smem_u32(A_LO);
    const u32 sWH = smem_u32(W_HI), sWL = smem_u32(W_LO);

    load_wsplit(W_HI, W_LO, w2a_bot, tid, 512);
    for (int i = tid; i < HD; i += 512) P[i] = b2a[i];
    __syncthreads();

    for (int t = blockIdx.x; t < NLT; t += gridDim.x) {
        int l0 = t * 128;
        #pragma unroll
        for (int j = 0; j < 8; ++j) {
            int idx = tid + j * 512; int xr = idx >> 5; int cg = idx & 31;
            int l = l0 + xr; if (l >= NLANES) l = NLANES - 1;
            int4 gv = __ldg(((const int4*)(g_lanemax)) + ((size_t)l * 32 + cg));
            store_split4(A_HI, A_LO, xr, cg * 4,
                make_float4(__int_as_float(gv.x), __int_as_float(gv.y),
                            __int_as_float(gv.z), __int_as_float(gv.w)));
        }
        __syncthreads();

        float acc[8][4];
        #pragma unroll
        for (int i = 0; i < 8; ++i) { acc[i][0]=acc[i][1]=acc[i][2]=acc[i][3]=0.f; }
        gemm_merged(sAH, sAL, sWH, sWL, aoff, boff, acc);

        #pragma unroll
        for (int rt = 0; rt < 2; ++rt)
        #pragma unroll
        for (int hh = 0; hh < 2; ++hh) {
            int row = wrow + rt*16 + hh*8 + lr;
            int l = l0 + row;
            if (l < NLANES) {
                #pragma unroll
                for (int nt = 0; nt < 4; ++nt) {
                    int c = wcol + nt*8 + lc*2;
                    *(float2*)(g_z + (size_t)l * HD + c) =
                        make_float2(acc[rt*4+nt][hh*2+0] + P[c],
                                    acc[rt*4+nt][hh*2+1] + P[c+1]);
                }
            }
        }
        __syncthreads();
    }
}

// ======================== fused fc2: h@w2a_top + Z[lane] -> LN -> ReLU -> @w2b -> LN -> ReLU
//                           -> +x -> final LN -> out  (f never touches gmem) ========================
// smem: W2A_HI 0 | W2A_LO WSZ | W2B_HI 2WSZ | W2B_LO 3WSZ | A_HI 4WSZ | A_LO 5WSZ
//       P 6WSZ (7*128 floats) | RS +3584 | RQ +5632
__global__ void __launch_bounds__(512, 1) k_fc2(
    const float* __restrict__ x, const int* __restrict__ lane_ids,
    const float* __restrict__ w2a_top,
    const float* __restrict__ g2a, const float* __restrict__ be2a,
    const float* __restrict__ w2b, const float* __restrict__ b2b,
    const float* __restrict__ g2b, const float* __restrict__ be2b,
    const float* __restrict__ gn, const float* __restrict__ bn,
    float* __restrict__ out)
{
    extern __shared__ char sm[];
    u32* WA_HI = (u32*)(sm);            u32* WA_LO = (u32*)(sm + WSZ);
    u32* WB_HI = (u32*)(sm + 2*WSZ);    u32* WB_LO = (u32*)(sm + 3*WSZ);
    u32* A_HI  = (u32*)(sm + 4*WSZ);    u32* A_LO  = (u32*)(sm + 5*WSZ);
    float* P  = (float*)(sm + 6*WSZ);
    float* RS = (float*)(sm + 6*WSZ + 3584);
    float* RQ = (float*)(sm + 6*WSZ + 5632);

    const int tid = threadIdx.x, w = tid >> 5, lane = tid & 31;
    const int lr = lane >> 2, lc = lane & 3;
    const int wrow = (w & 3) * 32, wcol = (w >> 2) * 32, cw = w >> 2;
    const u32 aoff = mk_aoff(wrow, lane), boff = mk_boff(wcol, lane);
    const u32 sAH = smem_u32(A_HI), sAL = smem_u32(A_LO);
    const u32 sWAH = smem_u32(WA_HI), sWAL = smem_u32(WA_LO);
    const u32 sWBH = smem_u32(WB_HI), sWBL = smem_u32(WB_LO);

    // prologue: issue first h-image load FIRST (overlaps weight-split loads)
    {
        const uint4* s4 = g_h + (size_t)blockIdx.x * TILEU4;
        #pragma unroll
        for (int j = 0; j < 9; ++j) {
            int i = tid + j * 512;
            if (i < TILEU4) CP16(sAH + (u32)i * 16, s4 + i);
        }
        CP_COMMIT();
    }
    load_wsplit(WA_HI, WA_LO, w2a_top, tid, 512);
    load_wsplit(WB_HI, WB_LO, w2b,     tid, 512);
    for (int i = tid; i < HD; i += 512) {
        P[i]       = g2a[i]; P[128+i] = be2a[i];
        P[256+i]   = b2b[i]; P[384+i] = g2b[i]; P[512+i] = be2b[i];
        P[640+i]   = gn[i];  P[768+i] = bn[i];
    }
    {
        int grow = blockIdx.x * TM + (tid >> 2);
        if (grow < NROWS) PREF_L2((const char*)x + (size_t)blockIdx.x * TM * HD * 4 + tid * 128);
    }
    __syncthreads();

    for (int t = blockIdx.x; t < NT; t += gridDim.x) {
        int r0 = t * TM;
        int tn = t + gridDim.x; if (tn >= NT) tn = t;

        CP_WAIT0();                       // current h image resident in A
        __syncthreads();

        // warm L2 with NEXT tile's h image (the real cp.async is issued after GEMM2)
        {
            const char* nh = (const char*)(g_h + (size_t)tn * TILEU4);
            for (int l = tid; l < 544; l += 512) PREF_L2(nh + (size_t)l * 128);
        }
        // prefetch this tile's Z rows into L2
        {
            int grow = r0 + (tid >> 2); if (grow >= NROWS) grow = NROWS - 1;
            int lnid = __ldg(lane_ids + grow);
            PREF_L2(g_z + (size_t)lnid * HD + (tid & 3) * 32);
        }

        float acc[8][4];
        #pragma unroll
        for (int i = 0; i < 8; ++i) { acc[i][0]=acc[i][1]=acc[i][2]=acc[i][3]=0.f; }
        gemm_merged(sAH, sAL, sWAH, sWAL, aoff, boff, acc);

        // add Z[lane] (fp32, b2a folded in)
        #pragma unroll
        for (int rt = 0; rt < 2; ++rt)
        #pragma unroll
        for (int hh = 0; hh < 2; ++hh) {
            int row = wrow + rt*16 + hh*8 + lr;
            int grow = r0 + row; if (grow >= NROWS) grow = NROWS - 1;
            int lnid = __ldg(lane_ids + grow);
            const float* zr = g_z + (size_t)lnid * HD;
            #pragma unroll
            for (int nt = 0; nt < 4; ++nt) {
                int c = wcol + nt*8 + lc*2;
                float2 zv = __ldg((const float2*)(zr + c));
                acc[rt*4+nt][hh*2+0] += zv.x;
                acc[rt*4+nt][hh*2+1] += zv.y;
            }
        }
        // LN1 + ReLU (contains 2 syncthreads; first one guarantees all GEMM1 A-reads done)
        ln_tile<false, true>(acc, wrow, wcol, lr, lc, cw, P, P, P+128, RS, RQ);

        // store f into A (in place; safe per ln_tile syncs)
        store_acc_split(acc, A_HI, A_LO, wrow, wcol, lr, lc);
        __syncthreads();

        // GEMM2: f @ w2b
        #pragma unroll
        for (int i = 0; i < 8; ++i) { acc[i][0]=acc[i][1]=acc[i][2]=acc[i][3]=0.f; }
        gemm_merged(sAH, sAL, sWBH, sWBL, aoff, boff, acc);
        __syncthreads();                  // all A reads complete

        // A free: issue NEXT tile's h image now — overlaps the whole epilogue
        {
            const uint4* s4 = g_h + (size_t)tn * TILEU4;
            #pragma unroll
            for (int j = 0; j < 9; ++j) {
                int i = tid + j * 512;
                if (i < TILEU4) CP16(sAH + (u32)i * 16, s4 + i);
            }
            CP_COMMIT();
            int grow = tn * TM + (tid >> 2);
            if (grow < NROWS) PREF_L2((const char*)x + (size_t)tn * TM * HD * 4 + tid * 128);
        }

        // LN2 + ReLU (b2b, g2b, be2b)
        ln_tile<true, true>(acc, wrow, wcol, lr, lc, cw, P+256, P+384, P+512, RS, RQ);

        // residual add from x (L2-hot)
        #pragma unroll
        for (int rt = 0; rt < 2; ++rt)
        #pragma unroll
        for (int hh = 0; hh < 2; ++hh) {
            int row = wrow + rt*16 + hh*8 + lr;
            int grow = r0 + row; if (grow >= NROWS) grow = NROWS - 1;
            #pragma unroll
            for (int nt = 0; nt < 4; ++nt) {
                int c = wcol + nt*8 + lc*2;
                float2 xv = __ldg((const float2*)(x + (size_t)grow * HD + c));
                acc[rt*4+nt][hh*2+0] += xv.x;
                acc[rt*4+nt][hh*2+1] += xv.y;
            }
        }
        // final LN (gn, bn)
        ln_tile<false, false>(acc, wrow, wcol, lr, lc, cw, P, P+640, P+768, RS, RQ);

        // write out straight from registers
        #pragma unroll
        for (int rt = 0; rt < 2; ++rt)
        #pragma unroll
        for (int hh = 0; hh < 2; ++hh) {
            int row = wrow + rt*16 + hh*8 + lr;
            int grow = r0 + row;
            if (grow < NROWS) {
                #pragma unroll
                for (int nt = 0; nt < 4; ++nt) {
                    int c = wcol + nt*8 + lc*2;
                    *(float2*)(out + (size_t)grow * HD + c) =
                        make_float2(acc[rt*4+nt][hh*2+0], acc[rt*4+nt][hh*2+1]);
                }
            }
        }
        // no trailing sync needed: loop top CP_WAIT0 + __syncthreads gates A reuse
    }
}

// ---------------- launcher ----------------
extern "C" void kernel_launch(void* const* d_in, const int* in_sizes, int n_in,
                              void* d_out, int out_size) {
    (void)in_sizes; (void)n_in; (void)out_size;
    const float* x        = (const float*)d_in[0];
    const int*   lane_ids = (const int*)  d_in[1];
    const float* w1a  = (const float*)d_in[2];
    const float* b1a  = (const float*)d_in[3];
    const float* g1a  = (const float*)d_in[4];
    const float* be1a = (const float*)d_in[5];
    const float* w1b  = (const float*)d_in[6];
    const float* b1b  = (const float*)d_in[7];
    const float* g1b  = (const float*)d_in[8];
    const float* be1b = (const float*)d_in[9];
    const float* w2a  = (const float*)d_in[10];
    const float* b2a  = (const float*)d_in[11];
    const float* g2a  = (const float*)d_in[12];
    const float* be2a = (const float*)d_in[13];
    const float* w2b  = (const float*)d_in[14];
    const float* b2b  = (const float*)d_in[15];
    const float* g2b  = (const float*)d_in[16];
    const float* be2b = (const float*)d_in[17];
    const float* gn   = (const float*)d_in[18];
    const float* bn   = (const float*)d_in[19];
    float* out = (float*)d_out;

    const int SM1  = 6*WSZ + 3072 + 4096;   // fc1
    const int SMLG = 4*WSZ + 1024;          // lanegemm
    const int SM2  = 6*WSZ + 3584 + 4096;   // fused fc2 = 216576
    cudaFuncSetAttribute(k_fc1,      cudaFuncAttributeMaxDynamicSharedMemorySize, SM1);
    cudaFuncSetAttribute(k_lanegemm, cudaFuncAttributeMaxDynamicSharedMemorySize, SMLG);
    cudaFuncSetAttribute(k_fc2,      cudaFuncAttributeMaxDynamicSharedMemorySize, SM2);

    k_init_lanemax<<<(NLANES * HD + 511) / 512, 512>>>();
    k_fc1     <<<148, 512, SM1>>> (x, lane_ids, w1a, b1a, g1a, be1a, w1b, b1b, g1b, be1b);
    k_lanegemm<<<148, 512, SMLG>>>(w2a + 128 * HD, b2a);
    k_fc2     <<<148, 512, SM2>>> (x, lane_ids, w2a, g2a, be2a, w2b, b2b, g2b, be2b, gn, bn, out);
}

// round 9
// speedup vs baseline: 2.0111x; 1.0911x over previous
#include <cuda_runtime.h>
#include <cuda_bf16.h>
#include <cstdint>

#define NROWS  300000
#define HD     128
#define NLANES 25000
#define LNEPS  1e-5f
#define TM     128
#define NT     ((NROWS + TM - 1) / TM)     // 2344 tiles
#define NLT    ((NLANES + 127) / 128)      // 196 lane tiles
#define PADU   68                           // u32 per 128-bf16 row (272B, conflict-free)
#define ROWB   272
#define TILEU4 4352                         // uint4 per split tile image (hi+lo)

typedef unsigned int       u32;
typedef unsigned short     u16;
typedef unsigned long long u64;

// ---------------- device scratch ----------------
__device__ uint4 g_h[(size_t)NT * TILEU4];   // fc1 output image (split, padded)
__device__ int   g_lanemax[NLANES * HD];     // per-lane max (float bits, relu>=0)
__device__ float g_z[(size_t)NLANES * HD];   // per-lane Z = max @ w2a_bot + b2a

// ---------------- helpers ----------------
static __device__ __forceinline__ u32 smem_u32(const void* p) {
    u32 a;
    asm("{ .reg .u64 t; cvta.to.shared.u64 t, %1; cvt.u32.u64 %0, t; }" : "=r"(a) : "l"(p));
    return a;
}

// Fast exact bf16 hi/lo split of a pair (numerically identical to the old path:
// both terms round-to-nearest bf16; hi-as-float recovery is exact bit surgery).
static __device__ __forceinline__ void split_pair(float v0, float v1, u32& hi, u32& lo) {
    u32 h;
    asm("cvt.rn.satfinite.bf16x2.f32 %0, %1, %2;" : "=r"(h) : "f"(v1), "f"(v0)); // lo-half=v0
    float h0 = __uint_as_float(h << 16);
    float h1 = __uint_as_float(h & 0xffff0000u);
    float l0 = v0 - h0, l1 = v1 - h1;
    u32 l;
    asm("cvt.rn.satfinite.bf16x2.f32 %0, %1, %2;" : "=r"(l) : "f"(l1), "f"(l0));
    hi = h; lo = l;
}

#define CP16(sm_addr, gptr) \
    asm volatile("cp.async.cg.shared.global [%0], [%1], 16;" :: "r"(sm_addr), "l"(gptr))
#define CP_COMMIT() asm volatile("cp.async.commit_group;" ::: "memory")
#define CP_WAIT0()  asm volatile("cp.async.wait_group 0;" ::: "memory")
#define PREF_L2(p)  asm volatile("prefetch.global.L2 [%0];" :: "l"(p))

static __device__ __forceinline__ void ldsm4(u32& r0, u32& r1, u32& r2, u32& r3, u32 addr) {
    asm volatile("ldmatrix.sync.aligned.m8n8.x4.shared.b16 {%0,%1,%2,%3}, [%4];"
        : "=r"(r0), "=r"(r1), "=r"(r2), "=r"(r3) : "r"(addr));
}
static __device__ __forceinline__ void mma16816(float (&d)[4], const u32 (&a)[4], u32 b0, u32 b1) {
    asm volatile("mma.sync.aligned.m16n8k16.row.col.f32.bf16.bf16.f32 "
        "{%0,%1,%2,%3}, {%4,%5,%6,%7}, {%8,%9}, {%0,%1,%2,%3};"
        : "+f"(d[0]), "+f"(d[1]), "+f"(d[2]), "+f"(d[3])
        : "r"(a[0]), "r"(a[1]), "r"(a[2]), "r"(a[3]), "r"(b0), "r"(b1));
}

// Merged split GEMM: acc += Ah*Bh^T + Al*Bh^T + Ah*Bl^T over K=128.
static __device__ __forceinline__ void gemm_merged(
    u32 Ah, u32 Al, u32 Bh, u32 Bl, u32 aoff, u32 boff, float (&acc)[8][4])
{
    #pragma unroll
    for (int kc = 0; kc < 8; ++kc) {
        const u32 ka = kc * 32;
        u32 ah0[4], ah1[4], al0[4], al1[4], bh[8], bl[8];
        ldsm4(ah0[0], ah0[1], ah0[2], ah0[3], Ah + aoff + ka);
        ldsm4(ah1[0], ah1[1], ah1[2], ah1[3], Ah + aoff + 16 * ROWB + ka);
        ldsm4(al0[0], al0[1], al0[2], al0[3], Al + aoff + ka);
        ldsm4(al1[0], al1[1], al1[2], al1[3], Al + aoff + 16 * ROWB + ka);
        ldsm4(bh[0], bh[1], bh[2], bh[3], Bh + boff + ka);
        ldsm4(bh[4], bh[5], bh[6], bh[7], Bh + boff + 16 * ROWB + ka);
        ldsm4(bl[0], bl[1], bl[2], bl[3], Bl + boff + ka);
        ldsm4(bl[4], bl[5], bl[6], bl[7], Bl + boff + 16 * ROWB + ka);
        #pragma unroll
        for (int p = 0; p < 2; ++p)
        #pragma unroll
        for (int j = 0; j < 2; ++j) {
            const int nt = p * 2 + j;
            const u32 b0h = bh[p*4 + j*2], b1h = bh[p*4 + j*2 + 1];
            const u32 b0l = bl[p*4 + j*2], b1l = bl[p*4 + j*2 + 1];
            mma16816(acc[nt],     ah0, b0h, b1h);
            mma16816(acc[4 + nt], ah1, b0h, b1h);
            mma16816(acc[nt],     al0, b0h, b1h);
            mma16816(acc[4 + nt], al1, b0h, b1h);
            mma16816(acc[nt],     ah0, b0l, b1l);
            mma16816(acc[4 + nt], ah1, b0l, b1l);
        }
    }
}

// ---------------- LN epilogue (SINGLE barrier; caller alternates RS/RQ sets) ----------------
template<bool HASB, bool RELU>
static __device__ __forceinline__ void ln_tile(
    float (&acc)[8][4], int wrow, int wcol, int lr, int lc, int cw,
    const float* __restrict__ bias, const float* __restrict__ gam,
    const float* __restrict__ bet, float* RS, float* RQ)
{
    float s[4] = {0.f,0.f,0.f,0.f}, q[4] = {0.f,0.f,0.f,0.f};
    #pragma unroll
    for (int rt = 0; rt < 2; ++rt)
    #pragma unroll
    for (int nt = 0; nt < 4; ++nt) {
        float* a = acc[rt * 4 + nt];
        if (HASB) {
            int c = wcol + nt * 8 + lc * 2;
            float bx = bias[c], by = bias[c + 1];
            a[0] += bx; a[1] += by; a[2] += bx; a[3] += by;
        }
        s[rt*2+0] += a[0] + a[1]; q[rt*2+0] += a[0]*a[0] + a[1]*a[1];
        s[rt*2+1] += a[2] + a[3]; q[rt*2+1] += a[2]*a[2] + a[3]*a[3];
    }
    #pragma unroll
    for (int off = 1; off <= 2; off <<= 1)
        #pragma unroll
        for (int i = 0; i < 4; ++i) {
            s[i] += __shfl_xor_sync(0xffffffffu, s[i], off);
            q[i] += __shfl_xor_sync(0xffffffffu, q[i], off);
        }
    if (lc == 0) {
        #pragma unroll
        for (int i = 0; i < 4; ++i) {
            int row = wrow + (i >> 1) * 16 + (i & 1) * 8 + lr;
            RS[cw * 128 + row] = s[i];
            RQ[cw * 128 + row] = q[i];
        }
    }
    __syncthreads();
    float mm[4], rsd[4];
    #pragma unroll
    for (int i = 0; i < 4; ++i) {
        int row = wrow + (i >> 1) * 16 + (i & 1) * 8 + lr;
        float S = RS[row] + RS[128 + row] + RS[256 + row] + RS[384 + row];
        float Q = RQ[row] + RQ[128 + row] + RQ[256 + row] + RQ[384 + row];
        float m = S * (1.f / 128.f);
        mm[i] = m;
        rsd[i] = rsqrtf(Q * (1.f / 128.f) - m * m + LNEPS);
    }
    #pragma unroll
    for (int rt = 0; rt < 2; ++rt)
    #pragma unroll
    for (int nt = 0; nt < 4; ++nt) {
        int c = wcol + nt * 8 + lc * 2;
        float gx = gam[c], gy = gam[c + 1], ex = bet[c], ey = bet[c + 1];
        float* a = acc[rt * 4 + nt];
        int s0 = rt * 2, s1 = rt * 2 + 1;
        a[0] = (a[0] - mm[s0]) * rsd[s0] * gx + ex;
        a[1] = (a[1] - mm[s0]) * rsd[s0] * gy + ey;
        a[2] = (a[2] - mm[s1]) * rsd[s1] * gx + ex;
        a[3] = (a[3] - mm[s1]) * rsd[s1] * gy + ey;
        if (RELU) {
            a[0] = fmaxf(a[0], 0.f); a[1] = fmaxf(a[1], 0.f);
            a[2] = fmaxf(a[2], 0.f); a[3] = fmaxf(a[3], 0.f);
        }
    }
}

static __device__ __forceinline__ void store_acc_split(
    const float (&acc)[8][4], u32* hi, u32* lo, int wrow, int wcol, int lr, int lc)
{
    #pragma unroll
    for (int rt = 0; rt < 2; ++rt)
    #pragma unroll
    for (int hh = 0; hh < 2; ++hh) {
        int row = wrow + rt * 16 + hh * 8 + lr;
        u32 base = row * PADU + (wcol >> 1) + lc;
        #pragma unroll
        for (int nt = 0; nt < 4; ++nt) {
            u32 h, l;
            split_pair(acc[rt*4+nt][hh*2+0], acc[rt*4+nt][hh*2+1], h, l);
            hi[base + nt*4] = h;
            lo[base + nt*4] = l;
        }
    }
}

static __device__ __forceinline__ void store_split4(u32* hi, u32* lo, int row, int col, float4 xv) {
    u32 idx = row * PADU + (col >> 1);
    u32 h0, l0, h1, l1;
    split_pair(xv.x, xv.y, h0, l0);
    split_pair(xv.z, xv.w, h1, l1);
    hi[idx]   = h0; hi[idx+1] = h1;
    lo[idx]   = l0; lo[idx+1] = l1;
}

static __device__ __forceinline__ void load_wsplit(u32* hi, u32* lo, const float* __restrict__ w,
                                                   int tid, int nth) {
    for (int idx = tid; idx < HD * HD / 2; idx += nth) {
        int o = idx & 127, k2 = idx >> 7;
        float v0 = w[(2*k2)   * HD + o];
        float v1 = w[(2*k2+1) * HD + o];
        u32 off = o * PADU + k2;
        u32 h, l;
        split_pair(v0, v1, h, l);
        hi[off] = h;
        lo[off] = l;
    }
}

__global__ void k_init_lanemax() {
    int i = blockIdx.x * blockDim.x + threadIdx.x;
    if (i < NLANES * HD) g_lanemax[i] = 0;
}

#define WSZ 34816

static __device__ __forceinline__ u32 mk_aoff(int wrow, int lane) {
    return (u32)((wrow + (lane & 15)) * ROWB + ((lane >> 4) & 1) * 16);
}
static __device__ __forceinline__ u32 mk_boff(int wcol, int lane) {
    return (u32)((wcol + ((lane >> 4) & 1) * 8 + (lane & 7)) * ROWB + ((lane >> 3) & 1) * 16);
}

// ======================== fc1 ========================
// smem: WA_HI 0 | WA_LO WSZ | WB_HI 2WSZ | WB_LO 3WSZ | A_HI 4WSZ | A_LO 5WSZ
//       P 6WSZ (3072B) | RS0 +3072 | RQ0 +5120 | RS1 +7168 | RQ1 +9216
__global__ void __launch_bounds__(512, 1) k_fc1(
    const float* __restrict__ x, const int* __restrict__ lane_ids,
    const float* __restrict__ w1a, const float* __restrict__ b1a,
    const float* __restrict__ g1a, const float* __restrict__ be1a,
    const float* __restrict__ w1b, const float* __restrict__ b1b,
    const float* __restrict__ g1b, const float* __restrict__ be1b)
{
    extern __shared__ char sm[];
    u32* WA_HI = (u32*)(sm);            u32* WA_LO = (u32*)(sm + WSZ);
    u32* WB_HI = (u32*)(sm + 2*WSZ);    u32* WB_LO = (u32*)(sm + 3*WSZ);
    u32* A_HI  = (u32*)(sm + 4*WSZ);    u32* A_LO  = (u32*)(sm + 5*WSZ);
    float* P   = (float*)(sm + 6*WSZ);
    float* RS0 = (float*)(sm + 6*WSZ + 3072);
    float* RQ0 = (float*)(sm + 6*WSZ + 5120);
    float* RS1 = (float*)(sm + 6*WSZ + 7168);
    float* RQ1 = (float*)(sm + 6*WSZ + 9216);

    const int tid = threadIdx.x, w = tid >> 5, lane = tid & 31;
    const int lr = lane >> 2, lc = lane & 3;
    const int wrow = (w & 3) * 32, wcol = (w >> 2) * 32, cw = w >> 2;
    const u32 aoff = mk_aoff(wrow, lane), boff = mk_boff(wcol, lane);
    const u32 sAH = smem_u32(A_HI), sAL = smem_u32(A_LO);
    const u32 sWAH = smem_u32(WA_HI), sWAL = smem_u32(WA_LO);
    const u32 sWBH = smem_u32(WB_HI), sWBL = smem_u32(WB_LO);

    load_wsplit(WA_HI, WA_LO, w1a, tid, 512);
    load_wsplit(WB_HI, WB_LO, w1b, tid, 512);
    for (int i = tid; i < HD; i += 512) {
        P[i] = b1a[i]; P[128+i] = g1a[i]; P[256+i] = be1a[i];
        P[384+i] = b1b[i]; P[512+i] = g1b[i]; P[640+i] = be1b[i];
    }
    {
        int grow = blockIdx.x * TM + (tid >> 2);
        if (grow < NROWS) PREF_L2((const char*)x + (size_t)blockIdx.x * TM * HD * 4 + tid * 128);
    }
    __syncthreads();

    for (int t = blockIdx.x; t < NT; t += gridDim.x) {
        int r0 = t * TM;
        #pragma unroll
        for (int j = 0; j < 8; ++j) {
            int idx = tid + j * 512; int xr = idx >> 5; int cg = idx & 31;
            int grow = r0 + xr; if (grow >= NROWS) grow = NROWS - 1;
            float4 xv = __ldg(((const float4*)x) + ((size_t)grow * 32 + cg));
            store_split4(A_HI, A_LO, xr, cg * 4, xv);
        }
        {
            int tn = t + gridDim.x; if (tn >= NT) tn = t;
            int grow = tn * TM + (tid >> 2);
            if (grow < NROWS) PREF_L2((const char*)x + (size_t)tn * TM * HD * 4 + tid * 128);
        }
        __syncthreads();

        float acc[8][4];
        #pragma unroll
        for (int i = 0; i < 8; ++i) { acc[i][0]=acc[i][1]=acc[i][2]=acc[i][3]=0.f; }
        gemm_merged(sAH, sAL, sWAH, sWAL, aoff, boff, acc);
        ln_tile<true, true>(acc, wrow, wcol, lr, lc, cw, P, P+128, P+256, RS0, RQ0);
        store_acc_split(acc, A_HI, A_LO, wrow, wcol, lr, lc);
        __syncthreads();

        #pragma unroll
        for (int i = 0; i < 8; ++i) { acc[i][0]=acc[i][1]=acc[i][2]=acc[i][3]=0.f; }
        gemm_merged(sAH, sAL, sWBH, sWBL, aoff, boff, acc);
        ln_tile<true, true>(acc, wrow, wcol, lr, lc, cw, P+384, P+512, P+640, RS1, RQ1);

        // scatter-max (predicated: relu zeros are no-ops vs init 0)
        #pragma unroll
        for (int rt = 0; rt < 2; ++rt)
        #pragma unroll
        for (int hh = 0; hh < 2; ++hh) {
            int row = wrow + rt*16 + hh*8 + lr;
            int grow = r0 + row; if (grow >= NROWS) grow = NROWS - 1;
            int ln = __ldg(lane_ids + grow);
            int* bp = g_lanemax + ln * HD;
            #pragma unroll
            for (int nt = 0; nt < 4; ++nt) {
                int c = wcol + nt*8 + lc*2;
                float v0 = acc[rt*4+nt][hh*2+0], v1 = acc[rt*4+nt][hh*2+1];
                if (v0 > 0.f) atomicMax(bp + c,     __float_as_int(v0));
                if (v1 > 0.f) atomicMax(bp + c + 1, __float_as_int(v1));
            }
        }
        store_acc_split(acc, A_HI, A_LO, wrow, wcol, lr, lc);
        __syncthreads();

        const uint4* s4 = (const uint4*)A_HI;
        uint4* d4 = g_h + (size_t)t * TILEU4;
        for (int i = tid; i < TILEU4; i += 512) d4[i] = s4[i];
        __syncthreads();
    }
}

// ======================== k_lanegemm: Z = lane_max @ w2a_bot + b2a ========================
__global__ void __launch_bounds__(512, 1) k_lanegemm(
    const float* __restrict__ w2a_bot, const float* __restrict__ b2a)
{
    extern __shared__ char sm[];
    u32* W_HI = (u32*)(sm);            u32* W_LO = (u32*)(sm + WSZ);
    u32* A_HI = (u32*)(sm + 2*WSZ);    u32* A_LO = (u32*)(sm + 3*WSZ);
    float* P  = (float*)(sm + 4*WSZ);   // b2a

    const int tid = threadIdx.x, w = tid >> 5, lane = tid & 31;
    const int lr = lane >> 2, lc = lane & 3;
    const int wrow = (w & 3) * 32, wcol = (w >> 2) * 32;
    const u32 aoff = mk_aoff(wrow, lane), boff = mk_boff(wcol, lane);
    const u32 sAH = smem_u32(A_HI), sAL = smem_u32(A_LO);
    const u32 sWH = smem_u32(W_HI), sWL = smem_u32(W_LO);

    load_wsplit(W_HI, W_LO, w2a_bot, tid, 512);
    for (int i = tid; i < HD; i += 512) P[i] = b2a[i];
    __syncthreads();

    for (int t = blockIdx.x; t < NLT; t += gridDim.x) {
        int l0 = t * 128;
        #pragma unroll
        for (int j = 0; j < 8; ++j) {
            int idx = tid + j * 512; int xr = idx >> 5; int cg = idx & 31;
            int l = l0 + xr; if (l >= NLANES) l = NLANES - 1;
            int4 gv = __ldg(((const int4*)(g_lanemax)) + ((size_t)l * 32 + cg));
            store_split4(A_HI, A_LO, xr, cg * 4,
                make_float4(__int_as_float(gv.x), __int_as_float(gv.y),
                            __int_as_float(gv.z), __int_as_float(gv.w)));
        }
        __syncthreads();

        float acc[8][4];
        #pragma unroll
        for (int i = 0; i < 8; ++i) { acc[i][0]=acc[i][1]=acc[i][2]=acc[i][3]=0.f; }
        gemm_merged(sAH, sAL, sWH, sWL, aoff, boff, acc);

        #pragma unroll
        for (int rt = 0; rt < 2; ++rt)
        #pragma unroll
        for (int hh = 0; hh < 2; ++hh) {
            int row = wrow + rt*16 + hh*8 + lr;
            int l = l0 + row;
            if (l < NLANES) {
                #pragma unroll
                for (int nt = 0; nt < 4; ++nt) {
                    int c = wcol + nt*8 + lc*2;
                    *(float2*)(g_z + (size_t)l * HD + c) =
                        make_float2(acc[rt*4+nt][hh*2+0] + P[c],
                                    acc[rt*4+nt][hh*2+1] + P[c+1]);
                }
            }
        }
        __syncthreads();
    }
}

// ======================== fused fc2 ========================
// smem: W2A_HI 0 | W2A_LO WSZ | W2B_HI 2WSZ | W2B_LO 3WSZ | A_HI 4WSZ | A_LO 5WSZ
//       P 6WSZ (3584B) | RS0 +3584 | RQ0 +5632 | RS1 +7680 | RQ1 +9728
__global__ void __launch_bounds__(512, 1) k_fc2(
    const float* __restrict__ x, const int* __restrict__ lane_ids,
    const float* __restrict__ w2a_top,
    const float* __restrict__ g2a, const float* __restrict__ be2a,
    const float* __restrict__ w2b, const float* __restrict__ b2b,
    const float* __restrict__ g2b, const float* __restrict__ be2b,
    const float* __restrict__ gn, const float* __restrict__ bn,
    float* __restrict__ out)
{
    extern __shared__ char sm[];
    u32* WA_HI = (u32*)(sm);            u32* WA_LO = (u32*)(sm + WSZ);
    u32* WB_HI = (u32*)(sm + 2*WSZ);    u32* WB_LO = (u32*)(sm + 3*WSZ);
    u32* A_HI  = (u32*)(sm + 4*WSZ);    u32* A_LO  = (u32*)(sm + 5*WSZ);
    float* P   = (float*)(sm + 6*WSZ);
    float* RS0 = (float*)(sm + 6*WSZ + 3584);
    float* RQ0 = (float*)(sm + 6*WSZ + 5632);
    float* RS1 = (float*)(sm + 6*WSZ + 7680);
    float* RQ1 = (float*)(sm + 6*WSZ + 9728);

    const int tid = threadIdx.x, w = tid >> 5, lane = tid & 31;
    const int lr = lane >> 2, lc = lane & 3;
    const int wrow = (w & 3) * 32, wcol = (w >> 2) * 32, cw = w >> 2;
    const u32 aoff = mk_aoff(wrow, lane), boff = mk_boff(wcol, lane);
    const u32 sAH = smem_u32(A_HI), sAL = smem_u32(A_LO);
    const u32 sWAH = smem_u32(WA_HI), sWAL = smem_u32(WA_LO);
    const u32 sWBH = smem_u32(WB_HI), sWBL = smem_u32(WB_LO);

    // prologue: issue first h-image load FIRST (overlaps weight-split loads)
    {
        const uint4* s4 = g_h + (size_t)blockIdx.x * TILEU4;
        #pragma unroll
        for (int j = 0; j < 9; ++j) {
            int i = tid + j * 512;
            if (i < TILEU4) CP16(sAH + (u32)i * 16, s4 + i);
        }
        CP_COMMIT();
    }
    load_wsplit(WA_HI, WA_LO, w2a_top, tid, 512);
    load_wsplit(WB_HI, WB_LO, w2b,     tid, 512);
    for (int i = tid; i < HD; i += 512) {
        P[i]       = g2a[i]; P[128+i] = be2a[i];
        P[256+i]   = b2b[i]; P[384+i] = g2b[i]; P[512+i] = be2b[i];
        P[640+i]   = gn[i];  P[768+i] = bn[i];
    }
    {
        int grow = blockIdx.x * TM + (tid >> 2);
        if (grow < NROWS) PREF_L2((const char*)x + (size_t)blockIdx.x * TM * HD * 4 + tid * 128);
    }
    __syncthreads();

    for (int t = blockIdx.x; t < NT; t += gridDim.x) {
        int r0 = t * TM;
        int tn = t + gridDim.x; if (tn >= NT) tn = t;

        CP_WAIT0();                       // current h image resident in A
        __syncthreads();

        // warm L2 with NEXT tile's h image (real cp.async issued after GEMM2)
        {
            const char* nh = (const char*)(g_h + (size_t)tn * TILEU4);
            for (int l = tid; l < 544; l += 512) PREF_L2(nh + (size_t)l * 128);
        }
        // prefetch this tile's Z rows into L2
        {
            int grow = r0 + (tid >> 2); if (grow >= NROWS) grow = NROWS - 1;
            int lnid = __ldg(lane_ids + grow);
            PREF_L2(g_z + (size_t)lnid * HD + (tid & 3) * 32);
        }

        float acc[8][4];
        #pragma unroll
        for (int i = 0; i < 8; ++i) { acc[i][0]=acc[i][1]=acc[i][2]=acc[i][3]=0.f; }
        gemm_merged(sAH, sAL, sWAH, sWAL, aoff, boff, acc);

        // add Z[lane] (fp32, b2a folded in)
        #pragma unroll
        for (int rt = 0; rt < 2; ++rt)
        #pragma unroll
        for (int hh = 0; hh < 2; ++hh) {
            int row = wrow + rt*16 + hh*8 + lr;
            int grow = r0 + row; if (grow >= NROWS) grow = NROWS - 1;
            int lnid = __ldg(lane_ids + grow);
            const float* zr = g_z + (size_t)lnid * HD;
            #pragma unroll
            for (int nt = 0; nt < 4; ++nt) {
                int c = wcol + nt*8 + lc*2;
                float2 zv = __ldg((const float2*)(zr + c));
                acc[rt*4+nt][hh*2+0] += zv.x;
                acc[rt*4+nt][hh*2+1] += zv.y;
            }
        }
        // LN1 + ReLU (set0; its barrier also guarantees all GEMM1 A-reads done)
        ln_tile<false, true>(acc, wrow, wcol, lr, lc, cw, P, P, P+128, RS0, RQ0);

        // store f into A (in place; safe per LN1 barrier)
        store_acc_split(acc, A_HI, A_LO, wrow, wcol, lr, lc);
        __syncthreads();

        // GEMM2: f @ w2b
        #pragma unroll
        for (int i = 0; i < 8; ++i) { acc[i][0]=acc[i][1]=acc[i][2]=acc[i][3]=0.f; }
        gemm_merged(sAH, sAL, sWBH, sWBL, aoff, boff, acc);
        __syncthreads();                  // all A reads complete

        // A free: issue NEXT tile's h image now — overlaps the whole epilogue
        {
            const uint4* s4 = g_h + (size_t)tn * TILEU4;
            #pragma unroll
            for (int j = 0; j < 9; ++j) {
                int i = tid + j * 512;
                if (i < TILEU4) CP16(sAH + (u32)i * 16, s4 + i);
            }
            CP_COMMIT();
            int grow = tn * TM + (tid >> 2);
            if (grow < NROWS) PREF_L2((const char*)x + (size_t)tn * TM * HD * 4 + tid * 128);
        }

        // LN2 + ReLU (set1)
        ln_tile<true, true>(acc, wrow, wcol, lr, lc, cw, P+256, P+384, P+512, RS1, RQ1);

        // residual add from x (L2-hot)
        #pragma unroll
        for (int rt = 0; rt < 2; ++rt)
        #pragma unroll
        for (int hh = 0; hh < 2; ++hh) {
            int row = wrow + rt*16 + hh*8 + lr;
            int grow = r0 + row; if (grow >= NROWS) grow = NROWS - 1;
            #pragma unroll
            for (int nt = 0; nt < 4; ++nt) {
                int c = wcol + nt*8 + lc*2;
                float2 xv = __ldg((const float2*)(x + (size_t)grow * HD + c));
                acc[rt*4+nt][hh*2+0] += xv.x;
                acc[rt*4+nt][hh*2+1] += xv.y;
            }
        }
        // final LN (set0 — safe: last set0 read was LN1, separated by post-GEMM2 barrier)
        ln_tile<false, false>(acc, wrow, wcol, lr, lc, cw, P, P+640, P+768, RS0, RQ0);

        // write out straight from registers
        #pragma unroll
        for (int rt = 0; rt < 2; ++rt)
        #pragma unroll
        for (int hh = 0; hh < 2; ++hh) {
            int row = wrow + rt*16 + hh*8 + lr;
            int grow = r0 + row;
            if (grow < NROWS) {
                #pragma unroll
                for (int nt = 0; nt < 4; ++nt) {
                    int c = wcol + nt*8 + lc*2;
                    *(float2*)(out + (size_t)grow * HD + c) =
                        make_float2(acc[rt*4+nt][hh*2+0], acc[rt*4+nt][hh*2+1]);
                }
            }
        }
        // loop-top CP_WAIT0 + __syncthreads gates A and RS0 reuse
    }
}

// ---------------- launcher ----------------
extern "C" void kernel_launch(void* const* d_in, const int* in_sizes, int n_in,
                              void* d_out, int out_size) {
    (void)in_sizes; (void)n_in; (void)out_size;
    const float* x        = (const float*)d_in[0];
    const int*   lane_ids = (const int*)  d_in[1];
    const float* w1a  = (const float*)d_in[2];
    const float* b1a  = (const float*)d_in[3];
    const float* g1a  = (const float*)d_in[4];
    const float* be1a = (const float*)d_in[5];
    const float* w1b  = (const float*)d_in[6];
    const float* b1b  = (const float*)d_in[7];
    const float* g1b  = (const float*)d_in[8];
    const float* be1b = (const float*)d_in[9];
    const float* w2a  = (const float*)d_in[10];
    const float* b2a  = (const float*)d_in[11];
    const float* g2a  = (const float*)d_in[12];
    const float* be2a = (const float*)d_in[13];
    const float* w2b  = (const float*)d_in[14];
    const float* b2b  = (const float*)d_in[15];
    const float* g2b  = (const float*)d_in[16];
    const float* be2b = (const float*)d_in[17];
    const float* gn   = (const float*)d_in[18];
    const float* bn   = (const float*)d_in[19];
    float* out = (float*)d_out;

    const int SM1  = 6*WSZ + 3072 + 8192;   // 220160
    const int SMLG = 4*WSZ + 1024;          // lanegemm
    const int SM2  = 6*WSZ + 3584 + 8192;   // 220672
    cudaFuncSetAttribute(k_fc1,      cudaFuncAttributeMaxDynamicSharedMemorySize, SM1);
    cudaFuncSetAttribute(k_lanegemm, cudaFuncAttributeMaxDynamicSharedMemorySize, SMLG);
    cudaFuncSetAttribute(k_fc2,      cudaFuncAttributeMaxDynamicSharedMemorySize, SM2);

    k_init_lanemax<<<(NLANES * HD + 511) / 512, 512>>>();
    k_fc1     <<<148, 512, SM1>>> (x, lane_ids, w1a, b1a, g1a, be1a, w1b, b1b, g1b, be1b);
    k_lanegemm<<<148, 512, SMLG>>>(w2a + 128 * HD, b2a);
    k_fc2     <<<148, 512, SM2>>> (x, lane_ids, w2a, g2a, be2a, w2b, b2b, g2b, be2b, gn, bn, out);
}

// round 10
// speedup vs baseline: 2.1710x; 1.0795x over previous
#include <cuda_runtime.h>
#include <cuda_bf16.h>
#include <cuda_fp16.h>
#include <cstdint>

#define NROWS  300000
#define HD     128
#define NLANES 25000
#define LNEPS  1e-5f
#define TM     128
#define NT     ((NROWS + TM - 1) / TM)     // 2344 tiles
#define NLT    ((NLANES + 127) / 128)      // 196 lane tiles
#define PADU   68                           // u32 per 128-b16 row (272B, conflict-free)
#define ROWB   272
#define TILEU4 4352                         // uint4 per split tile image (hi+lo)

typedef unsigned int       u32;
typedef unsigned short     u16;
typedef unsigned long long u64;

// ---------------- device scratch ----------------
__device__ uint4 g_h[(size_t)NT * TILEU4];   // fc1 output image (fp16 split, padded)
__device__ int   g_lanemax[NLANES * HD];     // per-lane max (float bits, relu>=0)
__device__ float g_z[(size_t)NLANES * HD];   // per-lane Z = max @ w2a_bot + b2a

// ---------------- helpers ----------------
static __device__ __forceinline__ u32 smem_u32(const void* p) {
    u32 a;
    asm("{ .reg .u64 t; cvta.to.shared.u64 t, %1; cvt.u32.u64 %0, t; }" : "=r"(a) : "l"(p));
    return a;
}

// bf16 hi/lo split of a pair (fc1 internal path)
static __device__ __forceinline__ void split_pair(float v0, float v1, u32& hi, u32& lo) {
    u32 h;
    asm("cvt.rn.satfinite.bf16x2.f32 %0, %1, %2;" : "=r"(h) : "f"(v1), "f"(v0)); // lo-half=v0
    float h0 = __uint_as_float(h << 16);
    float h1 = __uint_as_float(h & 0xffff0000u);
    float l0 = v0 - h0, l1 = v1 - h1;
    u32 l;
    asm("cvt.rn.satfinite.bf16x2.f32 %0, %1, %2;" : "=r"(l) : "f"(l1), "f"(l0));
    hi = h; lo = l;
}

// fp16 hi/lo split of a pair (fc2 / lanegemm path)
static __device__ __forceinline__ void split_pair_f16(float v0, float v1, u32& hi, u32& lo) {
    __half2 h = __floats2half2_rn(v0, v1);
    float h0 = __low2float(h), h1 = __high2float(h);
    __half2 l = __floats2half2_rn(v0 - h0, v1 - h1);
    hi = *reinterpret_cast<u32*>(&h);
    lo = *reinterpret_cast<u32*>(&l);
}

#define CP16(sm_addr, gptr) \
    asm volatile("cp.async.cg.shared.global [%0], [%1], 16;" :: "r"(sm_addr), "l"(gptr))
#define CP_COMMIT() asm volatile("cp.async.commit_group;" ::: "memory")
#define CP_WAIT0()  asm volatile("cp.async.wait_group 0;" ::: "memory")
#define PREF_L2(p)  asm volatile("prefetch.global.L2 [%0];" :: "l"(p))

static __device__ __forceinline__ void ldsm4(u32& r0, u32& r1, u32& r2, u32& r3, u32 addr) {
    asm volatile("ldmatrix.sync.aligned.m8n8.x4.shared.b16 {%0,%1,%2,%3}, [%4];"
        : "=r"(r0), "=r"(r1), "=r"(r2), "=r"(r3) : "r"(addr));
}
static __device__ __forceinline__ void mma16816(float (&d)[4], const u32 (&a)[4], u32 b0, u32 b1) {
    asm volatile("mma.sync.aligned.m16n8k16.row.col.f32.bf16.bf16.f32 "
        "{%0,%1,%2,%3}, {%4,%5,%6,%7}, {%8,%9}, {%0,%1,%2,%3};"
        : "+f"(d[0]), "+f"(d[1]), "+f"(d[2]), "+f"(d[3])
        : "r"(a[0]), "r"(a[1]), "r"(a[2]), "r"(a[3]), "r"(b0), "r"(b1));
}
static __device__ __forceinline__ void mma_f16(float (&d)[4], const u32 (&a)[4], u32 b0, u32 b1) {
    asm volatile("mma.sync.aligned.m16n8k16.row.col.f32.f16.f16.f32 "
        "{%0,%1,%2,%3}, {%4,%5,%6,%7}, {%8,%9}, {%0,%1,%2,%3};"
        : "+f"(d[0]), "+f"(d[1]), "+f"(d[2]), "+f"(d[3])
        : "r"(a[0]), "r"(a[1]), "r"(a[2]), "r"(a[3]), "r"(b0), "r"(b1));
}

// bf16 3-pass merged GEMM (fc1): acc += Ah*Bh + Al*Bh + Ah*Bl over K=128.
static __device__ __forceinline__ void gemm_merged(
    u32 Ah, u32 Al, u32 Bh, u32 Bl, u32 aoff, u32 boff, float (&acc)[8][4])
{
    #pragma unroll
    for (int kc = 0; kc < 8; ++kc) {
        const u32 ka = kc * 32;
        u32 ah0[4], ah1[4], al0[4], al1[4], bh[8], bl[8];
        ldsm4(ah0[0], ah0[1], ah0[2], ah0[3], Ah + aoff + ka);
        ldsm4(ah1[0], ah1[1], ah1[2], ah1[3], Ah + aoff + 16 * ROWB + ka);
        ldsm4(al0[0], al0[1], al0[2], al0[3], Al + aoff + ka);
        ldsm4(al1[0], al1[1], al1[2], al1[3], Al + aoff + 16 * ROWB + ka);
        ldsm4(bh[0], bh[1], bh[2], bh[3], Bh + boff + ka);
        ldsm4(bh[4], bh[5], bh[6], bh[7], Bh + boff + 16 * ROWB + ka);
        ldsm4(bl[0], bl[1], bl[2], bl[3], Bl + boff + ka);
        ldsm4(bl[4], bl[5], bl[6], bl[7], Bl + boff + 16 * ROWB + ka);
        #pragma unroll
        for (int p = 0; p < 2; ++p)
        #pragma unroll
        for (int j = 0; j < 2; ++j) {
            const int nt = p * 2 + j;
            const u32 b0h = bh[p*4 + j*2], b1h = bh[p*4 + j*2 + 1];
            const u32 b0l = bl[p*4 + j*2], b1l = bl[p*4 + j*2 + 1];
            mma16816(acc[nt],     ah0, b0h, b1h);
            mma16816(acc[4 + nt], ah1, b0h, b1h);
            mma16816(acc[nt],     al0, b0h, b1h);
            mma16816(acc[4 + nt], al1, b0h, b1h);
            mma16816(acc[nt],     ah0, b0l, b1l);
            mma16816(acc[4 + nt], ah1, b0l, b1l);
        }
    }
}

// fp16 2-pass GEMM (fc2 / lanegemm): acc += Ah*B + Al*B over K=128 (B single fp16).
static __device__ __forceinline__ void gemm_f16_2p(
    u32 Ah, u32 Al, u32 B, u32 aoff, u32 boff, float (&acc)[8][4])
{
    #pragma unroll
    for (int kc = 0; kc < 8; ++kc) {
        const u32 ka = kc * 32;
        u32 ah0[4], ah1[4], al0[4], al1[4], b[8];
        ldsm4(ah0[0], ah0[1], ah0[2], ah0[3], Ah + aoff + ka);
        ldsm4(ah1[0], ah1[1], ah1[2], ah1[3], Ah + aoff + 16 * ROWB + ka);
        ldsm4(al0[0], al0[1], al0[2], al0[3], Al + aoff + ka);
        ldsm4(al1[0], al1[1], al1[2], al1[3], Al + aoff + 16 * ROWB + ka);
        ldsm4(b[0], b[1], b[2], b[3], B + boff + ka);
        ldsm4(b[4], b[5], b[6], b[7], B + boff + 16 * ROWB + ka);
        #pragma unroll
        for (int p = 0; p < 2; ++p)
        #pragma unroll
        for (int j = 0; j < 2; ++j) {
            const int nt = p * 2 + j;
            const u32 b0 = b[p*4 + j*2], b1 = b[p*4 + j*2 + 1];
            mma_f16(acc[nt],     ah0, b0, b1);
            mma_f16(acc[4 + nt], ah1, b0, b1);
            mma_f16(acc[nt],     al0, b0, b1);
            mma_f16(acc[4 + nt], al1, b0, b1);
        }
    }
}

// ---------------- LN epilogue (single barrier; caller alternates RS/RQ sets) ----------------
template<bool HASB, bool RELU>
static __device__ __forceinline__ void ln_tile(
    float (&acc)[8][4], int wrow, int wcol, int lr, int lc, int cw,
    const float* __restrict__ bias, const float* __restrict__ gam,
    const float* __restrict__ bet, float* RS, float* RQ)
{
    float s[4] = {0.f,0.f,0.f,0.f}, q[4] = {0.f,0.f,0.f,0.f};
    #pragma unroll
    for (int rt = 0; rt < 2; ++rt)
    #pragma unroll
    for (int nt = 0; nt < 4; ++nt) {
        float* a = acc[rt * 4 + nt];
        if (HASB) {
            int c = wcol + nt * 8 + lc * 2;
            float bx = bias[c], by = bias[c + 1];
            a[0] += bx; a[1] += by; a[2] += bx; a[3] += by;
        }
        s[rt*2+0] += a[0] + a[1]; q[rt*2+0] += a[0]*a[0] + a[1]*a[1];
        s[rt*2+1] += a[2] + a[3]; q[rt*2+1] += a[2]*a[2] + a[3]*a[3];
    }
    #pragma unroll
    for (int off = 1; off <= 2; off <<= 1)
        #pragma unroll
        for (int i = 0; i < 4; ++i) {
            s[i] += __shfl_xor_sync(0xffffffffu, s[i], off);
            q[i] += __shfl_xor_sync(0xffffffffu, q[i], off);
        }
    if (lc == 0) {
        #pragma unroll
        for (int i = 0; i < 4; ++i) {
            int row = wrow + (i >> 1) * 16 + (i & 1) * 8 + lr;
            RS[cw * 128 + row] = s[i];
            RQ[cw * 128 + row] = q[i];
        }
    }
    __syncthreads();
    float mm[4], rsd[4];
    #pragma unroll
    for (int i = 0; i < 4; ++i) {
        int row = wrow + (i >> 1) * 16 + (i & 1) * 8 + lr;
        float S = RS[row] + RS[128 + row] + RS[256 + row] + RS[384 + row];
        float Q = RQ[row] + RQ[128 + row] + RQ[256 + row] + RQ[384 + row];
        float m = S * (1.f / 128.f);
        mm[i] = m;
        rsd[i] = rsqrtf(Q * (1.f / 128.f) - m * m + LNEPS);
    }
    #pragma unroll
    for (int rt = 0; rt < 2; ++rt)
    #pragma unroll
    for (int nt = 0; nt < 4; ++nt) {
        int c = wcol + nt * 8 + lc * 2;
        float gx = gam[c], gy = gam[c + 1], ex = bet[c], ey = bet[c + 1];
        float* a = acc[rt * 4 + nt];
        int s0 = rt * 2, s1 = rt * 2 + 1;
        a[0] = (a[0] - mm[s0]) * rsd[s0] * gx + ex;
        a[1] = (a[1] - mm[s0]) * rsd[s0] * gy + ey;
        a[2] = (a[2] - mm[s1]) * rsd[s1] * gx + ex;
        a[3] = (a[3] - mm[s1]) * rsd[s1] * gy + ey;
        if (RELU) {
            a[0] = fmaxf(a[0], 0.f); a[1] = fmaxf(a[1], 0.f);
            a[2] = fmaxf(a[2], 0.f); a[3] = fmaxf(a[3], 0.f);
        }
    }
}

// bf16 fragment store (fc1 internal)
static __device__ __forceinline__ void store_acc_split(
    const float (&acc)[8][4], u32* hi, u32* lo, int wrow, int wcol, int lr, int lc)
{
    #pragma unroll
    for (int rt = 0; rt < 2; ++rt)
    #pragma unroll
    for (int hh = 0; hh < 2; ++hh) {
        int row = wrow + rt * 16 + hh * 8 + lr;
        u32 base = row * PADU + (wcol >> 1) + lc;
        #pragma unroll
        for (int nt = 0; nt < 4; ++nt) {
            u32 h, l;
            split_pair(acc[rt*4+nt][hh*2+0], acc[rt*4+nt][hh*2+1], h, l);
            hi[base + nt*4] = h;
            lo[base + nt*4] = l;
        }
    }
}

// fp16 fragment store (h image / f)
static __device__ __forceinline__ void store_acc_split_f16(
    const float (&acc)[8][4], u32* hi, u32* lo, int wrow, int wcol, int lr, int lc)
{
    #pragma unroll
    for (int rt = 0; rt < 2; ++rt)
    #pragma unroll
    for (int hh = 0; hh < 2; ++hh) {
        int row = wrow + rt * 16 + hh * 8 + lr;
        u32 base = row * PADU + (wcol >> 1) + lc;
        #pragma unroll
        for (int nt = 0; nt < 4; ++nt) {
            u32 h, l;
            split_pair_f16(acc[rt*4+nt][hh*2+0], acc[rt*4+nt][hh*2+1], h, l);
            hi[base + nt*4] = h;
            lo[base + nt*4] = l;
        }
    }
}

static __device__ __forceinline__ void store_split4(u32* hi, u32* lo, int row, int col, float4 xv) {
    u32 idx = row * PADU + (col >> 1);
    u32 h0, l0, h1, l1;
    split_pair(xv.x, xv.y, h0, l0);
    split_pair(xv.z, xv.w, h1, l1);
    hi[idx]   = h0; hi[idx+1] = h1;
    lo[idx]   = l0; lo[idx+1] = l1;
}
static __device__ __forceinline__ void store_split4_f16(u32* hi, u32* lo, int row, int col, float4 xv) {
    u32 idx = row * PADU + (col >> 1);
    u32 h0, l0, h1, l1;
    split_pair_f16(xv.x, xv.y, h0, l0);
    split_pair_f16(xv.z, xv.w, h1, l1);
    hi[idx]   = h0; hi[idx+1] = h1;
    lo[idx]   = l0; lo[idx+1] = l1;
}

// bf16 split weight loader (fc1)
static __device__ __forceinline__ void load_wsplit(u32* hi, u32* lo, const float* __restrict__ w,
                                                   int tid, int nth) {
    for (int idx = tid; idx < HD * HD / 2; idx += nth) {
        int o = idx & 127, k2 = idx >> 7;
        float v0 = w[(2*k2)   * HD + o];
        float v1 = w[(2*k2+1) * HD + o];
        u32 off = o * PADU + k2;
        u32 h, l;
        split_pair(v0, v1, h, l);
        hi[off] = h;
        lo[off] = l;
    }
}
// single-fp16 weight loader (fc2 / lanegemm)
static __device__ __forceinline__ void load_w_f16(u32* dst, const float* __restrict__ w,
                                                  int tid, int nth) {
    for (int idx = tid; idx < HD * HD / 2; idx += nth) {
        int o = idx & 127, k2 = idx >> 7;
        float v0 = w[(2*k2)   * HD + o];
        float v1 = w[(2*k2+1) * HD + o];
        __half2 h = __floats2half2_rn(v0, v1);
        dst[o * PADU + k2] = *reinterpret_cast<u32*>(&h);
    }
}

__global__ void k_init_lanemax() {
    int i = blockIdx.x * blockDim.x + threadIdx.x;
    if (i < NLANES * HD) g_lanemax[i] = 0;
}

#define WSZ 34816

static __device__ __forceinline__ u32 mk_aoff(int wrow, int lane) {
    return (u32)((wrow + (lane & 15)) * ROWB + ((lane >> 4) & 1) * 16);
}
static __device__ __forceinline__ u32 mk_boff(int wcol, int lane) {
    return (u32)((wcol + ((lane >> 4) & 1) * 8 + (lane & 7)) * ROWB + ((lane >> 3) & 1) * 16);
}

// ======================== fc1 (bf16 3-pass; h image stored fp16-split) ========================
__global__ void __launch_bounds__(512, 1) k_fc1(
    const float* __restrict__ x, const int* __restrict__ lane_ids,
    const float* __restrict__ w1a, const float* __restrict__ b1a,
    const float* __restrict__ g1a, const float* __restrict__ be1a,
    const float* __restrict__ w1b, const float* __restrict__ b1b,
    const float* __restrict__ g1b, const float* __restrict__ be1b)
{
    extern __shared__ char sm[];
    u32* WA_HI = (u32*)(sm);            u32* WA_LO = (u32*)(sm + WSZ);
    u32* WB_HI = (u32*)(sm + 2*WSZ);    u32* WB_LO = (u32*)(sm + 3*WSZ);
    u32* A_HI  = (u32*)(sm + 4*WSZ);    u32* A_LO  = (u32*)(sm + 5*WSZ);
    float* P   = (float*)(sm + 6*WSZ);
    float* RS0 = (float*)(sm + 6*WSZ + 3072);
    float* RQ0 = (float*)(sm + 6*WSZ + 5120);
    float* RS1 = (float*)(sm + 6*WSZ + 7168);
    float* RQ1 = (float*)(sm + 6*WSZ + 9216);

    const int tid = threadIdx.x, w = tid >> 5, lane = tid & 31;
    const int lr = lane >> 2, lc = lane & 3;
    const int wrow = (w & 3) * 32, wcol = (w >> 2) * 32, cw = w >> 2;
    const u32 aoff = mk_aoff(wrow, lane), boff = mk_boff(wcol, lane);
    const u32 sAH = smem_u32(A_HI), sAL = smem_u32(A_LO);
    const u32 sWAH = smem_u32(WA_HI), sWAL = smem_u32(WA_LO);
    const u32 sWBH = smem_u32(WB_HI), sWBL = smem_u32(WB_LO);

    load_wsplit(WA_HI, WA_LO, w1a, tid, 512);
    load_wsplit(WB_HI, WB_LO, w1b, tid, 512);
    for (int i = tid; i < HD; i += 512) {
        P[i] = b1a[i]; P[128+i] = g1a[i]; P[256+i] = be1a[i];
        P[384+i] = b1b[i]; P[512+i] = g1b[i]; P[640+i] = be1b[i];
    }
    {
        int grow = blockIdx.x * TM + (tid >> 2);
        if (grow < NROWS) PREF_L2((const char*)x + (size_t)blockIdx.x * TM * HD * 4 + tid * 128);
    }
    __syncthreads();

    for (int t = blockIdx.x; t < NT; t += gridDim.x) {
        int r0 = t * TM;
        #pragma unroll
        for (int j = 0; j < 8; ++j) {
            int idx = tid + j * 512; int xr = idx >> 5; int cg = idx & 31;
            int grow = r0 + xr; if (grow >= NROWS) grow = NROWS - 1;
            float4 xv = __ldg(((const float4*)x) + ((size_t)grow * 32 + cg));
            store_split4(A_HI, A_LO, xr, cg * 4, xv);
        }
        {
            int tn = t + gridDim.x; if (tn >= NT) tn = t;
            int grow = tn * TM + (tid >> 2);
            if (grow < NROWS) PREF_L2((const char*)x + (size_t)tn * TM * HD * 4 + tid * 128);
        }
        __syncthreads();

        float acc[8][4];
        #pragma unroll
        for (int i = 0; i < 8; ++i) { acc[i][0]=acc[i][1]=acc[i][2]=acc[i][3]=0.f; }
        gemm_merged(sAH, sAL, sWAH, sWAL, aoff, boff, acc);
        ln_tile<true, true>(acc, wrow, wcol, lr, lc, cw, P, P+128, P+256, RS0, RQ0);
        store_acc_split(acc, A_HI, A_LO, wrow, wcol, lr, lc);
        __syncthreads();

        #pragma unroll
        for (int i = 0; i < 8; ++i) { acc[i][0]=acc[i][1]=acc[i][2]=acc[i][3]=0.f; }
        gemm_merged(sAH, sAL, sWBH, sWBL, aoff, boff, acc);
        ln_tile<true, true>(acc, wrow, wcol, lr, lc, cw, P+384, P+512, P+640, RS1, RQ1);

        // scatter-max (predicated: relu zeros are no-ops vs init 0)
        #pragma unroll
        for (int rt = 0; rt < 2; ++rt)
        #pragma unroll
        for (int hh = 0; hh < 2; ++hh) {
            int row = wrow + rt*16 + hh*8 + lr;
            int grow = r0 + row; if (grow >= NROWS) grow = NROWS - 1;
            int ln = __ldg(lane_ids + grow);
            int* bp = g_lanemax + ln * HD;
            #pragma unroll
            for (int nt = 0; nt < 4; ++nt) {
                int c = wcol + nt*8 + lc*2;
                float v0 = acc[rt*4+nt][hh*2+0], v1 = acc[rt*4+nt][hh*2+1];
                if (v0 > 0.f) atomicMax(bp + c,     __float_as_int(v0));
                if (v1 > 0.f) atomicMax(bp + c + 1, __float_as_int(v1));
            }
        }
        store_acc_split_f16(acc, A_HI, A_LO, wrow, wcol, lr, lc);   // h image is fp16-split
        __syncthreads();

        const uint4* s4 = (const uint4*)A_HI;
        uint4* d4 = g_h + (size_t)t * TILEU4;
        for (int i = tid; i < TILEU4; i += 512) d4[i] = s4[i];
        __syncthreads();
    }
}

// ======================== k_lanegemm: Z = lane_max @ w2a_bot + b2a (fp16 2-pass) ========================
__global__ void __launch_bounds__(512, 1) k_lanegemm(
    const float* __restrict__ w2a_bot, const float* __restrict__ b2a)
{
    extern __shared__ char sm[];
    u32* W    = (u32*)(sm);
    u32* A_HI = (u32*)(sm + WSZ);
    u32* A_LO = (u32*)(sm + 2*WSZ);
    float* P  = (float*)(sm + 3*WSZ);   // b2a

    const int tid = threadIdx.x, w = tid >> 5, lane = tid & 31;
    const int lr = lane >> 2, lc = lane & 3;
    const int wrow = (w & 3) * 32, wcol = (w >> 2) * 32;
    const u32 aoff = mk_aoff(wrow, lane), boff = mk_boff(wcol, lane);
    const u32 sAH = smem_u32(A_HI), sAL = smem_u32(A_LO);
    const u32 sW  = smem_u32(W);

    load_w_f16(W, w2a_bot, tid, 512);
    for (int i = tid; i < HD; i += 512) P[i] = b2a[i];
    __syncthreads();

    for (int t = blockIdx.x; t < NLT; t += gridDim.x) {
        int l0 = t * 128;
        #pragma unroll
        for (int j = 0; j < 8; ++j) {
            int idx = tid + j * 512; int xr = idx >> 5; int cg = idx & 31;
            int l = l0 + xr; if (l >= NLANES) l = NLANES - 1;
            int4 gv = __ldg(((const int4*)(g_lanemax)) + ((size_t)l * 32 + cg));
            store_split4_f16(A_HI, A_LO, xr, cg * 4,
                make_float4(__int_as_float(gv.x), __int_as_float(gv.y),
                            __int_as_float(gv.z), __int_as_float(gv.w)));
        }
        __syncthreads();

        float acc[8][4];
        #pragma unroll
        for (int i = 0; i < 8; ++i) { acc[i][0]=acc[i][1]=acc[i][2]=acc[i][3]=0.f; }
        gemm_f16_2p(sAH, sAL, sW, aoff, boff, acc);

        #pragma unroll
        for (int rt = 0; rt < 2; ++rt)
        #pragma unroll
        for (int hh = 0; hh < 2; ++hh) {
            int row = wrow + rt*16 + hh*8 + lr;
            int l = l0 + row;
            if (l < NLANES) {
                #pragma unroll
                for (int nt = 0; nt < 4; ++nt) {
                    int c = wcol + nt*8 + lc*2;
                    *(float2*)(g_z + (size_t)l * HD + c) =
                        make_float2(acc[rt*4+nt][hh*2+0] + P[c],
                                    acc[rt*4+nt][hh*2+1] + P[c+1]);
                }
            }
        }
        __syncthreads();
    }
}

// ======================== fused fc2 (fp16 2-pass, double-buffered A) ========================
// smem: WA 0 | WB WSZ | A0_HI 2WSZ | A0_LO 3WSZ | A1_HI 4WSZ | A1_LO 5WSZ
//       P 6WSZ (3584B) | RS0 +3584 | RQ0 +5632 | RS1 +7680 | RQ1 +9728
__global__ void __launch_bounds__(512, 1) k_fc2(
    const float* __restrict__ x, const int* __restrict__ lane_ids,
    const float* __restrict__ w2a_top,
    const float* __restrict__ g2a, const float* __restrict__ be2a,
    const float* __restrict__ w2b, const float* __restrict__ b2b,
    const float* __restrict__ g2b, const float* __restrict__ be2b,
    const float* __restrict__ gn, const float* __restrict__ bn,
    float* __restrict__ out)
{
    extern __shared__ char sm[];
    u32* WA = (u32*)(sm);
    u32* WB = (u32*)(sm + WSZ);
    float* P   = (float*)(sm + 6*WSZ);
    float* RS0 = (float*)(sm + 6*WSZ + 3584);
    float* RQ0 = (float*)(sm + 6*WSZ + 5632);
    float* RS1 = (float*)(sm + 6*WSZ + 7680);
    float* RQ1 = (float*)(sm + 6*WSZ + 9728);

    const int tid = threadIdx.x, w = tid >> 5, lane = tid & 31;
    const int lr = lane >> 2, lc = lane & 3;
    const int wrow = (w & 3) * 32, wcol = (w >> 2) * 32, cw = w >> 2;
    const u32 aoff = mk_aoff(wrow, lane), boff = mk_boff(wcol, lane);
    const u32 sWA = smem_u32(WA), sWB = smem_u32(WB);
    const u32 sA0 = smem_u32(sm + 2*WSZ), sA1 = smem_u32(sm + 4*WSZ);

    // prologue: issue first h-image load FIRST (overlaps weight loads)
    {
        const uint4* s4 = g_h + (size_t)blockIdx.x * TILEU4;
        #pragma unroll
        for (int j = 0; j < 9; ++j) {
            int i = tid + j * 512;
            if (i < TILEU4) CP16(sA0 + (u32)i * 16, s4 + i);
        }
        CP_COMMIT();
    }
    load_w_f16(WA, w2a_top, tid, 512);
    load_w_f16(WB, w2b,     tid, 512);
    for (int i = tid; i < HD; i += 512) {
        P[i]       = g2a[i]; P[128+i] = be2a[i];
        P[256+i]   = b2b[i]; P[384+i] = g2b[i]; P[512+i] = be2b[i];
        P[640+i]   = gn[i];  P[768+i] = bn[i];
    }
    {
        int grow = blockIdx.x * TM + (tid >> 2);
        if (grow < NROWS) PREF_L2((const char*)x + (size_t)blockIdx.x * TM * HD * 4 + tid * 128);
    }
    __syncthreads();

    int buf = 0;
    for (int t = blockIdx.x; t < NT; t += gridDim.x, buf ^= 1) {
        int r0 = t * TM;
        int tn = t + gridDim.x; if (tn >= NT) tn = t;
        const u32 sA  = buf ? sA1 : sA0;
        const u32 sAn = buf ? sA0 : sA1;

        CP_WAIT0();                       // current h image resident
        __syncthreads();

        // issue NEXT tile's h image into the other buffer NOW — overlaps both GEMMs
        {
            const uint4* s4 = g_h + (size_t)tn * TILEU4;
            #pragma unroll
            for (int j = 0; j < 9; ++j) {
                int i = tid + j * 512;
                if (i < TILEU4) CP16(sAn + (u32)i * 16, s4 + i);
            }
            CP_COMMIT();
            int grow = tn * TM + (tid >> 2);
            if (grow < NROWS) PREF_L2((const char*)x + (size_t)tn * TM * HD * 4 + tid * 128);
        }
        // prefetch this tile's Z rows into L2
        {
            int grow = r0 + (tid >> 2); if (grow >= NROWS) grow = NROWS - 1;
            int lnid = __ldg(lane_ids + grow);
            PREF_L2(g_z + (size_t)lnid * HD + (tid & 3) * 32);
        }

        float acc[8][4];
        #pragma unroll
        for (int i = 0; i < 8; ++i) { acc[i][0]=acc[i][1]=acc[i][2]=acc[i][3]=0.f; }
        gemm_f16_2p(sA, sA + WSZ, sWA, aoff, boff, acc);

        // add Z[lane] (fp32, b2a folded in)
        #pragma unroll
        for (int rt = 0; rt < 2; ++rt)
        #pragma unroll
        for (int hh = 0; hh < 2; ++hh) {
            int row = wrow + rt*16 + hh*8 + lr;
            int grow = r0 + row; if (grow >= NROWS) grow = NROWS - 1;
            int lnid = __ldg(lane_ids + grow);
            const float* zr = g_z + (size_t)lnid * HD;
            #pragma unroll
            for (int nt = 0; nt < 4; ++nt) {
                int c = wcol + nt*8 + lc*2;
                float2 zv = __ldg((const float2*)(zr + c));
                acc[rt*4+nt][hh*2+0] += zv.x;
                acc[rt*4+nt][hh*2+1] += zv.y;
            }
        }
        // LN1 + ReLU (set0; its barrier also guarantees all GEMM1 A-reads done)
        ln_tile<false, true>(acc, wrow, wcol, lr, lc, cw, P, P, P+128, RS0, RQ0);

        // store f into current A (in place; safe per LN1 barrier)
        {
            u32* hi = (u32*)(sm + (buf ? 4*WSZ : 2*WSZ));
            u32* lo = (u32*)(sm + (buf ? 5*WSZ : 3*WSZ));
            store_acc_split_f16(acc, hi, lo, wrow, wcol, lr, lc);
        }
        __syncthreads();

        // GEMM2: f @ w2b
        #pragma unroll
        for (int i = 0; i < 8; ++i) { acc[i][0]=acc[i][1]=acc[i][2]=acc[i][3]=0.f; }
        gemm_f16_2p(sA, sA + WSZ, sWB, aoff, boff, acc);

        // LN2 + ReLU (set1; barrier also covers GEMM2 A-read completion before next-iter reuse)
        ln_tile<true, true>(acc, wrow, wcol, lr, lc, cw, P+256, P+384, P+512, RS1, RQ1);

        // residual add from x (L2-hot)
        #pragma unroll
        for (int rt = 0; rt < 2; ++rt)
        #pragma unroll
        for (int hh = 0; hh < 2; ++hh) {
            int row = wrow + rt*16 + hh*8 + lr;
            int grow = r0 + row; if (grow >= NROWS) grow = NROWS - 1;
            #pragma unroll
            for (int nt = 0; nt < 4; ++nt) {
                int c = wcol + nt*8 + lc*2;
                float2 xv = __ldg((const float2*)(x + (size_t)grow * HD + c));
                acc[rt*4+nt][hh*2+0] += xv.x;
                acc[rt*4+nt][hh*2+1] += xv.y;
            }
        }
        // final LN (set0 — safe: last set0 read was LN1, separated by f-store barrier)
        ln_tile<false, false>(acc, wrow, wcol, lr, lc, cw, P, P+640, P+768, RS0, RQ0);

        // write out straight from registers
        #pragma unroll
        for (int rt = 0; rt < 2; ++rt)
        #pragma unroll
        for (int hh = 0; hh < 2; ++hh) {
            int row = wrow + rt*16 + hh*8 + lr;
            int grow = r0 + row;
            if (grow < NROWS) {
                #pragma unroll
                for (int nt = 0; nt < 4; ++nt) {
                    int c = wcol + nt*8 + lc*2;
                    *(float2*)(out + (size_t)grow * HD + c) =
                        make_float2(acc[rt*4+nt][hh*2+0], acc[rt*4+nt][hh*2+1]);
                }
            }
        }
        // loop-top CP_WAIT0 + __syncthreads gates buffer & RS reuse
    }
}

// ---------------- launcher ----------------
extern "C" void kernel_launch(void* const* d_in, const int* in_sizes, int n_in,
                              void* d_out, int out_size) {
    (void)in_sizes; (void)n_in; (void)out_size;
    const float* x        = (const float*)d_in[0];
    const int*   lane_ids = (const int*)  d_in[1];
    const float* w1a  = (const float*)d_in[2];
    const float* b1a  = (const float*)d_in[3];
    const float* g1a  = (const float*)d_in[4];
    const float* be1a = (const float*)d_in[5];
    const float* w1b  = (const float*)d_in[6];
    const float* b1b  = (const float*)d_in[7];
    const float* g1b  = (const float*)d_in[8];
    const float* be1b = (const float*)d_in[9];
    const float* w2a  = (const float*)d_in[10];
    const float* b2a  = (const float*)d_in[11];
    const float* g2a  = (const float*)d_in[12];
    const float* be2a = (const float*)d_in[13];
    const float* w2b  = (const float*)d_in[14];
    const float* b2b  = (const float*)d_in[15];
    const float* g2b  = (const float*)d_in[16];
    const float* be2b = (const float*)d_in[17];
    const float* gn   = (const float*)d_in[18];
    const float* bn   = (const float*)d_in[19];
    float* out = (float*)d_out;

    const int SM1  = 6*WSZ + 3072 + 8192;   // 220160
    const int SMLG = 3*WSZ + 1024;          // 105472
    const int SM2  = 6*WSZ + 3584 + 8192;   // 220672
    cudaFuncSetAttribute(k_fc1,      cudaFuncAttributeMaxDynamicSharedMemorySize, SM1);
    cudaFuncSetAttribute(k_lanegemm, cudaFuncAttributeMaxDynamicSharedMemorySize, SMLG);
    cudaFuncSetAttribute(k_fc2,      cudaFuncAttributeMaxDynamicSharedMemorySize, SM2);

    k_init_lanemax<<<(NLANES * HD + 511) / 512, 512>>>();
    k_fc1     <<<148, 512, SM1>>> (x, lane_ids, w1a, b1a, g1a, be1a, w1b, b1b, g1b, be1b);
    k_lanegemm<<<148, 512, SMLG>>>(w2a + 128 * HD, b2a);
    k_fc2     <<<148, 512, SM2>>> (x, lane_ids, w2a, g2a, be2a, w2b, b2b, g2b, be2b, gn, bn, out);
}

// round 12
// speedup vs baseline: 2.3793x; 1.0959x over previous
#include <cuda_runtime.h>
#include <cuda_bf16.h>
#include <cuda_fp16.h>
#include <cstdint>

#define NROWS  300000
#define HD     128
#define NLANES 25000
#define LNEPS  1e-5f
#define TM     128
#define NT     ((NROWS + TM - 1) / TM)     // 2344 tiles
#define NLT    ((NLANES + 127) / 128)      // 196 lane tiles
#define PADU   68                           // u32 per 128-b16 row (272B, conflict-free)
#define ROWB   272
#define TILEU4 4352                         // uint4 per split tile image (hi+lo)

typedef unsigned int       u32;
typedef unsigned short     u16;
typedef unsigned long long u64;

// ---------------- device scratch ----------------
__device__ uint4 g_h[(size_t)NT * TILEU4];   // fc1 output image (fp16 split, padded)
__device__ int   g_lanemax[NLANES * HD];     // per-lane max (float bits, relu>=0)
__device__ float g_z[(size_t)NLANES * HD];   // per-lane Z = max @ w2a_bot + b2a

// ---------------- helpers ----------------
static __device__ __forceinline__ u32 smem_u32(const void* p) {
    u32 a;
    asm("{ .reg .u64 t; cvta.to.shared.u64 t, %1; cvt.u32.u64 %0, t; }" : "=r"(a) : "l"(p));
    return a;
}

// fp16 hi/lo split of a pair
static __device__ __forceinline__ void split_pair_f16(float v0, float v1, u32& hi, u32& lo) {
    __half2 h = __floats2half2_rn(v0, v1);
    float h0 = __low2float(h), h1 = __high2float(h);
    __half2 l = __floats2half2_rn(v0 - h0, v1 - h1);
    hi = *reinterpret_cast<u32*>(&h);
    lo = *reinterpret_cast<u32*>(&l);
}

#define CP16(sm_addr, gptr) \
    asm volatile("cp.async.cg.shared.global [%0], [%1], 16;" :: "r"(sm_addr), "l"(gptr))
#define CP_COMMIT() asm volatile("cp.async.commit_group;" ::: "memory")
#define CP_WAIT0()  asm volatile("cp.async.wait_group 0;" ::: "memory")
#define PREF_L2(p)  asm volatile("prefetch.global.L2 [%0];" :: "l"(p))

static __device__ __forceinline__ void ldsm4(u32& r0, u32& r1, u32& r2, u32& r3, u32 addr) {
    asm volatile("ldmatrix.sync.aligned.m8n8.x4.shared.b16 {%0,%1,%2,%3}, [%4];"
        : "=r"(r0), "=r"(r1), "=r"(r2), "=r"(r3) : "r"(addr));
}
static __device__ __forceinline__ void mma_f16(float (&d)[4], const u32 (&a)[4], u32 b0, u32 b1) {
    asm volatile("mma.sync.aligned.m16n8k16.row.col.f32.f16.f16.f32 "
        "{%0,%1,%2,%3}, {%4,%5,%6,%7}, {%8,%9}, {%0,%1,%2,%3};"
        : "+f"(d[0]), "+f"(d[1]), "+f"(d[2]), "+f"(d[3])
        : "r"(a[0]), "r"(a[1]), "r"(a[2]), "r"(a[3]), "r"(b0), "r"(b1));
}

// fp16 2-pass GEMM: acc += Ah*B + Al*B over K=128 (B single fp16).
static __device__ __forceinline__ void gemm_f16_2p(
    u32 Ah, u32 Al, u32 B, u32 aoff, u32 boff, float (&acc)[8][4])
{
    #pragma unroll
    for (int kc = 0; kc < 8; ++kc) {
        const u32 ka = kc * 32;
        u32 ah0[4], ah1[4], al0[4], al1[4], b[8];
        ldsm4(ah0[0], ah0[1], ah0[2], ah0[3], Ah + aoff + ka);
        ldsm4(ah1[0], ah1[1], ah1[2], ah1[3], Ah + aoff + 16 * ROWB + ka);
        ldsm4(al0[0], al0[1], al0[2], al0[3], Al + aoff + ka);
        ldsm4(al1[0], al1[1], al1[2], al1[3], Al + aoff + 16 * ROWB + ka);
        ldsm4(b[0], b[1], b[2], b[3], B + boff + ka);
        ldsm4(b[4], b[5], b[6], b[7], B + boff + 16 * ROWB + ka);
        #pragma unroll
        for (int p = 0; p < 2; ++p)
        #pragma unroll
        for (int j = 0; j < 2; ++j) {
            const int nt = p * 2 + j;
            const u32 b0 = b[p*4 + j*2], b1 = b[p*4 + j*2 + 1];
            mma_f16(acc[nt],     ah0, b0, b1);
            mma_f16(acc[4 + nt], ah1, b0, b1);
            mma_f16(acc[nt],     al0, b0, b1);
            mma_f16(acc[4 + nt], al1, b0, b1);
        }
    }
}

// ---------------- LN epilogue (single barrier; caller alternates RS/RQ sets) ----------------
template<bool HASB, bool RELU>
static __device__ __forceinline__ void ln_tile(
    float (&acc)[8][4], int wrow, int wcol, int lr, int lc, int cw,
    const float* __restrict__ bias, const float* __restrict__ gam,
    const float* __restrict__ bet, float* RS, float* RQ)
{
    float s[4] = {0.f,0.f,0.f,0.f}, q[4] = {0.f,0.f,0.f,0.f};
    #pragma unroll
    for (int rt = 0; rt < 2; ++rt)
    #pragma unroll
    for (int nt = 0; nt < 4; ++nt) {
        float* a = acc[rt * 4 + nt];
        if (HASB) {
            int c = wcol + nt * 8 + lc * 2;
            float bx = bias[c], by = bias[c + 1];
            a[0] += bx; a[1] += by; a[2] += bx; a[3] += by;
        }
        s[rt*2+0] += a[0] + a[1]; q[rt*2+0] += a[0]*a[0] + a[1]*a[1];
        s[rt*2+1] += a[2] + a[3]; q[rt*2+1] += a[2]*a[2] + a[3]*a[3];
    }
    #pragma unroll
    for (int off = 1; off <= 2; off <<= 1)
        #pragma unroll
        for (int i = 0; i < 4; ++i) {
            s[i] += __shfl_xor_sync(0xffffffffu, s[i], off);
            q[i] += __shfl_xor_sync(0xffffffffu, q[i], off);
        }
    if (lc == 0) {
        #pragma unroll
        for (int i = 0; i < 4; ++i) {
            int row = wrow + (i >> 1) * 16 + (i & 1) * 8 + lr;
            RS[cw * 128 + row] = s[i];
            RQ[cw * 128 + row] = q[i];
        }
    }
    __syncthreads();
    float mm[4], rsd[4];
    #pragma unroll
    for (int i = 0; i < 4; ++i) {
        int row = wrow + (i >> 1) * 16 + (i & 1) * 8 + lr;
        float S = RS[row] + RS[128 + row] + RS[256 + row] + RS[384 + row];
        float Q = RQ[row] + RQ[128 + row] + RQ[256 + row] + RQ[384 + row];
        float m = S * (1.f / 128.f);
        mm[i] = m;
        rsd[i] = rsqrtf(Q * (1.f / 128.f) - m * m + LNEPS);
    }
    #pragma unroll
    for (int rt = 0; rt < 2; ++rt)
    #pragma unroll
    for (int nt = 0; nt < 4; ++nt) {
        int c = wcol + nt * 8 + lc * 2;
        float gx = gam[c], gy = gam[c + 1], ex = bet[c], ey = bet[c + 1];
        float* a = acc[rt * 4 + nt];
        int s0 = rt * 2, s1 = rt * 2 + 1;
        a[0] = (a[0] - mm[s0]) * rsd[s0] * gx + ex;
        a[1] = (a[1] - mm[s0]) * rsd[s0] * gy + ey;
        a[2] = (a[2] - mm[s1]) * rsd[s1] * gx + ex;
        a[3] = (a[3] - mm[s1]) * rsd[s1] * gy + ey;
        if (RELU) {
            a[0] = fmaxf(a[0], 0.f); a[1] = fmaxf(a[1], 0.f);
            a[2] = fmaxf(a[2], 0.f); a[3] = fmaxf(a[3], 0.f);
        }
    }
}

// fp16 fragment store
static __device__ __forceinline__ void store_acc_split_f16(
    const float (&acc)[8][4], u32* hi, u32* lo, int wrow, int wcol, int lr, int lc)
{
    #pragma unroll
    for (int rt = 0; rt < 2; ++rt)
    #pragma unroll
    for (int hh = 0; hh < 2; ++hh) {
        int row = wrow + rt * 16 + hh * 8 + lr;
        u32 base = row * PADU + (wcol >> 1) + lc;
        #pragma unroll
        for (int nt = 0; nt < 4; ++nt) {
            u32 h, l;
            split_pair_f16(acc[rt*4+nt][hh*2+0], acc[rt*4+nt][hh*2+1], h, l);
            hi[base + nt*4] = h;
            lo[base + nt*4] = l;
        }
    }
}

static __device__ __forceinline__ void store_split4_f16(u32* hi, u32* lo, int row, int col, float4 xv) {
    u32 idx = row * PADU + (col >> 1);
    u32 h0, l0, h1, l1;
    split_pair_f16(xv.x, xv.y, h0, l0);
    split_pair_f16(xv.z, xv.w, h1, l1);
    hi[idx]   = h0; hi[idx+1] = h1;
    lo[idx]   = l0; lo[idx+1] = l1;
}

// single-fp16 weight loader
static __device__ __forceinline__ void load_w_f16(u32* dst, const float* __restrict__ w,
                                                  int tid, int nth) {
    for (int idx = tid; idx < HD * HD / 2; idx += nth) {
        int o = idx & 127, k2 = idx >> 7;
        float v0 = w[(2*k2)   * HD + o];
        float v1 = w[(2*k2+1) * HD + o];
        __half2 h = __floats2half2_rn(v0, v1);
        dst[o * PADU + k2] = *reinterpret_cast<u32*>(&h);
    }
}

__global__ void k_init_lanemax() {
    int i = blockIdx.x * blockDim.x + threadIdx.x;
    if (i < NLANES * HD) g_lanemax[i] = 0;
}

#define WSZ 34816

static __device__ __forceinline__ u32 mk_aoff(int wrow, int lane) {
    return (u32)((wrow + (lane & 15)) * ROWB + ((lane >> 4) & 1) * 16);
}
static __device__ __forceinline__ u32 mk_boff(int wcol, int lane) {
    return (u32)((wcol + ((lane >> 4) & 1) * 8 + (lane & 7)) * ROWB + ((lane >> 3) & 1) * 16);
}

// ======================== fc1 (fp16 2-pass both GEMMs) ========================
// smem: WA 0 | WB WSZ | A_HI 2WSZ | A_LO 3WSZ
//       P 4WSZ (3072B) | RS0 +3072 | RQ0 +5120 | RS1 +7168 | RQ1 +9216
__global__ void __launch_bounds__(512, 1) k_fc1(
    const float* __restrict__ x, const int* __restrict__ lane_ids,
    const float* __restrict__ w1a, const float* __restrict__ b1a,
    const float* __restrict__ g1a, const float* __restrict__ be1a,
    const float* __restrict__ w1b, const float* __restrict__ b1b,
    const float* __restrict__ g1b, const float* __restrict__ be1b)
{
    extern __shared__ char sm[];
    u32* WA   = (u32*)(sm);
    u32* WB   = (u32*)(sm + WSZ);
    u32* A_HI = (u32*)(sm + 2*WSZ);
    u32* A_LO = (u32*)(sm + 3*WSZ);
    float* P   = (float*)(sm + 4*WSZ);
    float* RS0 = (float*)(sm + 4*WSZ + 3072);
    float* RQ0 = (float*)(sm + 4*WSZ + 5120);
    float* RS1 = (float*)(sm + 4*WSZ + 7168);
    float* RQ1 = (float*)(sm + 4*WSZ + 9216);

    const int tid = threadIdx.x, w = tid >> 5, lane = tid & 31;
    const int lr = lane >> 2, lc = lane & 3;
    const int wrow = (w & 3) * 32, wcol = (w >> 2) * 32, cw = w >> 2;
    const u32 aoff = mk_aoff(wrow, lane), boff = mk_boff(wcol, lane);
    const u32 sAH = smem_u32(A_HI), sAL = smem_u32(A_LO);
    const u32 sWA = smem_u32(WA), sWB = smem_u32(WB);

    load_w_f16(WA, w1a, tid, 512);
    load_w_f16(WB, w1b, tid, 512);
    for (int i = tid; i < HD; i += 512) {
        P[i] = b1a[i]; P[128+i] = g1a[i]; P[256+i] = be1a[i];
        P[384+i] = b1b[i]; P[512+i] = g1b[i]; P[640+i] = be1b[i];
    }
    {
        int grow = blockIdx.x * TM + (tid >> 2);
        if (grow < NROWS) PREF_L2((const char*)x + (size_t)blockIdx.x * TM * HD * 4 + tid * 128);
    }
    __syncthreads();

    for (int t = blockIdx.x; t < NT; t += gridDim.x) {
        int r0 = t * TM;
        #pragma unroll
        for (int j = 0; j < 8; ++j) {
            int idx = tid + j * 512; int xr = idx >> 5; int cg = idx & 31;
            int grow = r0 + xr; if (grow >= NROWS) grow = NROWS - 1;
            float4 xv = __ldg(((const float4*)x) + ((size_t)grow * 32 + cg));
            store_split4_f16(A_HI, A_LO, xr, cg * 4, xv);
        }
        {
            int tn = t + gridDim.x; if (tn >= NT) tn = t;
            int grow = tn * TM + (tid >> 2);
            if (grow < NROWS) PREF_L2((const char*)x + (size_t)tn * TM * HD * 4 + tid * 128);
        }
        __syncthreads();

        float acc[8][4];
        #pragma unroll
        for (int i = 0; i < 8; ++i) { acc[i][0]=acc[i][1]=acc[i][2]=acc[i][3]=0.f; }
        gemm_f16_2p(sAH, sAL, sWA, aoff, boff, acc);
        ln_tile<true, true>(acc, wrow, wcol, lr, lc, cw, P, P+128, P+256, RS0, RQ0);
        store_acc_split_f16(acc, A_HI, A_LO, wrow, wcol, lr, lc);
        __syncthreads();

        #pragma unroll
        for (int i = 0; i < 8; ++i) { acc[i][0]=acc[i][1]=acc[i][2]=acc[i][3]=0.f; }
        gemm_f16_2p(sAH, sAL, sWB, aoff, boff, acc);
        ln_tile<true, true>(acc, wrow, wcol, lr, lc, cw, P+384, P+512, P+640, RS1, RQ1);

        // scatter-max (predicated: relu zeros are no-ops vs init 0)
        #pragma unroll
        for (int rt = 0; rt < 2; ++rt)
        #pragma unroll
        for (int hh = 0; hh < 2; ++hh) {
            int row = wrow + rt*16 + hh*8 + lr;
            int grow = r0 + row; if (grow >= NROWS) grow = NROWS - 1;
            int ln = __ldg(lane_ids + grow);
            int* bp = g_lanemax + ln * HD;
            #pragma unroll
            for (int nt = 0; nt < 4; ++nt) {
                int c = wcol + nt*8 + lc*2;
                float v0 = acc[rt*4+nt][hh*2+0], v1 = acc[rt*4+nt][hh*2+1];
                if (v0 > 0.f) atomicMax(bp + c,     __float_as_int(v0));
                if (v1 > 0.f) atomicMax(bp + c + 1, __float_as_int(v1));
            }
        }
        store_acc_split_f16(acc, A_HI, A_LO, wrow, wcol, lr, lc);   // h image (fp16 split)
        __syncthreads();

        const uint4* s4 = (const uint4*)A_HI;
        uint4* d4 = g_h + (size_t)t * TILEU4;
        for (int i = tid; i < TILEU4; i += 512) d4[i] = s4[i];
        __syncthreads();
    }
}

// ======================== k_lanegemm: Z = lane_max @ w2a_bot + b2a (fp16 2-pass) ========================
__global__ void __launch_bounds__(512, 1) k_lanegemm(
    const float* __restrict__ w2a_bot, const float* __restrict__ b2a)
{
    extern __shared__ char sm[];
    u32* W    = (u32*)(sm);
    u32* A_HI = (u32*)(sm + WSZ);
    u32* A_LO = (u32*)(sm + 2*WSZ);
    float* P  = (float*)(sm + 3*WSZ);   // b2a

    const int tid = threadIdx.x, w = tid >> 5, lane = tid & 31;
    const int lr = lane >> 2, lc = lane & 3;
    const int wrow = (w & 3) * 32, wcol = (w >> 2) * 32;
    const u32 aoff = mk_aoff(wrow, lane), boff = mk_boff(wcol, lane);
    const u32 sAH = smem_u32(A_HI), sAL = smem_u32(A_LO);
    const u32 sW  = smem_u32(W);

    load_w_f16(W, w2a_bot, tid, 512);
    for (int i = tid; i < HD; i += 512) P[i] = b2a[i];
    __syncthreads();

    for (int t = blockIdx.x; t < NLT; t += gridDim.x) {
        int l0 = t * 128;
        #pragma unroll
        for (int j = 0; j < 8; ++j) {
            int idx = tid + j * 512; int xr = idx >> 5; int cg = idx & 31;
            int l = l0 + xr; if (l >= NLANES) l = NLANES - 1;
            int4 gv = __ldg(((const int4*)(g_lanemax)) + ((size_t)l * 32 + cg));
            store_split4_f16(A_HI, A_LO, xr, cg * 4,
                make_float4(__int_as_float(gv.x), __int_as_float(gv.y),
                            __int_as_float(gv.z), __int_as_float(gv.w)));
        }
        __syncthreads();

        float acc[8][4];
        #pragma unroll
        for (int i = 0; i < 8; ++i) { acc[i][0]=acc[i][1]=acc[i][2]=acc[i][3]=0.f; }
        gemm_f16_2p(sAH, sAL, sW, aoff, boff, acc);

        #pragma unroll
        for (int rt = 0; rt < 2; ++rt)
        #pragma unroll
        for (int hh = 0; hh < 2; ++hh) {
            int row = wrow + rt*16 + hh*8 + lr;
            int l = l0 + row;
            if (l < NLANES) {
                #pragma unroll
                for (int nt = 0; nt < 4; ++nt) {
                    int c = wcol + nt*8 + lc*2;
                    *(float2*)(g_z + (size_t)l * HD + c) =
                        make_float2(acc[rt*4+nt][hh*2+0] + P[c],
                                    acc[rt*4+nt][hh*2+1] + P[c+1]);
                }
            }
        }
        __syncthreads();
    }
}

// ======================== fused fc2 (fp16 2-pass, double-buffered A) ========================
// smem: WA 0 | WB WSZ | A0_HI 2WSZ | A0_LO 3WSZ | A1_HI 4WSZ | A1_LO 5WSZ
//       P 6WSZ (3584B) | RS0 +3584 | RQ0 +5632 | RS1 +7680 | RQ1 +9728
__global__ void __launch_bounds__(512, 1) k_fc2(
    const float* __restrict__ x, const int* __restrict__ lane_ids,
    const float* __restrict__ w2a_top,
    const float* __restrict__ g2a, const float* __restrict__ be2a,
    const float* __restrict__ w2b, const float* __restrict__ b2b,
    const float* __restrict__ g2b, const float* __restrict__ be2b,
    const float* __restrict__ gn, const float* __restrict__ bn,
    float* __restrict__ out)
{
    extern __shared__ char sm[];
    u32* WA = (u32*)(sm);
    u32* WB = (u32*)(sm + WSZ);
    float* P   = (float*)(sm + 6*WSZ);
    float* RS0 = (float*)(sm + 6*WSZ + 3584);
    float* RQ0 = (float*)(sm + 6*WSZ + 5632);
    float* RS1 = (float*)(sm + 6*WSZ + 7680);
    float* RQ1 = (float*)(sm + 6*WSZ + 9728);

    const int tid = threadIdx.x, w = tid >> 5, lane = tid & 31;
    const int lr = lane >> 2, lc = lane & 3;
    const int wrow = (w & 3) * 32, wcol = (w >> 2) * 32, cw = w >> 2;
    const u32 aoff = mk_aoff(wrow, lane), boff = mk_boff(wcol, lane);
    const u32 sWA = smem_u32(WA), sWB = smem_u32(WB);
    const u32 sA0 = smem_u32(sm + 2*WSZ), sA1 = smem_u32(sm + 4*WSZ);

    // prologue: issue first h-image load FIRST (overlaps weight loads)
    {
        const uint4* s4 = g_h + (size_t)blockIdx.x * TILEU4;
        #pragma unroll
        for (int j = 0; j < 9; ++j) {
            int i = tid + j * 512;
            if (i < TILEU4) CP16(sA0 + (u32)i * 16, s4 + i);
        }
        CP_COMMIT();
    }
    load_w_f16(WA, w2a_top, tid, 512);
    load_w_f16(WB, w2b,     tid, 512);
    for (int i = tid; i < HD; i += 512) {
        P[i]       = g2a[i]; P[128+i] = be2a[i];
        P[256+i]   = b2b[i]; P[384+i] = g2b[i]; P[512+i] = be2b[i];
        P[640+i]   = gn[i];  P[768+i] = bn[i];
    }
    {
        int grow = blockIdx.x * TM + (tid >> 2);
        if (grow < NROWS) PREF_L2((const char*)x + (size_t)blockIdx.x * TM * HD * 4 + tid * 128);
    }
    __syncthreads();

    int buf = 0;
    for (int t = blockIdx.x; t < NT; t += gridDim.x, buf ^= 1) {
        int r0 = t * TM;
        int tn = t + gridDim.x; if (tn >= NT) tn = t;
        const u32 sA  = buf ? sA1 : sA0;
        const u32 sAn = buf ? sA0 : sA1;

        CP_WAIT0();                       // current h image resident
        __syncthreads();

        // issue NEXT tile's h image into the other buffer NOW — overlaps both GEMMs
        {
            const uint4* s4 = g_h + (size_t)tn * TILEU4;
            #pragma unroll
            for (int j = 0; j < 9; ++j) {
                int i = tid + j * 512;
                if (i < TILEU4) CP16(sAn + (u32)i * 16, s4 + i);
            }
            CP_COMMIT();
            int grow = tn * TM + (tid >> 2);
            if (grow < NROWS) PREF_L2((const char*)x + (size_t)tn * TM * HD * 4 + tid * 128);
        }
        // prefetch this tile's Z rows into L2
        {
            int grow = r0 + (tid >> 2); if (grow >= NROWS) grow = NROWS - 1;
            int lnid = __ldg(lane_ids + grow);
            PREF_L2(g_z + (size_t)lnid * HD + (tid & 3) * 32);
        }

        float acc[8][4];
        #pragma unroll
        for (int i = 0; i < 8; ++i) { acc[i][0]=acc[i][1]=acc[i][2]=acc[i][3]=0.f; }
        gemm_f16_2p(sA, sA + WSZ, sWA, aoff, boff, acc);

        // add Z[lane] (fp32, b2a folded in)
        #pragma unroll
        for (int rt = 0; rt < 2; ++rt)
        #pragma unroll
        for (int hh = 0; hh < 2; ++hh) {
            int row = wrow + rt*16 + hh*8 + lr;
            int grow = r0 + row; if (grow >= NROWS) grow = NROWS - 1;
            int lnid = __ldg(lane_ids + grow);
            const float* zr = g_z + (size_t)lnid * HD;
            #pragma unroll
            for (int nt = 0; nt < 4; ++nt) {
                int c = wcol + nt*8 + lc*2;
                float2 zv = __ldg((const float2*)(zr + c));
                acc[rt*4+nt][hh*2+0] += zv.x;
                acc[rt*4+nt][hh*2+1] += zv.y;
            }
        }
        // LN1 + ReLU (set0; its barrier also guarantees all GEMM1 A-reads done)
        ln_tile<false, true>(acc, wrow, wcol, lr, lc, cw, P, P, P+128, RS0, RQ0);

        // store f into current A (in place; safe per LN1 barrier)
        {
            u32* hi = (u32*)(sm + (buf ? 4*WSZ : 2*WSZ));
            u32* lo = (u32*)(sm + (buf ? 5*WSZ : 3*WSZ));
            store_acc_split_f16(acc, hi, lo, wrow, wcol, lr, lc);
        }
        __syncthreads();

        // GEMM2: f @ w2b
        #pragma unroll
        for (int i = 0; i < 8; ++i) { acc[i][0]=acc[i][1]=acc[i][2]=acc[i][3]=0.f; }
        gemm_f16_2p(sA, sA + WSZ, sWB, aoff, boff, acc);

        // LN2 + ReLU (set1; barrier also covers GEMM2 A-read completion before next-iter reuse)
        ln_tile<true, true>(acc, wrow, wcol, lr, lc, cw, P+256, P+384, P+512, RS1, RQ1);

        // residual add from x (L2-hot)
        #pragma unroll
        for (int rt = 0; rt < 2; ++rt)
        #pragma unroll
        for (int hh = 0; hh < 2; ++hh) {
            int row = wrow + rt*16 + hh*8 + lr;
            int grow = r0 + row; if (grow >= NROWS) grow = NROWS - 1;
            #pragma unroll
            for (int nt = 0; nt < 4; ++nt) {
                int c = wcol + nt*8 + lc*2;
                float2 xv = __ldg((const float2*)(x + (size_t)grow * HD + c));
                acc[rt*4+nt][hh*2+0] += xv.x;
                acc[rt*4+nt][hh*2+1] += xv.y;
            }
        }
        // final LN (set0 — safe: last set0 read was LN1, separated by f-store barrier)
        ln_tile<false, false>(acc, wrow, wcol, lr, lc, cw, P, P+640, P+768, RS0, RQ0);

        // write out straight from registers
        #pragma unroll
        for (int rt = 0; rt < 2; ++rt)
        #pragma unroll
        for (int hh = 0; hh < 2; ++hh) {
            int row = wrow + rt*16 + hh*8 + lr;
            int grow = r0 + row;
            if (grow < NROWS) {
                #pragma unroll
                for (int nt = 0; nt < 4; ++nt) {
                    int c = wcol + nt*8 + lc*2;
                    *(float2*)(out + (size_t)grow * HD + c) =
                        make_float2(acc[rt*4+nt][hh*2+0], acc[rt*4+nt][hh*2+1]);
                }
            }
        }
        // loop-top CP_WAIT0 + __syncthreads gates buffer & RS reuse
    }
}

// ---------------- launcher ----------------
extern "C" void kernel_launch(void* const* d_in, const int* in_sizes, int n_in,
                              void* d_out, int out_size) {
    (void)in_sizes; (void)n_in; (void)out_size;
    const float* x        = (const float*)d_in[0];
    const int*   lane_ids = (const int*)  d_in[1];
    const float* w1a  = (const float*)d_in[2];
    const float* b1a  = (const float*)d_in[3];
    const float* g1a  = (const float*)d_in[4];
    const float* be1a = (const float*)d_in[5];
    const float* w1b  = (const float*)d_in[6];
    const float* b1b  = (const float*)d_in[7];
    const float* g1b  = (const float*)d_in[8];
    const float* be1b = (const float*)d_in[9];
    const float* w2a  = (const float*)d_in[10];
    const float* b2a  = (const float*)d_in[11];
    const float* g2a  = (const float*)d_in[12];
    const float* be2a = (const float*)d_in[13];
    const float* w2b  = (const float*)d_in[14];
    const float* b2b  = (const float*)d_in[15];
    const float* g2b  = (const float*)d_in[16];
    const float* be2b = (const float*)d_in[17];
    const float* gn   = (const float*)d_in[18];
    const float* bn   = (const float*)d_in[19];
    float* out = (float*)d_out;

    const int SM1  = 4*WSZ + 3072 + 8192;   // 150528
    const int SMLG = 3*WSZ + 1024;          // 105472
    const int SM2  = 6*WSZ + 3584 + 8192;   // 220672
    cudaFuncSetAttribute(k_fc1,      cudaFuncAttributeMaxDynamicSharedMemorySize, SM1);
    cudaFuncSetAttribute(k_lanegemm, cudaFuncAttributeMaxDynamicSharedMemorySize, SMLG);
    cudaFuncSetAttribute(k_fc2,      cudaFuncAttributeMaxDynamicSharedMemorySize, SM2);

    k_init_lanemax<<<(NLANES * HD + 511) / 512, 512>>>();
    k_fc1     <<<148, 512, SM1>>> (x, lane_ids, w1a, b1a, g1a, be1a, w1b, b1b, g1b, be1b);
    k_lanegemm<<<148, 512, SMLG>>>(w2a + 128 * HD, b2a);
    k_fc2     <<<148, 512, SM2>>> (x, lane_ids, w2a, g2a, be2a, w2b, b2b, g2b, be2b, gn, bn, out);
}

// round 13
// speedup vs baseline: 2.6468x; 1.1124x over previous
#include <cuda_runtime.h>
#include <cuda_bf16.h>
#include <cuda_fp16.h>
#include <cstdint>

#define NROWS  300000
#define HD     128
#define NLANES 25000
#define LNEPS  1e-5f
#define TM64   64
#define NT64   ((NROWS + TM64 - 1) / TM64)  // 4688 tiles (64-row)
#define NLT    ((NLANES + 127) / 128)       // 196 lane tiles
#define PADU   68                            // u32 per 128-b16 row (272B, conflict-free)
#define ROWB   272
#define TU64   2176                          // uint4 per 64-row split tile image (hi+lo)

typedef unsigned int       u32;
typedef unsigned short     u16;
typedef unsigned long long u64;

// ---------------- device scratch ----------------
__device__ uint4 g_h[(size_t)NT64 * TU64];   // fc1 output image (fp16 split, 64-row tiles)
__device__ int   g_lanemax[NLANES * HD];     // per-lane max (float bits, relu>=0)
__device__ float g_z[(size_t)NLANES * HD];   // per-lane Z = max @ w2a_bot + b2a

// ---------------- helpers ----------------
static __device__ __forceinline__ u32 smem_u32(const void* p) {
    u32 a;
    asm("{ .reg .u64 t; cvta.to.shared.u64 t, %1; cvt.u32.u64 %0, t; }" : "=r"(a) : "l"(p));
    return a;
}

// fp16 hi/lo split of a pair
static __device__ __forceinline__ void split_pair_f16(float v0, float v1, u32& hi, u32& lo) {
    __half2 h = __floats2half2_rn(v0, v1);
    float h0 = __low2float(h), h1 = __high2float(h);
    __half2 l = __floats2half2_rn(v0 - h0, v1 - h1);
    hi = *reinterpret_cast<u32*>(&h);
    lo = *reinterpret_cast<u32*>(&l);
}

#define CP16(sm_addr, gptr) \
    asm volatile("cp.async.cg.shared.global [%0], [%1], 16;" :: "r"(sm_addr), "l"(gptr))
#define CP_COMMIT() asm volatile("cp.async.commit_group;" ::: "memory")
#define CP_WAIT0()  asm volatile("cp.async.wait_group 0;" ::: "memory")
#define PREF_L2(p)  asm volatile("prefetch.global.L2 [%0];" :: "l"(p))

static __device__ __forceinline__ void ldsm4(u32& r0, u32& r1, u32& r2, u32& r3, u32 addr) {
    asm volatile("ldmatrix.sync.aligned.m8n8.x4.shared.b16 {%0,%1,%2,%3}, [%4];"
        : "=r"(r0), "=r"(r1), "=r"(r2), "=r"(r3) : "r"(addr));
}
static __device__ __forceinline__ void mma_f16(float (&d)[4], const u32 (&a)[4], u32 b0, u32 b1) {
    asm volatile("mma.sync.aligned.m16n8k16.row.col.f32.f16.f16.f32 "
        "{%0,%1,%2,%3}, {%4,%5,%6,%7}, {%8,%9}, {%0,%1,%2,%3};"
        : "+f"(d[0]), "+f"(d[1]), "+f"(d[2]), "+f"(d[3])
        : "r"(a[0]), "r"(a[1]), "r"(a[2]), "r"(a[3]), "r"(b0), "r"(b1));
}

// fp16 2-pass GEMM: acc += Ah*B + Al*B over K=128 (B single fp16). Warp covers 32x32.
static __device__ __forceinline__ void gemm_f16_2p(
    u32 Ah, u32 Al, u32 B, u32 aoff, u32 boff, float (&acc)[8][4])
{
    #pragma unroll
    for (int kc = 0; kc < 8; ++kc) {
        const u32 ka = kc * 32;
        u32 ah0[4], ah1[4], al0[4], al1[4], b[8];
        ldsm4(ah0[0], ah0[1], ah0[2], ah0[3], Ah + aoff + ka);
        ldsm4(ah1[0], ah1[1], ah1[2], ah1[3], Ah + aoff + 16 * ROWB + ka);
        ldsm4(al0[0], al0[1], al0[2], al0[3], Al + aoff + ka);
        ldsm4(al1[0], al1[1], al1[2], al1[3], Al + aoff + 16 * ROWB + ka);
        ldsm4(b[0], b[1], b[2], b[3], B + boff + ka);
        ldsm4(b[4], b[5], b[6], b[7], B + boff + 16 * ROWB + ka);
        #pragma unroll
        for (int p = 0; p < 2; ++p)
        #pragma unroll
        for (int j = 0; j < 2; ++j) {
            const int nt = p * 2 + j;
            const u32 b0 = b[p*4 + j*2], b1 = b[p*4 + j*2 + 1];
            mma_f16(acc[nt],     ah0, b0, b1);
            mma_f16(acc[4 + nt], ah1, b0, b1);
            mma_f16(acc[nt],     al0, b0, b1);
            mma_f16(acc[4 + nt], al1, b0, b1);
        }
    }
}

// ---------------- LN epilogue for 64-row tiles (single barrier; ping-pong RS/RQ) ----------------
// 8 warps: wrow in {0,32}, cw = wcol/32 in 0..3. RS/RQ: [4][64].
template<bool HASB, bool RELU>
static __device__ __forceinline__ void ln_tile64(
    float (&acc)[8][4], int wrow, int wcol, int lr, int lc, int cw,
    const float* __restrict__ bias, const float* __restrict__ gam,
    const float* __restrict__ bet, float* RS, float* RQ)
{
    float s[4] = {0.f,0.f,0.f,0.f}, q[4] = {0.f,0.f,0.f,0.f};
    #pragma unroll
    for (int rt = 0; rt < 2; ++rt)
    #pragma unroll
    for (int nt = 0; nt < 4; ++nt) {
        float* a = acc[rt * 4 + nt];
        if (HASB) {
            int c = wcol + nt * 8 + lc * 2;
            float bx = bias[c], by = bias[c + 1];
            a[0] += bx; a[1] += by; a[2] += bx; a[3] += by;
        }
        s[rt*2+0] += a[0] + a[1]; q[rt*2+0] += a[0]*a[0] + a[1]*a[1];
        s[rt*2+1] += a[2] + a[3]; q[rt*2+1] += a[2]*a[2] + a[3]*a[3];
    }
    #pragma unroll
    for (int off = 1; off <= 2; off <<= 1)
        #pragma unroll
        for (int i = 0; i < 4; ++i) {
            s[i] += __shfl_xor_sync(0xffffffffu, s[i], off);
            q[i] += __shfl_xor_sync(0xffffffffu, q[i], off);
        }
    if (lc == 0) {
        #pragma unroll
        for (int i = 0; i < 4; ++i) {
            int row = wrow + (i >> 1) * 16 + (i & 1) * 8 + lr;
            RS[cw * 64 + row] = s[i];
            RQ[cw * 64 + row] = q[i];
        }
    }
    __syncthreads();
    float mm[4], rsd[4];
    #pragma unroll
    for (int i = 0; i < 4; ++i) {
        int row = wrow + (i >> 1) * 16 + (i & 1) * 8 + lr;
        float S = RS[row] + RS[64 + row] + RS[128 + row] + RS[192 + row];
        float Q = RQ[row] + RQ[64 + row] + RQ[128 + row] + RQ[192 + row];
        float m = S * (1.f / 128.f);
        mm[i] = m;
        rsd[i] = rsqrtf(Q * (1.f / 128.f) - m * m + LNEPS);
    }
    #pragma unroll
    for (int rt = 0; rt < 2; ++rt)
    #pragma unroll
    for (int nt = 0; nt < 4; ++nt) {
        int c = wcol + nt * 8 + lc * 2;
        float gx = gam[c], gy = gam[c + 1], ex = bet[c], ey = bet[c + 1];
        float* a = acc[rt * 4 + nt];
        int s0 = rt * 2, s1 = rt * 2 + 1;
        a[0] = (a[0] - mm[s0]) * rsd[s0] * gx + ex;
        a[1] = (a[1] - mm[s0]) * rsd[s0] * gy + ey;
        a[2] = (a[2] - mm[s1]) * rsd[s1] * gx + ex;
        a[3] = (a[3] - mm[s1]) * rsd[s1] * gy + ey;
        if (RELU) {
            a[0] = fmaxf(a[0], 0.f); a[1] = fmaxf(a[1], 0.f);
            a[2] = fmaxf(a[2], 0.f); a[3] = fmaxf(a[3], 0.f);
        }
    }
}

// fp16 fragment store
static __device__ __forceinline__ void store_acc_split_f16(
    const float (&acc)[8][4], u32* hi, u32* lo, int wrow, int wcol, int lr, int lc)
{
    #pragma unroll
    for (int rt = 0; rt < 2; ++rt)
    #pragma unroll
    for (int hh = 0; hh < 2; ++hh) {
        int row = wrow + rt * 16 + hh * 8 + lr;
        u32 base = row * PADU + (wcol >> 1) + lc;
        #pragma unroll
        for (int nt = 0; nt < 4; ++nt) {
            u32 h, l;
            split_pair_f16(acc[rt*4+nt][hh*2+0], acc[rt*4+nt][hh*2+1], h, l);
            hi[base + nt*4] = h;
            lo[base + nt*4] = l;
        }
    }
}

static __device__ __forceinline__ void store_split4_f16(u32* hi, u32* lo, int row, int col, float4 xv) {
    u32 idx = row * PADU + (col >> 1);
    u32 h0, l0, h1, l1;
    split_pair_f16(xv.x, xv.y, h0, l0);
    split_pair_f16(xv.z, xv.w, h1, l1);
    hi[idx]   = h0; hi[idx+1] = h1;
    lo[idx]   = l0; lo[idx+1] = l1;
}

// single-fp16 weight loader
static __device__ __forceinline__ void load_w_f16(u32* dst, const float* __restrict__ w,
                                                  int tid, int nth) {
    for (int idx = tid; idx < HD * HD / 2; idx += nth) {
        int o = idx & 127, k2 = idx >> 7;
        float v0 = w[(2*k2)   * HD + o];
        float v1 = w[(2*k2+1) * HD + o];
        __half2 h = __floats2half2_rn(v0, v1);
        dst[o * PADU + k2] = *reinterpret_cast<u32*>(&h);
    }
}

__global__ void k_init_lanemax() {
    int i = blockIdx.x * blockDim.x + threadIdx.x;
    if (i < NLANES * HD) g_lanemax[i] = 0;
}

#define WSZ  34816    // 128x68 u32 (weights / 128-row arrays)
#define ASZ  17408    // 64x68 u32  (64-row activation arrays)

static __device__ __forceinline__ u32 mk_aoff(int wrow, int lane) {
    return (u32)((wrow + (lane & 15)) * ROWB + ((lane >> 4) & 1) * 16);
}
static __device__ __forceinline__ u32 mk_boff(int wcol, int lane) {
    return (u32)((wcol + ((lane >> 4) & 1) * 8 + (lane & 7)) * ROWB + ((lane >> 3) & 1) * 16);
}

// ======================== fc1 (fp16 2-pass, 64-row tiles, 2 CTAs/SM) ========================
// smem: WA 0 | WB WSZ | A_HI 2WSZ | A_LO 2WSZ+ASZ | P 2WSZ+2ASZ (3072B) | RS/RQ x2 (4x1024)
__global__ void __launch_bounds__(256, 2) k_fc1(
    const float* __restrict__ x, const int* __restrict__ lane_ids,
    const float* __restrict__ w1a, const float* __restrict__ b1a,
    const float* __restrict__ g1a, const float* __restrict__ be1a,
    const float* __restrict__ w1b, const float* __restrict__ b1b,
    const float* __restrict__ g1b, const float* __restrict__ be1b)
{
    extern __shared__ char sm[];
    u32* WA   = (u32*)(sm);
    u32* WB   = (u32*)(sm + WSZ);
    u32* A_HI = (u32*)(sm + 2*WSZ);
    u32* A_LO = (u32*)(sm + 2*WSZ + ASZ);
    float* P   = (float*)(sm + 2*WSZ + 2*ASZ);
    float* RS0 = (float*)(sm + 2*WSZ + 2*ASZ + 3072);
    float* RQ0 = (float*)(sm + 2*WSZ + 2*ASZ + 4096);
    float* RS1 = (float*)(sm + 2*WSZ + 2*ASZ + 5120);
    float* RQ1 = (float*)(sm + 2*WSZ + 2*ASZ + 6144);

    const int tid = threadIdx.x, w = tid >> 5, lane = tid & 31;
    const int lr = lane >> 2, lc = lane & 3;
    const int wrow = (w & 1) * 32, wcol = (w >> 1) * 32, cw = w >> 1;
    const u32 aoff = mk_aoff(wrow, lane), boff = mk_boff(wcol, lane);
    const u32 sAH = smem_u32(A_HI), sAL = smem_u32(A_LO);
    const u32 sWA = smem_u32(WA), sWB = smem_u32(WB);

    load_w_f16(WA, w1a, tid, 256);
    load_w_f16(WB, w1b, tid, 256);
    for (int i = tid; i < HD; i += 256) {
        P[i] = b1a[i]; P[128+i] = g1a[i]; P[256+i] = be1a[i];
        P[384+i] = b1b[i]; P[512+i] = g1b[i]; P[640+i] = be1b[i];
    }
    {
        int grow = blockIdx.x * TM64 + (tid >> 2);
        if (grow < NROWS) PREF_L2((const char*)x + (size_t)blockIdx.x * TM64 * HD * 4 + tid * 128);
    }
    __syncthreads();

    for (int t = blockIdx.x; t < NT64; t += gridDim.x) {
        int r0 = t * TM64;
        // load + split x tile (64 rows x 32 float4 = 2048)
        #pragma unroll
        for (int j = 0; j < 8; ++j) {
            int idx = tid + j * 256; int xr = idx >> 5; int cg = idx & 31;
            int grow = r0 + xr; if (grow >= NROWS) grow = NROWS - 1;
            float4 xv = __ldg(((const float4*)x) + ((size_t)grow * 32 + cg));
            store_split4_f16(A_HI, A_LO, xr, cg * 4, xv);
        }
        {
            int tn = t + gridDim.x; if (tn >= NT64) tn = t;
            int grow = tn * TM64 + (tid >> 2);
            if (grow < NROWS) PREF_L2((const char*)x + (size_t)tn * TM64 * HD * 4 + tid * 128);
        }
        __syncthreads();

        float acc[8][4];
        #pragma unroll
        for (int i = 0; i < 8; ++i) { acc[i][0]=acc[i][1]=acc[i][2]=acc[i][3]=0.f; }
        gemm_f16_2p(sAH, sAL, sWA, aoff, boff, acc);
        ln_tile64<true, true>(acc, wrow, wcol, lr, lc, cw, P, P+128, P+256, RS0, RQ0);
        store_acc_split_f16(acc, A_HI, A_LO, wrow, wcol, lr, lc);
        __syncthreads();

        #pragma unroll
        for (int i = 0; i < 8; ++i) { acc[i][0]=acc[i][1]=acc[i][2]=acc[i][3]=0.f; }
        gemm_f16_2p(sAH, sAL, sWB, aoff, boff, acc);
        ln_tile64<true, true>(acc, wrow, wcol, lr, lc, cw, P+384, P+512, P+640, RS1, RQ1);

        // scatter-max (predicated: relu zeros are no-ops vs init 0)
        #pragma unroll
        for (int rt = 0; rt < 2; ++rt)
        #pragma unroll
        for (int hh = 0; hh < 2; ++hh) {
            int row = wrow + rt*16 + hh*8 + lr;
            int grow = r0 + row; if (grow >= NROWS) grow = NROWS - 1;
            int ln = __ldg(lane_ids + grow);
            int* bp = g_lanemax + ln * HD;
            #pragma unroll
            for (int nt = 0; nt < 4; ++nt) {
                int c = wcol + nt*8 + lc*2;
                float v0 = acc[rt*4+nt][hh*2+0], v1 = acc[rt*4+nt][hh*2+1];
                if (v0 > 0.f) atomicMax(bp + c,     __float_as_int(v0));
                if (v1 > 0.f) atomicMax(bp + c + 1, __float_as_int(v1));
            }
        }
        store_acc_split_f16(acc, A_HI, A_LO, wrow, wcol, lr, lc);   // h image (fp16 split)
        __syncthreads();

        const uint4* s4 = (const uint4*)A_HI;   // A_HI ++ A_LO contiguous (2*ASZ = TU64 uint4)
        uint4* d4 = g_h + (size_t)t * TU64;
        for (int i = tid; i < TU64; i += 256) d4[i] = s4[i];
        __syncthreads();
    }
}

// ======================== k_lanegemm: Z = lane_max @ w2a_bot + b2a (fp16 2-pass, 512 thr) ========================
__global__ void __launch_bounds__(512, 1) k_lanegemm(
    const float* __restrict__ w2a_bot, const float* __restrict__ b2a)
{
    extern __shared__ char sm[];
    u32* W    = (u32*)(sm);
    u32* A_HI = (u32*)(sm + WSZ);
    u32* A_LO = (u32*)(sm + 2*WSZ);
    float* P  = (float*)(sm + 3*WSZ);   // b2a

    const int tid = threadIdx.x, w = tid >> 5, lane = tid & 31;
    const int lr = lane >> 2, lc = lane & 3;
    const int wrow = (w & 3) * 32, wcol = (w >> 2) * 32;
    const u32 aoff = mk_aoff(wrow, lane), boff = mk_boff(wcol, lane);
    const u32 sAH = smem_u32(A_HI), sAL = smem_u32(A_LO);
    const u32 sW  = smem_u32(W);

    load_w_f16(W, w2a_bot, tid, 512);
    for (int i = tid; i < HD; i += 512) P[i] = b2a[i];
    __syncthreads();

    for (int t = blockIdx.x; t < NLT; t += gridDim.x) {
        int l0 = t * 128;
        #pragma unroll
        for (int j = 0; j < 8; ++j) {
            int idx = tid + j * 512; int xr = idx >> 5; int cg = idx & 31;
            int l = l0 + xr; if (l >= NLANES) l = NLANES - 1;
            int4 gv = __ldg(((const int4*)(g_lanemax)) + ((size_t)l * 32 + cg));
            store_split4_f16(A_HI, A_LO, xr, cg * 4,
                make_float4(__int_as_float(gv.x), __int_as_float(gv.y),
                            __int_as_float(gv.z), __int_as_float(gv.w)));
        }
        __syncthreads();

        float acc[8][4];
        #pragma unroll
        for (int i = 0; i < 8; ++i) { acc[i][0]=acc[i][1]=acc[i][2]=acc[i][3]=0.f; }
        gemm_f16_2p(sAH, sAL, sW, aoff, boff, acc);

        #pragma unroll
        for (int rt = 0; rt < 2; ++rt)
        #pragma unroll
        for (int hh = 0; hh < 2; ++hh) {
            int row = wrow + rt*16 + hh*8 + lr;
            int l = l0 + row;
            if (l < NLANES) {
                #pragma unroll
                for (int nt = 0; nt < 4; ++nt) {
                    int c = wcol + nt*8 + lc*2;
                    *(float2*)(g_z + (size_t)l * HD + c) =
                        make_float2(acc[rt*4+nt][hh*2+0] + P[c],
                                    acc[rt*4+nt][hh*2+1] + P[c+1]);
                }
            }
        }
        __syncthreads();
    }
}

// ======================== fused fc2 (fp16 2-pass, 64-row tiles, 2 CTAs/SM) ========================
// smem: WA 0 | WB WSZ | A_HI 2WSZ | A_LO 2WSZ+ASZ | P 2WSZ+2ASZ (3584B) | RS/RQ x2
__global__ void __launch_bounds__(256, 2) k_fc2(
    const float* __restrict__ x, const int* __restrict__ lane_ids,
    const float* __restrict__ w2a_top,
    const float* __restrict__ g2a, const float* __restrict__ be2a,
    const float* __restrict__ w2b, const float* __restrict__ b2b,
    const float* __restrict__ g2b, const float* __restrict__ be2b,
    const float* __restrict__ gn, const float* __restrict__ bn,
    float* __restrict__ out)
{
    extern __shared__ char sm[];
    u32* WA   = (u32*)(sm);
    u32* WB   = (u32*)(sm + WSZ);
    u32* A_HI = (u32*)(sm + 2*WSZ);
    u32* A_LO = (u32*)(sm + 2*WSZ + ASZ);
    float* P   = (float*)(sm + 2*WSZ + 2*ASZ);
    float* RS0 = (float*)(sm + 2*WSZ + 2*ASZ + 3584);
    float* RQ0 = (float*)(sm + 2*WSZ + 2*ASZ + 4608);
    float* RS1 = (float*)(sm + 2*WSZ + 2*ASZ + 5632);
    float* RQ1 = (float*)(sm + 2*WSZ + 2*ASZ + 6656);

    const int tid = threadIdx.x, w = tid >> 5, lane = tid & 31;
    const int lr = lane >> 2, lc = lane & 3;
    const int wrow = (w & 1) * 32, wcol = (w >> 1) * 32, cw = w >> 1;
    const u32 aoff = mk_aoff(wrow, lane), boff = mk_boff(wcol, lane);
    const u32 sWA = smem_u32(WA), sWB = smem_u32(WB);
    const u32 sAH = smem_u32(A_HI), sAL = smem_u32(A_LO);

    // prologue: issue first h-image load FIRST (overlaps weight loads)
    {
        const uint4* s4 = g_h + (size_t)blockIdx.x * TU64;
        #pragma unroll
        for (int j = 0; j < 9; ++j) {
            int i = tid + j * 256;
            if (i < TU64) CP16(sAH + (u32)i * 16, s4 + i);
        }
        CP_COMMIT();
    }
    load_w_f16(WA, w2a_top, tid, 256);
    load_w_f16(WB, w2b,     tid, 256);
    for (int i = tid; i < HD; i += 256) {
        P[i]       = g2a[i]; P[128+i] = be2a[i];
        P[256+i]   = b2b[i]; P[384+i] = g2b[i]; P[512+i] = be2b[i];
        P[640+i]   = gn[i];  P[768+i] = bn[i];
    }
    {
        int grow = blockIdx.x * TM64 + (tid >> 2);
        if (grow < NROWS) PREF_L2((const char*)x + (size_t)blockIdx.x * TM64 * HD * 4 + tid * 128);
    }
    __syncthreads();

    for (int t = blockIdx.x; t < NT64; t += gridDim.x) {
        int r0 = t * TM64;
        int tn = t + gridDim.x; if (tn >= NT64) tn = t;

        CP_WAIT0();                       // current h image resident in A
        __syncthreads();

        // warm L2 with NEXT tile's h image (real cp.async issued after GEMM2)
        {
            const char* nh = (const char*)(g_h + (size_t)tn * TU64);
            for (int l = tid; l < 272; l += 256) PREF_L2(nh + (size_t)l * 128);
        }
        // prefetch this tile's Z rows into L2
        {
            int grow = r0 + (tid >> 2); if (grow >= NROWS) grow = NROWS - 1;
            int lnid = __ldg(lane_ids + grow);
            PREF_L2(g_z + (size_t)lnid * HD + (tid & 3) * 32);
        }

        float acc[8][4];
        #pragma unroll
        for (int i = 0; i < 8; ++i) { acc[i][0]=acc[i][1]=acc[i][2]=acc[i][3]=0.f; }
        gemm_f16_2p(sAH, sAL, sWA, aoff, boff, acc);

        // add Z[lane] (fp32, b2a folded in)
        #pragma unroll
        for (int rt = 0; rt < 2; ++rt)
        #pragma unroll
        for (int hh = 0; hh < 2; ++hh) {
            int row = wrow + rt*16 + hh*8 + lr;
            int grow = r0 + row; if (grow >= NROWS) grow = NROWS - 1;
            int lnid = __ldg(lane_ids + grow);
            const float* zr = g_z + (size_t)lnid * HD;
            #pragma unroll
            for (int nt = 0; nt < 4; ++nt) {
                int c = wcol + nt*8 + lc*2;
                float2 zv = __ldg((const float2*)(zr + c));
                acc[rt*4+nt][hh*2+0] += zv.x;
                acc[rt*4+nt][hh*2+1] += zv.y;
            }
        }
        // LN1 + ReLU (set0; its barrier also guarantees all GEMM1 A-reads done)
        ln_tile64<false, true>(acc, wrow, wcol, lr, lc, cw, P, P, P+128, RS0, RQ0);

        // store f into A (in place; safe per LN1 barrier)
        store_acc_split_f16(acc, A_HI, A_LO, wrow, wcol, lr, lc);
        __syncthreads();

        // GEMM2: f @ w2b
        #pragma unroll
        for (int i = 0; i < 8; ++i) { acc[i][0]=acc[i][1]=acc[i][2]=acc[i][3]=0.f; }
        gemm_f16_2p(sAH, sAL, sWB, aoff, boff, acc);
        __syncthreads();                  // all A reads complete

        // A free: issue NEXT tile's h image now — overlaps the whole epilogue
        {
            const uint4* s4 = g_h + (size_t)tn * TU64;
            #pragma unroll
            for (int j = 0; j < 9; ++j) {
                int i = tid + j * 256;
                if (i < TU64) CP16(sAH + (u32)i * 16, s4 + i);
            }
            CP_COMMIT();
            int grow = tn * TM64 + (tid >> 2);
            if (grow < NROWS) PREF_L2((const char*)x + (size_t)tn * TM64 * HD * 4 + tid * 128);
        }

        // LN2 + ReLU (set1)
        ln_tile64<true, true>(acc, wrow, wcol, lr, lc, cw, P+256, P+384, P+512, RS1, RQ1);

        // residual add from x (L2-hot)
        #pragma unroll
        for (int rt = 0; rt < 2; ++rt)
        #pragma unroll
        for (int hh = 0; hh < 2; ++hh) {
            int row = wrow + rt*16 + hh*8 + lr;
            int grow = r0 + row; if (grow >= NROWS) grow = NROWS - 1;
            #pragma unroll
            for (int nt = 0; nt < 4; ++nt) {
                int c = wcol + nt*8 + lc*2;
                float2 xv = __ldg((const float2*)(x + (size_t)grow * HD + c));
                acc[rt*4+nt][hh*2+0] += xv.x;
                acc[rt*4+nt][hh*2+1] += xv.y;
            }
        }
        // final LN (set0 — safe: last set0 read was LN1, separated by f-store barrier)
        ln_tile64<false, false>(acc, wrow, wcol, lr, lc, cw, P, P+640, P+768, RS0, RQ0);

        // write out straight from registers
        #pragma unroll
        for (int rt = 0; rt < 2; ++rt)
        #pragma unroll
        for (int hh = 0; hh < 2; ++hh) {
            int row = wrow + rt*16 + hh*8 + lr;
            int grow = r0 + row;
            if (grow < NROWS) {
                #pragma unroll
                for (int nt = 0; nt < 4; ++nt) {
                    int c = wcol + nt*8 + lc*2;
                    *(float2*)(out + (size_t)grow * HD + c) =
                        make_float2(acc[rt*4+nt][hh*2+0], acc[rt*4+nt][hh*2+1]);
                }
            }
        }
        // loop-top CP_WAIT0 + __syncthreads gates A and RS0 reuse
    }
}

// ---------------- launcher ----------------
extern "C" void kernel_launch(void* const* d_in, const int* in_sizes, int n_in,
                              void* d_out, int out_size) {
    (void)in_sizes; (void)n_in; (void)out_size;
    const float* x        = (const float*)d_in[0];
    const int*   lane_ids = (const int*)  d_in[1];
    const float* w1a  = (const float*)d_in[2];
    const float* b1a  = (const float*)d_in[3];
    const float* g1a  = (const float*)d_in[4];
    const float* be1a = (const float*)d_in[5];
    const float* w1b  = (const float*)d_in[6];
    const float* b1b  = (const float*)d_in[7];
    const float* g1b  = (const float*)d_in[8];
    const float* be1b = (const float*)d_in[9];
    const float* w2a  = (const float*)d_in[10];
    const float* b2a  = (const float*)d_in[11];
    const float* g2a  = (const float*)d_in[12];
    const float* be2a = (const float*)d_in[13];
    const float* w2b  = (const float*)d_in[14];
    const float* b2b  = (const float*)d_in[15];
    const float* g2b  = (const float*)d_in[16];
    const float* be2b = (const float*)d_in[17];
    const float* gn   = (const float*)d_in[18];
    const float* bn   = (const float*)d_in[19];
    float* out = (float*)d_out;

    const int SM1  = 2*WSZ + 2*ASZ + 3072 + 4096;   // 111616
    const int SMLG = 3*WSZ + 1024;                  // 105472
    const int SM2  = 2*WSZ + 2*ASZ + 3584 + 4096;   // 112128
    cudaFuncSetAttribute(k_fc1,      cudaFuncAttributeMaxDynamicSharedMemorySize, SM1);
    cudaFuncSetAttribute(k_lanegemm, cudaFuncAttributeMaxDynamicSharedMemorySize, SMLG);
    cudaFuncSetAttribute(k_fc2,      cudaFuncAttributeMaxDynamicSharedMemorySize, SM2);

    k_init_lanemax<<<(NLANES * HD + 511) / 512, 512>>>();
    k_fc1     <<<296, 256, SM1>>> (x, lane_ids, w1a, b1a, g1a, be1a, w1b, b1b, g1b, be1b);
    k_lanegemm<<<148, 512, SMLG>>>(w2a + 128 * HD, b2a);
    k_fc2     <<<296, 256, SM2>>> (x, lane_ids, w2a, g2a, be2a, w2b, b2b, g2b, be2b, gn, bn, out);
}

// round 14
// speedup vs baseline: 2.6503x; 1.0013x over previous
#include <cuda_runtime.h>
#include <cuda_bf16.h>
#include <cuda_fp16.h>
#include <cstdint>

#define NROWS  300000
#define HD     128
#define NLANES 25000
#define LNEPS  1e-5f
#define TM64   64
#define NT64   ((NROWS + TM64 - 1) / TM64)  // 4688 tiles (64-row)
#define NLT    ((NLANES + 127) / 128)       // 196 lane tiles
#define PADU   68                            // u32 per 128-b16 row (272B, conflict-free)
#define ROWB   272
#define TU64   2176                          // uint4 per 64-row split tile image (hi+lo)

typedef unsigned int       u32;
typedef unsigned short     u16;
typedef unsigned long long u64;

// ---------------- device scratch ----------------
__device__ uint4 g_h[(size_t)NT64 * TU64];   // fc1 output image (fp16 split, 64-row tiles)
__device__ int   g_lanemax[NLANES * HD];     // per-lane max (float bits, relu>=0)
__device__ float g_z[(size_t)NLANES * HD];   // per-lane Z = max @ w2a_bot + b2a

// ---------------- helpers ----------------
static __device__ __forceinline__ u32 smem_u32(const void* p) {
    u32 a;
    asm("{ .reg .u64 t; cvta.to.shared.u64 t, %1; cvt.u32.u64 %0, t; }" : "=r"(a) : "l"(p));
    return a;
}

// fp16 hi/lo split of a pair
static __device__ __forceinline__ void split_pair_f16(float v0, float v1, u32& hi, u32& lo) {
    __half2 h = __floats2half2_rn(v0, v1);
    float h0 = __low2float(h), h1 = __high2float(h);
    __half2 l = __floats2half2_rn(v0 - h0, v1 - h1);
    hi = *reinterpret_cast<u32*>(&h);
    lo = *reinterpret_cast<u32*>(&l);
}

#define CP16(sm_addr, gptr) \
    asm volatile("cp.async.cg.shared.global [%0], [%1], 16;" :: "r"(sm_addr), "l"(gptr))
#define CP_COMMIT() asm volatile("cp.async.commit_group;" ::: "memory")
#define CP_WAIT0()  asm volatile("cp.async.wait_group 0;" ::: "memory")
#define PREF_L2(p)  asm volatile("prefetch.global.L2 [%0];" :: "l"(p))

static __device__ __forceinline__ void ldsm4(u32& r0, u32& r1, u32& r2, u32& r3, u32 addr) {
    asm volatile("ldmatrix.sync.aligned.m8n8.x4.shared.b16 {%0,%1,%2,%3}, [%4];"
        : "=r"(r0), "=r"(r1), "=r"(r2), "=r"(r3) : "r"(addr));
}
static __device__ __forceinline__ void mma_f16(float (&d)[4], const u32 (&a)[4], u32 b0, u32 b1) {
    asm volatile("mma.sync.aligned.m16n8k16.row.col.f32.f16.f16.f32 "
        "{%0,%1,%2,%3}, {%4,%5,%6,%7}, {%8,%9}, {%0,%1,%2,%3};"
        : "+f"(d[0]), "+f"(d[1]), "+f"(d[2]), "+f"(d[3])
        : "r"(a[0]), "r"(a[1]), "r"(a[2]), "r"(a[3]), "r"(b0), "r"(b1));
}

// Fragment set for one k-chunk (A hi/lo 2 row-tiles + B 2 col-tiles)
struct Frag {
    u32 ah0[4], ah1[4], al0[4], al1[4], b[8];
};
static __device__ __forceinline__ void ld_frag(Frag& f, u32 Ah, u32 Al, u32 B,
                                               u32 aoff, u32 boff, u32 ka) {
    ldsm4(f.ah0[0], f.ah0[1], f.ah0[2], f.ah0[3], Ah + aoff + ka);
    ldsm4(f.ah1[0], f.ah1[1], f.ah1[2], f.ah1[3], Ah + aoff + 16 * ROWB + ka);
    ldsm4(f.al0[0], f.al0[1], f.al0[2], f.al0[3], Al + aoff + ka);
    ldsm4(f.al1[0], f.al1[1], f.al1[2], f.al1[3], Al + aoff + 16 * ROWB + ka);
    ldsm4(f.b[0], f.b[1], f.b[2], f.b[3], B + boff + ka);
    ldsm4(f.b[4], f.b[5], f.b[6], f.b[7], B + boff + 16 * ROWB + ka);
}
static __device__ __forceinline__ void mma_frag(const Frag& f, float (&acc)[8][4]) {
    #pragma unroll
    for (int p = 0; p < 2; ++p)
    #pragma unroll
    for (int j = 0; j < 2; ++j) {
        const int nt = p * 2 + j;
        const u32 b0 = f.b[p*4 + j*2], b1 = f.b[p*4 + j*2 + 1];
        mma_f16(acc[nt],     f.ah0, b0, b1);
        mma_f16(acc[4 + nt], f.ah1, b0, b1);
        mma_f16(acc[nt],     f.al0, b0, b1);
        mma_f16(acc[4 + nt], f.al1, b0, b1);
    }
}

// fp16 2-pass GEMM with software-pipelined fragment loads:
// chunk k+1's ldsm issue while chunk k's MMAs execute.
static __device__ __forceinline__ void gemm_f16_2p(
    u32 Ah, u32 Al, u32 B, u32 aoff, u32 boff, float (&acc)[8][4])
{
    Fragment_pipeline:;
    Frag fa, fb;
    ld_frag(fa, Ah, Al, B, aoff, boff, 0);
    #pragma unroll
    for (int kc = 0; kc < 8; ++kc) {
        if ((kc & 1) == 0) {
            if (kc < 7) ld_frag(fb, Ah, Al, B, aoff, boff, (u32)(kc + 1) * 32);
            mma_frag(fa, acc);
        } else {
            if (kc < 7) ld_frag(fa, Ah, Al, B, aoff, boff, (u32)(kc + 1) * 32);
            mma_frag(fb, acc);
        }
    }
}

// ---------------- LN epilogue for 64-row tiles (single barrier; ping-pong RS/RQ) ----------------
template<bool HASB, bool RELU>
static __device__ __forceinline__ void ln_tile64(
    float (&acc)[8][4], int wrow, int wcol, int lr, int lc, int cw,
    const float* __restrict__ bias, const float* __restrict__ gam,
    const float* __restrict__ bet, float* RS, float* RQ)
{
    float s[4] = {0.f,0.f,0.f,0.f}, q[4] = {0.f,0.f,0.f,0.f};
    #pragma unroll
    for (int rt = 0; rt < 2; ++rt)
    #pragma unroll
    for (int nt = 0; nt < 4; ++nt) {
        float* a = acc[rt * 4 + nt];
        if (HASB) {
            int c = wcol + nt * 8 + lc * 2;
            float bx = bias[c], by = bias[c + 1];
            a[0] += bx; a[1] += by; a[2] += bx; a[3] += by;
        }
        s[rt*2+0] += a[0] + a[1]; q[rt*2+0] += a[0]*a[0] + a[1]*a[1];
        s[rt*2+1] += a[2] + a[3]; q[rt*2+1] += a[2]*a[2] + a[3]*a[3];
    }
    #pragma unroll
    for (int off = 1; off <= 2; off <<= 1)
        #pragma unroll
        for (int i = 0; i < 4; ++i) {
            s[i] += __shfl_xor_sync(0xffffffffu, s[i], off);
            q[i] += __shfl_xor_sync(0xffffffffu, q[i], off);
        }
    if (lc == 0) {
        #pragma unroll
        for (int i = 0; i < 4; ++i) {
            int row = wrow + (i >> 1) * 16 + (i & 1) * 8 + lr;
            RS[cw * 64 + row] = s[i];
            RQ[cw * 64 + row] = q[i];
        }
    }
    __syncthreads();
    float mm[4], rsd[4];
    #pragma unroll
    for (int i = 0; i < 4; ++i) {
        int row = wrow + (i >> 1) * 16 + (i & 1) * 8 + lr;
        float S = RS[row] + RS[64 + row] + RS[128 + row] + RS[192 + row];
        float Q = RQ[row] + RQ[64 + row] + RQ[128 + row] + RQ[192 + row];
        float m = S * (1.f / 128.f);
        mm[i] = m;
        rsd[i] = rsqrtf(Q * (1.f / 128.f) - m * m + LNEPS);
    }
    #pragma unroll
    for (int rt = 0; rt < 2; ++rt)
    #pragma unroll
    for (int nt = 0; nt < 4; ++nt) {
        int c = wcol + nt * 8 + lc * 2;
        float gx = gam[c], gy = gam[c + 1], ex = bet[c], ey = bet[c + 1];
        float* a = acc[rt * 4 + nt];
        int s0 = rt * 2, s1 = rt * 2 + 1;
        a[0] = (a[0] - mm[s0]) * rsd[s0] * gx + ex;
        a[1] = (a[1] - mm[s0]) * rsd[s0] * gy + ey;
        a[2] = (a[2] - mm[s1]) * rsd[s1] * gx + ex;
        a[3] = (a[3] - mm[s1]) * rsd[s1] * gy + ey;
        if (RELU) {
            a[0] = fmaxf(a[0], 0.f); a[1] = fmaxf(a[1], 0.f);
            a[2] = fmaxf(a[2], 0.f); a[3] = fmaxf(a[3], 0.f);
        }
    }
}

// fp16 fragment store
static __device__ __forceinline__ void store_acc_split_f16(
    const float (&acc)[8][4], u32* hi, u32* lo, int wrow, int wcol, int lr, int lc)
{
    #pragma unroll
    for (int rt = 0; rt < 2; ++rt)
    #pragma unroll
    for (int hh = 0; hh < 2; ++hh) {
        int row = wrow + rt * 16 + hh * 8 + lr;
        u32 base = row * PADU + (wcol >> 1) + lc;
        #pragma unroll
        for (int nt = 0; nt < 4; ++nt) {
            u32 h, l;
            split_pair_f16(acc[rt*4+nt][hh*2+0], acc[rt*4+nt][hh*2+1], h, l);
            hi[base + nt*4] = h;
            lo[base + nt*4] = l;
        }
    }
}

static __device__ __forceinline__ void store_split4_f16(u32* hi, u32* lo, int row, int col, float4 xv) {
    u32 idx = row * PADU + (col >> 1);
    u32 h0, l0, h1, l1;
    split_pair_f16(xv.x, xv.y, h0, l0);
    split_pair_f16(xv.z, xv.w, h1, l1);
    hi[idx]   = h0; hi[idx+1] = h1;
    lo[idx]   = l0; lo[idx+1] = l1;
}

// single-fp16 weight loader
static __device__ __forceinline__ void load_w_f16(u32* dst, const float* __restrict__ w,
                                                  int tid, int nth) {
    for (int idx = tid; idx < HD * HD / 2; idx += nth) {
        int o = idx & 127, k2 = idx >> 7;
        float v0 = w[(2*k2)   * HD + o];
        float v1 = w[(2*k2+1) * HD + o];
        __half2 h = __floats2half2_rn(v0, v1);
        dst[o * PADU + k2] = *reinterpret_cast<u32*>(&h);
    }
}

__global__ void k_init_lanemax() {
    int i = blockIdx.x * blockDim.x + threadIdx.x;
    if (i < NLANES * HD) g_lanemax[i] = 0;
}

#define WSZ  34816    // 128x68 u32 (weights / 128-row arrays)
#define ASZ  17408    // 64x68 u32  (64-row activation arrays)

static __device__ __forceinline__ u32 mk_aoff(int wrow, int lane) {
    return (u32)((wrow + (lane & 15)) * ROWB + ((lane >> 4) & 1) * 16);
}
static __device__ __forceinline__ u32 mk_boff(int wcol, int lane) {
    return (u32)((wcol + ((lane >> 4) & 1) * 8 + (lane & 7)) * ROWB + ((lane >> 3) & 1) * 16);
}

// ======================== fc1 (fp16 2-pass, 64-row tiles, 2 CTAs/SM) ========================
__global__ void __launch_bounds__(256, 2) k_fc1(
    const float* __restrict__ x, const int* __restrict__ lane_ids,
    const float* __restrict__ w1a, const float* __restrict__ b1a,
    const float* __restrict__ g1a, const float* __restrict__ be1a,
    const float* __restrict__ w1b, const float* __restrict__ b1b,
    const float* __restrict__ g1b, const float* __restrict__ be1b)
{
    extern __shared__ char sm[];
    u32* WA   = (u32*)(sm);
    u32* WB   = (u32*)(sm + WSZ);
    u32* A_HI = (u32*)(sm + 2*WSZ);
    u32* A_LO = (u32*)(sm + 2*WSZ + ASZ);
    float* P   = (float*)(sm + 2*WSZ + 2*ASZ);
    float* RS0 = (float*)(sm + 2*WSZ + 2*ASZ + 3072);
    float* RQ0 = (float*)(sm + 2*WSZ + 2*ASZ + 4096);
    float* RS1 = (float*)(sm + 2*WSZ + 2*ASZ + 5120);
    float* RQ1 = (float*)(sm + 2*WSZ + 2*ASZ + 6144);

    const int tid = threadIdx.x, w = tid >> 5, lane = tid & 31;
    const int lr = lane >> 2, lc = lane & 3;
    const int wrow = (w & 1) * 32, wcol = (w >> 1) * 32, cw = w >> 1;
    const u32 aoff = mk_aoff(wrow, lane), boff = mk_boff(wcol, lane);
    const u32 sAH = smem_u32(A_HI), sAL = smem_u32(A_LO);
    const u32 sWA = smem_u32(WA), sWB = smem_u32(WB);

    load_w_f16(WA, w1a, tid, 256);
    load_w_f16(WB, w1b, tid, 256);
    for (int i = tid; i < HD; i += 256) {
        P[i] = b1a[i]; P[128+i] = g1a[i]; P[256+i] = be1a[i];
        P[384+i] = b1b[i]; P[512+i] = g1b[i]; P[640+i] = be1b[i];
    }
    {
        int grow = blockIdx.x * TM64 + (tid >> 2);
        if (grow < NROWS) PREF_L2((const char*)x + (size_t)blockIdx.x * TM64 * HD * 4 + tid * 128);
    }
    __syncthreads();

    for (int t = blockIdx.x; t < NT64; t += gridDim.x) {
        int r0 = t * TM64;
        #pragma unroll
        for (int j = 0; j < 8; ++j) {
            int idx = tid + j * 256; int xr = idx >> 5; int cg = idx & 31;
            int grow = r0 + xr; if (grow >= NROWS) grow = NROWS - 1;
            float4 xv = __ldg(((const float4*)x) + ((size_t)grow * 32 + cg));
            store_split4_f16(A_HI, A_LO, xr, cg * 4, xv);
        }
        {
            int tn = t + gridDim.x; if (tn >= NT64) tn = t;
            int grow = tn * TM64 + (tid >> 2);
            if (grow < NROWS) PREF_L2((const char*)x + (size_t)tn * TM64 * HD * 4 + tid * 128);
        }
        __syncthreads();

        float acc[8][4];
        #pragma unroll
        for (int i = 0; i < 8; ++i) { acc[i][0]=acc[i][1]=acc[i][2]=acc[i][3]=0.f; }
        gemm_f16_2p(sAH, sAL, sWA, aoff, boff, acc);
        ln_tile64<true, true>(acc, wrow, wcol, lr, lc, cw, P, P+128, P+256, RS0, RQ0);
        store_acc_split_f16(acc, A_HI, A_LO, wrow, wcol, lr, lc);
        __syncthreads();

        #pragma unroll
        for (int i = 0; i < 8; ++i) { acc[i][0]=acc[i][1]=acc[i][2]=acc[i][3]=0.f; }
        gemm_f16_2p(sAH, sAL, sWB, aoff, boff, acc);
        ln_tile64<true, true>(acc, wrow, wcol, lr, lc, cw, P+384, P+512, P+640, RS1, RQ1);

        // scatter-max (predicated: relu zeros are no-ops vs init 0)
        #pragma unroll
        for (int rt = 0; rt < 2; ++rt)
        #pragma unroll
        for (int hh = 0; hh < 2; ++hh) {
            int row = wrow + rt*16 + hh*8 + lr;
            int grow = r0 + row; if (grow >= NROWS) grow = NROWS - 1;
            int ln = __ldg(lane_ids + grow);
            int* bp = g_lanemax + ln * HD;
            #pragma unroll
            for (int nt = 0; nt < 4; ++nt) {
                int c = wcol + nt*8 + lc*2;
                float v0 = acc[rt*4+nt][hh*2+0], v1 = acc[rt*4+nt][hh*2+1];
                if (v0 > 0.f) atomicMax(bp + c,     __float_as_int(v0));
                if (v1 > 0.f) atomicMax(bp + c + 1, __float_as_int(v1));
            }
        }
        store_acc_split_f16(acc, A_HI, A_LO, wrow, wcol, lr, lc);   // h image (fp16 split)
        __syncthreads();

        const uint4* s4 = (const uint4*)A_HI;
        uint4* d4 = g_h + (size_t)t * TU64;
        for (int i = tid; i < TU64; i += 256) d4[i] = s4[i];
        __syncthreads();
    }
}

// ======================== k_lanegemm: Z = lane_max @ w2a_bot + b2a (fp16 2-pass, 512 thr) ========================
__global__ void __launch_bounds__(512, 1) k_lanegemm(
    const float* __restrict__ w2a_bot, const float* __restrict__ b2a)
{
    extern __shared__ char sm[];
    u32* W    = (u32*)(sm);
    u32* A_HI = (u32*)(sm + WSZ);
    u32* A_LO = (u32*)(sm + 2*WSZ);
    float* P  = (float*)(sm + 3*WSZ);   // b2a

    const int tid = threadIdx.x, w = tid >> 5, lane = tid & 31;
    const int lr = lane >> 2, lc = lane & 3;
    const int wrow = (w & 3) * 32, wcol = (w >> 2) * 32;
    const u32 aoff = mk_aoff(wrow, lane), boff = mk_boff(wcol, lane);
    const u32 sAH = smem_u32(A_HI), sAL = smem_u32(A_LO);
    const u32 sW  = smem_u32(W);

    load_w_f16(W, w2a_bot, tid, 512);
    for (int i = tid; i < HD; i += 512) P[i] = b2a[i];
    __syncthreads();

    for (int t = blockIdx.x; t < NLT; t += gridDim.x) {
        int l0 = t * 128;
        #pragma unroll
        for (int j = 0; j < 8; ++j) {
            int idx = tid + j * 512; int xr = idx >> 5; int cg = idx & 31;
            int l = l0 + xr; if (l >= NLANES) l = NLANES - 1;
            int4 gv = __ldg(((const int4*)(g_lanemax)) + ((size_t)l * 32 + cg));
            store_split4_f16(A_HI, A_LO, xr, cg * 4,
                make_float4(__int_as_float(gv.x), __int_as_float(gv.y),
                            __int_as_float(gv.z), __int_as_float(gv.w)));
        }
        __syncthreads();

        float acc[8][4];
        #pragma unroll
        for (int i = 0; i < 8; ++i) { acc[i][0]=acc[i][1]=acc[i][2]=acc[i][3]=0.f; }
        gemm_f16_2p(sAH, sAL, sW, aoff, boff, acc);

        #pragma unroll
        for (int rt = 0; rt < 2; ++rt)
        #pragma unroll
        for (int hh = 0; hh < 2; ++hh) {
            int row = wrow + rt*16 + hh*8 + lr;
            int l = l0 + row;
            if (l < NLANES) {
                #pragma unroll
                for (int nt = 0; nt < 4; ++nt) {
                    int c = wcol + nt*8 + lc*2;
                    *(float2*)(g_z + (size_t)l * HD + c) =
                        make_float2(acc[rt*4+nt][hh*2+0] + P[c],
                                    acc[rt*4+nt][hh*2+1] + P[c+1]);
                }
            }
        }
        __syncthreads();
    }
}

// ======================== fused fc2 (fp16 2-pass, 64-row tiles, 2 CTAs/SM) ========================
__global__ void __launch_bounds__(256, 2) k_fc2(
    const float* __restrict__ x, const int* __restrict__ lane_ids,
    const float* __restrict__ w2a_top,
    const float* __restrict__ g2a, const float* __restrict__ be2a,
    const float* __restrict__ w2b, const float* __restrict__ b2b,
    const float* __restrict__ g2b, const float* __restrict__ be2b,
    const float* __restrict__ gn, const float* __restrict__ bn,
    float* __restrict__ out)
{
    extern __shared__ char sm[];
    u32* WA   = (u32*)(sm);
    u32* WB   = (u32*)(sm + WSZ);
    u32* A_HI = (u32*)(sm + 2*WSZ);
    u32* A_LO = (u32*)(sm + 2*WSZ + ASZ);
    float* P   = (float*)(sm + 2*WSZ + 2*ASZ);
    float* RS0 = (float*)(sm + 2*WSZ + 2*ASZ + 3584);
    float* RQ0 = (float*)(sm + 2*WSZ + 2*ASZ + 4608);
    float* RS1 = (float*)(sm + 2*WSZ + 2*ASZ + 5632);
    float* RQ1 = (float*)(sm + 2*WSZ + 2*ASZ + 6656);

    const int tid = threadIdx.x, w = tid >> 5, lane = tid & 31;
    const int lr = lane >> 2, lc = lane & 3;
    const int wrow = (w & 1) * 32, wcol = (w >> 1) * 32, cw = w >> 1;
    const u32 aoff = mk_aoff(wrow, lane), boff = mk_boff(wcol, lane);
    const u32 sWA = smem_u32(WA), sWB = smem_u32(WB);
    const u32 sAH = smem_u32(A_HI), sAL = smem_u32(A_LO);

    // prologue: issue first h-image load FIRST (overlaps weight loads)
    {
        const uint4* s4 = g_h + (size_t)blockIdx.x * TU64;
        #pragma unroll
        for (int j = 0; j < 9; ++j) {
            int i = tid + j * 256;
            if (i < TU64) CP16(sAH + (u32)i * 16, s4 + i);
        }
        CP_COMMIT();
    }
    load_w_f16(WA, w2a_top, tid, 256);
    load_w_f16(WB, w2b,     tid, 256);
    for (int i = tid; i < HD; i += 256) {
        P[i]       = g2a[i]; P[128+i] = be2a[i];
        P[256+i]   = b2b[i]; P[384+i] = g2b[i]; P[512+i] = be2b[i];
        P[640+i]   = gn[i];  P[768+i] = bn[i];
    }
    {
        int grow = blockIdx.x * TM64 + (tid >> 2);
        if (grow < NROWS) PREF_L2((const char*)x + (size_t)blockIdx.x * TM64 * HD * 4 + tid * 128);
    }
    __syncthreads();

    for (int t = blockIdx.x; t < NT64; t += gridDim.x) {
        int r0 = t * TM64;
        int tn = t + gridDim.x; if (tn >= NT64) tn = t;

        CP_WAIT0();                       // current h image resident in A
        __syncthreads();

        // warm L2 with NEXT tile's h image (real cp.async issued after GEMM2)
        {
            const char* nh = (const char*)(g_h + (size_t)tn * TU64);
            for (int l = tid; l < 272; l += 256) PREF_L2(nh + (size_t)l * 128);
        }
        // prefetch this tile's Z rows into L2
        {
            int grow = r0 + (tid >> 2); if (grow >= NROWS) grow = NROWS - 1;
            int lnid = __ldg(lane_ids + grow);
            PREF_L2(g_z + (size_t)lnid * HD + (tid & 3) * 32);
        }

        float acc[8][4];
        #pragma unroll
        for (int i = 0; i < 8; ++i) { acc[i][0]=acc[i][1]=acc[i][2]=acc[i][3]=0.f; }
        gemm_f16_2p(sAH, sAL, sWA, aoff, boff, acc);

        // add Z[lane] (fp32, b2a folded in)
        #pragma unroll
        for (int rt = 0; rt < 2; ++rt)
        #pragma unroll
        for (int hh = 0; hh < 2; ++hh) {
            int row = wrow + rt*16 + hh*8 + lr;
            int grow = r0 + row; if (grow >= NROWS) grow = NROWS - 1;
            int lnid = __ldg(lane_ids + grow);
            const float* zr = g_z + (size_t)lnid * HD;
            #pragma unroll
            for (int nt = 0; nt < 4; ++nt) {
                int c = wcol + nt*8 + lc*2;
                float2 zv = __ldg((const float2*)(zr + c));
                acc[rt*4+nt][hh*2+0] += zv.x;
                acc[rt*4+nt][hh*2+1] += zv.y;
            }
        }
        // LN1 + ReLU (set0; its barrier also guarantees all GEMM1 A-reads done)
        ln_tile64<false, true>(acc, wrow, wcol, lr, lc, cw, P, P, P+128, RS0, RQ0);

        // store f into A (in place; safe per LN1 barrier)
        store_acc_split_f16(acc, A_HI, A_LO, wrow, wcol, lr, lc);
        __syncthreads();

        // GEMM2: f @ w2b
        #pragma unroll
        for (int i = 0; i < 8; ++i) { acc[i][0]=acc[i][1]=acc[i][2]=acc[i][3]=0.f; }
        gemm_f16_2p(sAH, sAL, sWB, aoff, boff, acc);
        __syncthreads();                  // all A reads complete

        // A free: issue NEXT tile's h image now — overlaps the whole epilogue
        {
            const uint4* s4 = g_h + (size_t)tn * TU64;
            #pragma unroll
            for (int j = 0; j < 9; ++j) {
                int i = tid + j * 256;
                if (i < TU64) CP16(sAH + (u32)i * 16, s4 + i);
            }
            CP_COMMIT();
            int grow = tn * TM64 + (tid >> 2);
            if (grow < NROWS) PREF_L2((const char*)x + (size_t)tn * TM64 * HD * 4 + tid * 128);
        }

        // LN2 + ReLU (set1)
        ln_tile64<true, true>(acc, wrow, wcol, lr, lc, cw, P+256, P+384, P+512, RS1, RQ1);

        // residual add from x (L2-hot)
        #pragma unroll
        for (int rt = 0; rt < 2; ++rt)
        #pragma unroll
        for (int hh = 0; hh < 2; ++hh) {
            int row = wrow + rt*16 + hh*8 + lr;
            int grow = r0 + row; if (grow >= NROWS) grow = NROWS - 1;
            #pragma unroll
            for (int nt = 0; nt < 4; ++nt) {
                int c = wcol + nt*8 + lc*2;
                float2 xv = __ldg((const float2*)(x + (size_t)grow * HD + c));
                acc[rt*4+nt][hh*2+0] += xv.x;
                acc[rt*4+nt][hh*2+1] += xv.y;
            }
        }
        // final LN (set0 — safe: last set0 read was LN1, separated by f-store barrier)
        ln_tile64<false, false>(acc, wrow, wcol, lr, lc, cw, P, P+640, P+768, RS0, RQ0);

        // write out straight from registers
        #pragma unroll
        for (int rt = 0; rt < 2; ++rt)
        #pragma unroll
        for (int hh = 0; hh < 2; ++hh) {
            int row = wrow + rt*16 + hh*8 + lr;
            int grow = r0 + row;
            if (grow < NROWS) {
                #pragma unroll
                for (int nt = 0; nt < 4; ++nt) {
                    int c = wcol + nt*8 + lc*2;
                    *(float2*)(out + (size_t)grow * HD + c) =
                        make_float2(acc[rt*4+nt][hh*2+0], acc[rt*4+nt][hh*2+1]);
                }
            }
        }
        // loop-top CP_WAIT0 + __syncthreads gates A and RS0 reuse
    }
}

// ---------------- launcher ----------------
extern "C" void kernel_launch(void* const* d_in, const int* in_sizes, int n_in,
                              void* d_out, int out_size) {
    (void)in_sizes; (void)n_in; (void)out_size;
    const float* x        = (const float*)d_in[0];
    const int*   lane_ids = (const int*)  d_in[1];
    const float* w1a  = (const float*)d_in[2];
    const float* b1a  = (const float*)d_in[3];
    const float* g1a  = (const float*)d_in[4];
    const float* be1a = (const float*)d_in[5];
    const float* w1b  = (const float*)d_in[6];
    const float* b1b  = (const float*)d_in[7];
    const float* g1b  = (const float*)d_in[8];
    const float* be1b = (const float*)d_in[9];
    const float* w2a  = (const float*)d_in[10];
    const float* b2a  = (const float*)d_in[11];
    const float* g2a  = (const float*)d_in[12];
    const float* be2a = (const float*)d_in[13];
    const float* w2b  = (const float*)d_in[14];
    const float* b2b  = (const float*)d_in[15];
    const float* g2b  = (const float*)d_in[16];
    const float* be2b = (const float*)d_in[17];
    const float* gn   = (const float*)d_in[18];
    const float* bn   = (const float*)d_in[19];
    float* out = (float*)d_out;

    const int SM1  = 2*WSZ + 2*ASZ + 3072 + 4096;   // 111616
    const int SMLG = 3*WSZ + 1024;                  // 105472
    const int SM2  = 2*WSZ + 2*ASZ + 3584 + 4096;   // 112128
    cudaFuncSetAttribute(k_fc1,      cudaFuncAttributeMaxDynamicSharedMemorySize, SM1);
    cudaFuncSetAttribute(k_lanegemm, cudaFuncAttributeMaxDynamicSharedMemorySize, SMLG);
    cudaFuncSetAttribute(k_fc2,      cudaFuncAttributeMaxDynamicSharedMemorySize, SM2);

    k_init_lanemax<<<(NLANES * HD + 511) / 512, 512>>>();
    k_fc1     <<<296, 256, SM1>>> (x, lane_ids, w1a, b1a, g1a, be1a, w1b, b1b, g1b, be1b);
    k_lanegemm<<<148, 512, SMLG>>>(w2a + 128 * HD, b2a);
    k_fc2     <<<296, 256, SM2>>> (x, lane_ids, w2a, g2a, be2a, w2b, b2b, g2b, be2b, gn, bn, out);
}

// round 15
// speedup vs baseline: 3.2645x; 1.2317x over previous
#include <cuda_runtime.h>
#include <cuda_fp16.h>
#include <cstdint>

#define NROWS  300000
#define HD     128
#define NLANES 25000
#define LNEPS  1e-5f
#define TM64   64
#define NT64   ((NROWS + TM64 - 1) / TM64)  // 4688 tiles (64-row)
#define NLT    ((NLANES + 127) / 128)       // 196 lane tiles
#define PADU   68                            // u32 per 128-fp16 row (272B, conflict-free)
#define ROWB   272
#define TU64H  1088                          // uint4 per 64-row fp16 tile image (hi only)

typedef unsigned int       u32;
typedef unsigned short     u16;
typedef unsigned long long u64;

// ---------------- device scratch ----------------
__device__ uint4 g_h[(size_t)NT64 * TU64H];  // fc1 output image (fp16, 64-row tiles)
__device__ int   g_lanemax[NLANES * HD];     // per-lane max (float bits, relu>=0)
__device__ float g_z[(size_t)NLANES * HD];   // per-lane Z = max @ w2a_bot + b2a

// ---------------- helpers ----------------
static __device__ __forceinline__ u32 smem_u32(const void* p) {
    u32 a;
    asm("{ .reg .u64 t; cvta.to.shared.u64 t, %1; cvt.u32.u64 %0, t; }" : "=r"(a) : "l"(p));
    return a;
}
static __device__ __forceinline__ u32 pack_f16(float v0, float v1) {
    __half2 h = __floats2half2_rn(v0, v1);
    return *reinterpret_cast<u32*>(&h);
}

#define CP16(sm_addr, gptr) \
    asm volatile("cp.async.cg.shared.global [%0], [%1], 16;" :: "r"(sm_addr), "l"(gptr))
#define CP_COMMIT() asm volatile("cp.async.commit_group;" ::: "memory")
#define CP_WAIT0()  asm volatile("cp.async.wait_group 0;" ::: "memory")
#define PREF_L2(p)  asm volatile("prefetch.global.L2 [%0];" :: "l"(p))

static __device__ __forceinline__ void ldsm4(u32& r0, u32& r1, u32& r2, u32& r3, u32 addr) {
    asm volatile("ldmatrix.sync.aligned.m8n8.x4.shared.b16 {%0,%1,%2,%3}, [%4];"
        : "=r"(r0), "=r"(r1), "=r"(r2), "=r"(r3) : "r"(addr));
}
static __device__ __forceinline__ void mma_f16(float (&d)[4], const u32 (&a)[4], u32 b0, u32 b1) {
    asm volatile("mma.sync.aligned.m16n8k16.row.col.f32.f16.f16.f32 "
        "{%0,%1,%2,%3}, {%4,%5,%6,%7}, {%8,%9}, {%0,%1,%2,%3};"
        : "+f"(d[0]), "+f"(d[1]), "+f"(d[2]), "+f"(d[3])
        : "r"(a[0]), "r"(a[1]), "r"(a[2]), "r"(a[3]), "r"(b0), "r"(b1));
}

// fp16 single-pass GEMM: acc += A*B over K=128. Warp covers 32x32.
static __device__ __forceinline__ void gemm_f16_1p(
    u32 A, u32 B, u32 aoff, u32 boff, float (&acc)[8][4])
{
    #pragma unroll
    for (int kc = 0; kc < 8; ++kc) {
        const u32 ka = kc * 32;
        u32 a0[4], a1[4], b[8];
        ldsm4(a0[0], a0[1], a0[2], a0[3], A + aoff + ka);
        ldsm4(a1[0], a1[1], a1[2], a1[3], A + aoff + 16 * ROWB + ka);
        ldsm4(b[0], b[1], b[2], b[3], B + boff + ka);
        ldsm4(b[4], b[5], b[6], b[7], B + boff + 16 * ROWB + ka);
        #pragma unroll
        for (int p = 0; p < 2; ++p)
        #pragma unroll
        for (int j = 0; j < 2; ++j) {
            const int nt = p * 2 + j;
            const u32 b0 = b[p*4 + j*2], b1 = b[p*4 + j*2 + 1];
            mma_f16(acc[nt],     a0, b0, b1);
            mma_f16(acc[4 + nt], a1, b0, b1);
        }
    }
}

// ---------------- LN epilogue for 64-row tiles (single barrier; ping-pong RS/RQ) ----------------
template<bool HASB, bool RELU>
static __device__ __forceinline__ void ln_tile64(
    float (&acc)[8][4], int wrow, int wcol, int lr, int lc, int cw,
    const float* __restrict__ bias, const float* __restrict__ gam,
    const float* __restrict__ bet, float* RS, float* RQ)
{
    float s[4] = {0.f,0.f,0.f,0.f}, q[4] = {0.f,0.f,0.f,0.f};
    #pragma unroll
    for (int rt = 0; rt < 2; ++rt)
    #pragma unroll
    for (int nt = 0; nt < 4; ++nt) {
        float* a = acc[rt * 4 + nt];
        if (HASB) {
            int c = wcol + nt * 8 + lc * 2;
            float bx = bias[c], by = bias[c + 1];
            a[0] += bx; a[1] += by; a[2] += bx; a[3] += by;
        }
        s[rt*2+0] += a[0] + a[1]; q[rt*2+0] += a[0]*a[0] + a[1]*a[1];
        s[rt*2+1] += a[2] + a[3]; q[rt*2+1] += a[2]*a[2] + a[3]*a[3];
    }
    #pragma unroll
    for (int off = 1; off <= 2; off <<= 1)
        #pragma unroll
        for (int i = 0; i < 4; ++i) {
            s[i] += __shfl_xor_sync(0xffffffffu, s[i], off);
            q[i] += __shfl_xor_sync(0xffffffffu, q[i], off);
        }
    if (lc == 0) {
        #pragma unroll
        for (int i = 0; i < 4; ++i) {
            int row = wrow + (i >> 1) * 16 + (i & 1) * 8 + lr;
            RS[cw * 64 + row] = s[i];
            RQ[cw * 64 + row] = q[i];
        }
    }
    __syncthreads();
    float mm[4], rsd[4];
    #pragma unroll
    for (int i = 0; i < 4; ++i) {
        int row = wrow + (i >> 1) * 16 + (i & 1) * 8 + lr;
        float S = RS[row] + RS[64 + row] + RS[128 + row] + RS[192 + row];
        float Q = RQ[row] + RQ[64 + row] + RQ[128 + row] + RQ[192 + row];
        float m = S * (1.f / 128.f);
        mm[i] = m;
        rsd[i] = rsqrtf(Q * (1.f / 128.f) - m * m + LNEPS);
    }
    #pragma unroll
    for (int rt = 0; rt < 2; ++rt)
    #pragma unroll
    for (int nt = 0; nt < 4; ++nt) {
        int c = wcol + nt * 8 + lc * 2;
        float gx = gam[c], gy = gam[c + 1], ex = bet[c], ey = bet[c + 1];
        float* a = acc[rt * 4 + nt];
        int s0 = rt * 2, s1 = rt * 2 + 1;
        a[0] = (a[0] - mm[s0]) * rsd[s0] * gx + ex;
        a[1] = (a[1] - mm[s0]) * rsd[s0] * gy + ey;
        a[2] = (a[2] - mm[s1]) * rsd[s1] * gx + ex;
        a[3] = (a[3] - mm[s1]) * rsd[s1] * gy + ey;
        if (RELU) {
            a[0] = fmaxf(a[0], 0.f); a[1] = fmaxf(a[1], 0.f);
            a[2] = fmaxf(a[2], 0.f); a[3] = fmaxf(a[3], 0.f);
        }
    }
}

// fp16 fragment store (hi only)
static __device__ __forceinline__ void store_acc_f16(
    const float (&acc)[8][4], u32* dst, int wrow, int wcol, int lr, int lc)
{
    #pragma unroll
    for (int rt = 0; rt < 2; ++rt)
    #pragma unroll
    for (int hh = 0; hh < 2; ++hh) {
        int row = wrow + rt * 16 + hh * 8 + lr;
        u32 base = row * PADU + (wcol >> 1) + lc;
        #pragma unroll
        for (int nt = 0; nt < 4; ++nt)
            dst[base + nt*4] = pack_f16(acc[rt*4+nt][hh*2+0], acc[rt*4+nt][hh*2+1]);
    }
}

static __device__ __forceinline__ void store4_f16(u32* dst, int row, int col, float4 xv) {
    u32 idx = row * PADU + (col >> 1);
    dst[idx]   = pack_f16(xv.x, xv.y);
    dst[idx+1] = pack_f16(xv.z, xv.w);
}

// single-fp16 weight loader
static __device__ __forceinline__ void load_w_f16(u32* dst, const float* __restrict__ w,
                                                  int tid, int nth) {
    for (int idx = tid; idx < HD * HD / 2; idx += nth) {
        int o = idx & 127, k2 = idx >> 7;
        dst[o * PADU + k2] = pack_f16(w[(2*k2) * HD + o], w[(2*k2+1) * HD + o]);
    }
}

__global__ void k_init_lanemax() {
    int i = blockIdx.x * blockDim.x + threadIdx.x;
    if (i < NLANES * HD) g_lanemax[i] = 0;
}

#define WSZ  34816    // 128x68 u32 (weights / 128-row arrays)
#define ASZ  17408    // 64x68 u32  (64-row activation arrays)

static __device__ __forceinline__ u32 mk_aoff(int wrow, int lane) {
    return (u32)((wrow + (lane & 15)) * ROWB + ((lane >> 4) & 1) * 16);
}
static __device__ __forceinline__ u32 mk_boff(int wcol, int lane) {
    return (u32)((wcol + ((lane >> 4) & 1) * 8 + (lane & 7)) * ROWB + ((lane >> 3) & 1) * 16);
}

// ======================== fc1 (fp16 1-pass, 64-row tiles, 2 CTAs/SM) ========================
// smem: WA 0 | WB WSZ | A 2WSZ | P 2WSZ+ASZ (3072B) | RS/RQ x2 (4x1024)
__global__ void __launch_bounds__(256, 2) k_fc1(
    const float* __restrict__ x, const int* __restrict__ lane_ids,
    const float* __restrict__ w1a, const float* __restrict__ b1a,
    const float* __restrict__ g1a, const float* __restrict__ be1a,
    const float* __restrict__ w1b, const float* __restrict__ b1b,
    const float* __restrict__ g1b, const float* __restrict__ be1b)
{
    extern __shared__ char sm[];
    u32* WA = (u32*)(sm);
    u32* WB = (u32*)(sm + WSZ);
    u32* A  = (u32*)(sm + 2*WSZ);
    float* P   = (float*)(sm + 2*WSZ + ASZ);
    float* RS0 = (float*)(sm + 2*WSZ + ASZ + 3072);
    float* RQ0 = (float*)(sm + 2*WSZ + ASZ + 4096);
    float* RS1 = (float*)(sm + 2*WSZ + ASZ + 5120);
    float* RQ1 = (float*)(sm + 2*WSZ + ASZ + 6144);

    const int tid = threadIdx.x, w = tid >> 5, lane = tid & 31;
    const int lr = lane >> 2, lc = lane & 3;
    const int wrow = (w & 1) * 32, wcol = (w >> 1) * 32, cw = w >> 1;
    const u32 aoff = mk_aoff(wrow, lane), boff = mk_boff(wcol, lane);
    const u32 sA = smem_u32(A), sWA = smem_u32(WA), sWB = smem_u32(WB);

    load_w_f16(WA, w1a, tid, 256);
    load_w_f16(WB, w1b, tid, 256);
    for (int i = tid; i < HD; i += 256) {
        P[i] = b1a[i]; P[128+i] = g1a[i]; P[256+i] = be1a[i];
        P[384+i] = b1b[i]; P[512+i] = g1b[i]; P[640+i] = be1b[i];
    }
    {
        int grow = blockIdx.x * TM64 + (tid >> 2);
        if (grow < NROWS) PREF_L2((const char*)x + (size_t)blockIdx.x * TM64 * HD * 4 + tid * 128);
    }
    __syncthreads();

    for (int t = blockIdx.x; t < NT64; t += gridDim.x) {
        int r0 = t * TM64;
        // load + convert x tile (64 rows x 32 float4 = 2048)
        #pragma unroll
        for (int j = 0; j < 8; ++j) {
            int idx = tid + j * 256; int xr = idx >> 5; int cg = idx & 31;
            int grow = r0 + xr; if (grow >= NROWS) grow = NROWS - 1;
            float4 xv = __ldg(((const float4*)x) + ((size_t)grow * 32 + cg));
            store4_f16(A, xr, cg * 4, xv);
        }
        {
            int tn = t + gridDim.x; if (tn >= NT64) tn = t;
            int grow = tn * TM64 + (tid >> 2);
            if (grow < NROWS) PREF_L2((const char*)x + (size_t)tn * TM64 * HD * 4 + tid * 128);
        }
        __syncthreads();

        float acc[8][4];
        #pragma unroll
        for (int i = 0; i < 8; ++i) { acc[i][0]=acc[i][1]=acc[i][2]=acc[i][3]=0.f; }
        gemm_f16_1p(sA, sWA, aoff, boff, acc);
        ln_tile64<true, true>(acc, wrow, wcol, lr, lc, cw, P, P+128, P+256, RS0, RQ0);
        store_acc_f16(acc, A, wrow, wcol, lr, lc);
        __syncthreads();

        #pragma unroll
        for (int i = 0; i < 8; ++i) { acc[i][0]=acc[i][1]=acc[i][2]=acc[i][3]=0.f; }
        gemm_f16_1p(sA, sWB, aoff, boff, acc);
        ln_tile64<true, true>(acc, wrow, wcol, lr, lc, cw, P+384, P+512, P+640, RS1, RQ1);

        // scatter-max (predicated: relu zeros are no-ops vs init 0)
        #pragma unroll
        for (int rt = 0; rt < 2; ++rt)
        #pragma unroll
        for (int hh = 0; hh < 2; ++hh) {
            int row = wrow + rt*16 + hh*8 + lr;
            int grow = r0 + row; if (grow >= NROWS) grow = NROWS - 1;
            int ln = __ldg(lane_ids + grow);
            int* bp = g_lanemax + ln * HD;
            #pragma unroll
            for (int nt = 0; nt < 4; ++nt) {
                int c = wcol + nt*8 + lc*2;
                float v0 = acc[rt*4+nt][hh*2+0], v1 = acc[rt*4+nt][hh*2+1];
                if (v0 > 0.f) atomicMax(bp + c,     __float_as_int(v0));
                if (v1 > 0.f) atomicMax(bp + c + 1, __float_as_int(v1));
            }
        }
        store_acc_f16(acc, A, wrow, wcol, lr, lc);   // h image (fp16)
        __syncthreads();

        const uint4* s4 = (const uint4*)A;
        uint4* d4 = g_h + (size_t)t * TU64H;
        #pragma unroll
        for (int j = 0; j < 5; ++j) {
            int i = tid + j * 256;
            if (i < TU64H) d4[i] = s4[i];
        }
        __syncthreads();
    }
}

// ======================== k_lanegemm: Z = lane_max @ w2a_bot + b2a (fp16 1-pass, 512 thr) ========================
__global__ void __launch_bounds__(512, 1) k_lanegemm(
    const float* __restrict__ w2a_bot, const float* __restrict__ b2a)
{
    extern __shared__ char sm[];
    u32* W = (u32*)(sm);
    u32* A = (u32*)(sm + WSZ);              // 128-lane tile (WSZ)
    float* P = (float*)(sm + 2*WSZ);        // b2a

    const int tid = threadIdx.x, w = tid >> 5, lane = tid & 31;
    const int lr = lane >> 2, lc = lane & 3;
    const int wrow = (w & 3) * 32, wcol = (w >> 2) * 32;
    const u32 aoff = mk_aoff(wrow, lane), boff = mk_boff(wcol, lane);
    const u32 sA = smem_u32(A), sW = smem_u32(W);

    load_w_f16(W, w2a_bot, tid, 512);
    for (int i = tid; i < HD; i += 512) P[i] = b2a[i];
    __syncthreads();

    for (int t = blockIdx.x; t < NLT; t += gridDim.x) {
        int l0 = t * 128;
        #pragma unroll
        for (int j = 0; j < 8; ++j) {
            int idx = tid + j * 512; int xr = idx >> 5; int cg = idx & 31;
            int l = l0 + xr; if (l >= NLANES) l = NLANES - 1;
            int4 gv = __ldg(((const int4*)(g_lanemax)) + ((size_t)l * 32 + cg));
            store4_f16(A, xr, cg * 4,
                make_float4(__int_as_float(gv.x), __int_as_float(gv.y),
                            __int_as_float(gv.z), __int_as_float(gv.w)));
        }
        __syncthreads();

        float acc[8][4];
        #pragma unroll
        for (int i = 0; i < 8; ++i) { acc[i][0]=acc[i][1]=acc[i][2]=acc[i][3]=0.f; }
        gemm_f16_1p(sA, sW, aoff, boff, acc);

        #pragma unroll
        for (int rt = 0; rt < 2; ++rt)
        #pragma unroll
        for (int hh = 0; hh < 2; ++hh) {
            int row = wrow + rt*16 + hh*8 + lr;
            int l = l0 + row;
            if (l < NLANES) {
                #pragma unroll
                for (int nt = 0; nt < 4; ++nt) {
                    int c = wcol + nt*8 + lc*2;
                    *(float2*)(g_z + (size_t)l * HD + c) =
                        make_float2(acc[rt*4+nt][hh*2+0] + P[c],
                                    acc[rt*4+nt][hh*2+1] + P[c+1]);
                }
            }
        }
        __syncthreads();
    }
}

// ======================== fused fc2 (fp16 1-pass, 64-row tiles, 2 CTAs/SM, dbl-buffered A) ========================
// smem: WA 0 | WB WSZ | A0 2WSZ | A1 2WSZ+ASZ | P 2WSZ+2ASZ (3584B) | RS/RQ x2
__global__ void __launch_bounds__(256, 2) k_fc2(
    const float* __restrict__ x, const int* __restrict__ lane_ids,
    const float* __restrict__ w2a_top,
    const float* __restrict__ g2a, const float* __restrict__ be2a,
    const float* __restrict__ w2b, const float* __restrict__ b2b,
    const float* __restrict__ g2b, const float* __restrict__ be2b,
    const float* __restrict__ gn, const float* __restrict__ bn,
    float* __restrict__ out)
{
    extern __shared__ char sm[];
    u32* WA = (u32*)(sm);
    u32* WB = (u32*)(sm + WSZ);
    float* P   = (float*)(sm + 2*WSZ + 2*ASZ);
    float* RS0 = (float*)(sm + 2*WSZ + 2*ASZ + 3584);
    float* RQ0 = (float*)(sm + 2*WSZ + 2*ASZ + 4608);
    float* RS1 = (float*)(sm + 2*WSZ + 2*ASZ + 5632);
    float* RQ1 = (float*)(sm + 2*WSZ + 2*ASZ + 6656);

    const int tid = threadIdx.x, w = tid >> 5, lane = tid & 31;
    const int lr = lane >> 2, lc = lane & 3;
    const int wrow = (w & 1) * 32, wcol = (w >> 1) * 32, cw = w >> 1;
    const u32 aoff = mk_aoff(wrow, lane), boff = mk_boff(wcol, lane);
    const u32 sWA = smem_u32(WA), sWB = smem_u32(WB);
    const u32 sA0 = smem_u32(sm + 2*WSZ), sA1 = smem_u32(sm + 2*WSZ + ASZ);

    // prologue: issue first h-image load FIRST (overlaps weight loads)
    {
        const uint4* s4 = g_h + (size_t)blockIdx.x * TU64H;
        #pragma unroll
        for (int j = 0; j < 5; ++j) {
            int i = tid + j * 256;
            if (i < TU64H) CP16(sA0 + (u32)i * 16, s4 + i);
        }
        CP_COMMIT();
    }
    load_w_f16(WA, w2a_top, tid, 256);
    load_w_f16(WB, w2b,     tid, 256);
    for (int i = tid; i < HD; i += 256) {
        P[i]       = g2a[i]; P[128+i] = be2a[i];
        P[256+i]   = b2b[i]; P[384+i] = g2b[i]; P[512+i] = be2b[i];
        P[640+i]   = gn[i];  P[768+i] = bn[i];
    }
    {
        int grow = blockIdx.x * TM64 + (tid >> 2);
        if (grow < NROWS) PREF_L2((const char*)x + (size_t)blockIdx.x * TM64 * HD * 4 + tid * 128);
    }
    __syncthreads();

    int buf = 0;
    for (int t = blockIdx.x; t < NT64; t += gridDim.x, buf ^= 1) {
        int r0 = t * TM64;
        int tn = t + gridDim.x; if (tn >= NT64) tn = t;
        const u32 sA  = buf ? sA1 : sA0;
        const u32 sAn = buf ? sA0 : sA1;
        u32* Acur = (u32*)(sm + 2*WSZ + (buf ? ASZ : 0));

        CP_WAIT0();                       // current h image resident
        __syncthreads();

        // issue NEXT tile's h image into the other buffer NOW — overlaps both GEMMs
        {
            const uint4* s4 = g_h + (size_t)tn * TU64H;
            #pragma unroll
            for (int j = 0; j < 5; ++j) {
                int i = tid + j * 256;
                if (i < TU64H) CP16(sAn + (u32)i * 16, s4 + i);
            }
            CP_COMMIT();
            int grow = tn * TM64 + (tid >> 2);
            if (grow < NROWS) PREF_L2((const char*)x + (size_t)tn * TM64 * HD * 4 + tid * 128);
        }
        // prefetch this tile's Z rows into L2
        {
            int grow = r0 + (tid >> 2); if (grow >= NROWS) grow = NROWS - 1;
            int lnid = __ldg(lane_ids + grow);
            PREF_L2(g_z + (size_t)lnid * HD + (tid & 3) * 32);
        }

        float acc[8][4];
        #pragma unroll
        for (int i = 0; i < 8; ++i) { acc[i][0]=acc[i][1]=acc[i][2]=acc[i][3]=0.f; }
        gemm_f16_1p(sA, sWA, aoff, boff, acc);

        // add Z[lane] (fp32, b2a folded in)
        #pragma unroll
        for (int rt = 0; rt < 2; ++rt)
        #pragma unroll
        for (int hh = 0; hh < 2; ++hh) {
            int row = wrow + rt*16 + hh*8 + lr;
            int grow = r0 + row; if (grow >= NROWS) grow = NROWS - 1;
            int lnid = __ldg(lane_ids + grow);
            const float* zr = g_z + (size_t)lnid * HD;
            #pragma unroll
            for (int nt = 0; nt < 4; ++nt) {
                int c = wcol + nt*8 + lc*2;
                float2 zv = __ldg((const float2*)(zr + c));
                acc[rt*4+nt][hh*2+0] += zv.x;
                acc[rt*4+nt][hh*2+1] += zv.y;
            }
        }
        // LN1 + ReLU (set0; its barrier also guarantees all GEMM1 A-reads done)
        ln_tile64<false, true>(acc, wrow, wcol, lr, lc, cw, P, P, P+128, RS0, RQ0);

        // store f into current A (in place; safe per LN1 barrier)
        store_acc_f16(acc, Acur, wrow, wcol, lr, lc);
        __syncthreads();

        // GEMM2: f @ w2b
        #pragma unroll
        for (int i = 0; i < 8; ++i) { acc[i][0]=acc[i][1]=acc[i][2]=acc[i][3]=0.f; }
        gemm_f16_1p(sA, sWB, aoff, boff, acc);

        // LN2 + ReLU (set1; its barrier covers GEMM2 A-reads before next-iter cp into this buffer)
        ln_tile64<true, true>(acc, wrow, wcol, lr, lc, cw, P+256, P+384, P+512, RS1, RQ1);

        // residual add from x (L2-hot)
        #pragma unroll
        for (int rt = 0; rt < 2; ++rt)
        #pragma unroll
        for (int hh = 0; hh < 2; ++hh) {
            int row = wrow + rt*16 + hh*8 + lr;
            int grow = r0 + row; if (grow >= NROWS) grow = NROWS - 1;
            #pragma unroll
            for (int nt = 0; nt < 4; ++nt) {
                int c = wcol + nt*8 + lc*2;
                float2 xv = __ldg((const float2*)(x + (size_t)grow * HD + c));
                acc[rt*4+nt][hh*2+0] += xv.x;
                acc[rt*4+nt][hh*2+1] += xv.y;
            }
        }
        // final LN (set0 — safe: last set0 read was LN1, separated by f-store barrier)
        ln_tile64<false, false>(acc, wrow, wcol, lr, lc, cw, P, P+640, P+768, RS0, RQ0);

        // write out straight from registers
        #pragma unroll
        for (int rt = 0; rt < 2; ++rt)
        #pragma unroll
        for (int hh = 0; hh < 2; ++hh) {
            int row = wrow + rt*16 + hh*8 + lr;
            int grow = r0 + row;
            if (grow < NROWS) {
                #pragma unroll
                for (int nt = 0; nt < 4; ++nt) {
                    int c = wcol + nt*8 + lc*2;
                    *(float2*)(out + (size_t)grow * HD + c) =
                        make_float2(acc[rt*4+nt][hh*2+0], acc[rt*4+nt][hh*2+1]);
                }
            }
        }
        // loop-top CP_WAIT0 + __syncthreads gates buffer & RS reuse
    }
}

// ---------------- launcher ----------------
extern "C" void kernel_launch(void* const* d_in, const int* in_sizes, int n_in,
                              void* d_out, int out_size) {
    (void)in_sizes; (void)n_in; (void)out_size;
    const float* x        = (const float*)d_in[0];
    const int*   lane_ids = (const int*)  d_in[1];
    const float* w1a  = (const float*)d_in[2];
    const float* b1a  = (const float*)d_in[3];
    const float* g1a  = (const float*)d_in[4];
    const float* be1a = (const float*)d_in[5];
    const float* w1b  = (const float*)d_in[6];
    const float* b1b  = (const float*)d_in[7];
    const float* g1b  = (const float*)d_in[8];
    const float* be1b = (const float*)d_in[9];
    const float* w2a  = (const float*)d_in[10];
    const float* b2a  = (const float*)d_in[11];
    const float* g2a  = (const float*)d_in[12];
    const float* be2a = (const float*)d_in[13];
    const float* w2b  = (const float*)d_in[14];
    const float* b2b  = (const float*)d_in[15];
    const float* g2b  = (const float*)d_in[16];
    const float* be2b = (const float*)d_in[17];
    const float* gn   = (const float*)d_in[18];
    const float* bn   = (const float*)d_in[19];
    float* out = (float*)d_out;

    const int SM1  = 2*WSZ + ASZ + 3072 + 4096;     // 94208
    const int SMLG = 2*WSZ + 1024;                  // 70656
    const int SM2  = 2*WSZ + 2*ASZ + 3584 + 4096;   // 112128
    cudaFuncSetAttribute(k_fc1,      cudaFuncAttributeMaxDynamicSharedMemorySize, SM1);
    cudaFuncSetAttribute(k_lanegemm, cudaFuncAttributeMaxDynamicSharedMemorySize, SMLG);
    cudaFuncSetAttribute(k_fc2,      cudaFuncAttributeMaxDynamicSharedMemorySize, SM2);

    k_init_lanemax<<<(NLANES * HD + 511) / 512, 512>>>();
    k_fc1     <<<296, 256, SM1>>> (x, lane_ids, w1a, b1a, g1a, be1a, w1b, b1b, g1b, be1b);
    k_lanegemm<<<148, 512, SMLG>>>(w2a + 128 * HD, b2a);
    k_fc2     <<<296, 256, SM2>>> (x, lane_ids, w2a, g2a, be2a, w2b, b2b, g2b, be2b, gn, bn, out);
}